// round 3
// baseline (speedup 1.0000x reference)
#include <cuda_runtime.h>
#include <math.h>

typedef unsigned long long u64;

#define Bb 4
#define Nn 2048
#define Cc 256
#define Hh 4
#define Dd 64
#define SCALE 0.125f   // D^-0.5

// f32x2 packed helpers (Blackwell sm_100+)
__device__ __forceinline__ u64 dup2(float v) {
    u64 r; asm("mov.b64 %0,{%1,%1};" : "=l"(r) : "f"(v)); return r;
}
__device__ __forceinline__ u64 fma2(u64 a, u64 b, u64 c) {
    u64 d; asm("fma.rn.f32x2 %0,%1,%2,%3;" : "=l"(d) : "l"(a), "l"(b), "l"(c)); return d;
}
__device__ __forceinline__ u64 mul2(u64 a, u64 b) {
    u64 d; asm("mul.rn.f32x2 %0,%1,%2;" : "=l"(d) : "l"(a), "l"(b)); return d;
}
__device__ __forceinline__ float2 unpk(u64 p) {
    float2 f; asm("mov.b64 {%0,%1},%2;" : "=f"(f.x), "=f"(f.y) : "l"(p)); return f;
}

// Scratch (device globals; no allocations allowed)
__device__ __align__(16) float g_Q[Bb*Hh*Nn*Dd];
__device__ __align__(16) float g_K[Bb*Hh*Nn*Dd];
__device__ __align__(16) float g_V[Bb*Hh*Nn*Dd];
__device__ __align__(16) float g_RP[Bb*Nn*4];      // pre-multiplied by pos_scale
__device__ __align__(16) float g_AO[Bb*Nn*Cc];     // attention output before proj

// ---------------------------------------------------------------------------
// RP[b,j,c] = pos_scale * sum_d R[b,c,d] * P[j,d]
// ---------------------------------------------------------------------------
__global__ void rp_kernel(const float* __restrict__ R, const float* __restrict__ P,
                          const float* __restrict__ pos_scale) {
    int idx = blockIdx.x * blockDim.x + threadIdx.x;
    if (idx >= Bb * Nn) return;
    int b = idx / Nn, j = idx % Nn;
    float p0 = P[j*3+0], p1 = P[j*3+1], p2 = P[j*3+2];
    float ps = *pos_scale;
    const float* Rb = R + b*9;
#pragma unroll
    for (int c = 0; c < 3; c++)
        g_RP[idx*4 + c] = ps * (Rb[c*3+0]*p0 + Rb[c*3+1]*p1 + Rb[c*3+2]*p2);
    g_RP[idx*4 + 3] = 0.f;
}

// ---------------------------------------------------------------------------
// NT GEMM (f32x2): out[m,c] = sum_k A[m,k] * W[c,k] + bias[c]
// 128x128 CTA tile, 8x8 thread tile, K-tile 16, 256 threads.
// ---------------------------------------------------------------------------
#define SG 132   // smem k-major stride

template<bool IS_QKV>
__global__ __launch_bounds__(256)
void gemm2_kernel(const float* __restrict__ A, const float* __restrict__ W,
                  const float* __restrict__ bias, float* __restrict__ Out) {
    __shared__ __align__(16) float As[16 * SG];
    __shared__ __align__(16) float Ws[16 * SG];

    const float* Ap;
    if constexpr (IS_QKV) Ap = A; else Ap = g_AO;

    int tid = threadIdx.x;
    int tx = tid & 15, ty = tid >> 4;
    int m0 = blockIdx.y * 128, n0 = blockIdx.x * 128;
    int lr = tid >> 1;            // 0..127
    int kq = (tid & 1) * 8;       // 0 or 8

    u64 acc[8][4];
#pragma unroll
    for (int r = 0; r < 8; r++)
#pragma unroll
        for (int c = 0; c < 4; c++) acc[r][c] = 0ull;

    for (int k0 = 0; k0 < Cc; k0 += 16) {
        float4 a0 = *(const float4*)&Ap[(size_t)(m0 + lr) * Cc + k0 + kq];
        float4 a1 = *(const float4*)&Ap[(size_t)(m0 + lr) * Cc + k0 + kq + 4];
        float4 w0 = *(const float4*)&W [(size_t)(n0 + lr) * Cc + k0 + kq];
        float4 w1 = *(const float4*)&W [(size_t)(n0 + lr) * Cc + k0 + kq + 4];
        As[(kq+0)*SG+lr]=a0.x; As[(kq+1)*SG+lr]=a0.y; As[(kq+2)*SG+lr]=a0.z; As[(kq+3)*SG+lr]=a0.w;
        As[(kq+4)*SG+lr]=a1.x; As[(kq+5)*SG+lr]=a1.y; As[(kq+6)*SG+lr]=a1.z; As[(kq+7)*SG+lr]=a1.w;
        Ws[(kq+0)*SG+lr]=w0.x; Ws[(kq+1)*SG+lr]=w0.y; Ws[(kq+2)*SG+lr]=w0.z; Ws[(kq+3)*SG+lr]=w0.w;
        Ws[(kq+4)*SG+lr]=w1.x; Ws[(kq+5)*SG+lr]=w1.y; Ws[(kq+6)*SG+lr]=w1.z; Ws[(kq+7)*SG+lr]=w1.w;
        __syncthreads();
#pragma unroll
        for (int kk = 0; kk < 16; kk++) {
            float a[8];
            *(float4*)(a+0) = *(const float4*)&As[kk*SG + ty*8];
            *(float4*)(a+4) = *(const float4*)&As[kk*SG + ty*8 + 4];
            ulonglong2 b01 = *(const ulonglong2*)&Ws[kk*SG + tx*8];
            ulonglong2 b23 = *(const ulonglong2*)&Ws[kk*SG + tx*8 + 4];
            u64 B[4] = {b01.x, b01.y, b23.x, b23.y};
            u64 a2[8];
#pragma unroll
            for (int r = 0; r < 8; r++) a2[r] = dup2(a[r]);
#pragma unroll
            for (int r = 0; r < 8; r++)
#pragma unroll
                for (int c = 0; c < 4; c++) acc[r][c] = fma2(a2[r], B[c], acc[r][c]);
        }
        __syncthreads();
    }

#pragma unroll
    for (int r = 0; r < 8; r++) {
        int m = m0 + ty*8 + r;
#pragma unroll
        for (int cp = 0; cp < 4; cp++) {
            float2 v = unpk(acc[r][cp]);
            int c0 = n0 + tx*8 + cp*2;
            float o0 = v.x + bias[c0];
            float o1 = v.y + bias[c0+1];
            if constexpr (IS_QKV) {
#pragma unroll
                for (int e = 0; e < 2; e++) {
                    int c = c0 + e;
                    float val = e ? o1 : o0;
                    int bb = m >> 11;
                    int n  = m & (Nn - 1);
                    int which = c >> 8;
                    int h = (c >> 6) & (Hh - 1);
                    int d = c & (Dd - 1);
                    float* dst = (which == 0) ? g_Q : ((which == 1) ? g_K : g_V);
                    dst[((size_t)(bb*Hh + h) * Nn + n) * Dd + d] = val;
                }
            } else {
                Out[(size_t)m * Cc + c0] = o0;
                Out[(size_t)m * Cc + c0 + 1] = o1;
            }
        }
    }
}

// ---------------------------------------------------------------------------
// Flash attention (f32x2): one CTA per (b, h, 128-row q tile). 128-wide kv tiles.
// S = Q K^T * SCALE + RP_i . P_j ; O = softmax(S) V
// 256 threads, 8x8 per-thread S tile, 8x4 per-thread O tile.
// ---------------------------------------------------------------------------
#define SQ 132   // Qt/Kt stride (d-major)
#define SV 72    // Vs stride (j-major)
#define SP 136   // Ps stride (i-major)
#define FLASH_FLOATS (64*SQ*2 + 128*SV + 128*SP + 512 + 512)
#define FLASH_SMEM (FLASH_FLOATS * sizeof(float))

__global__ __launch_bounds__(256, 1)
void flash2_kernel(const float* __restrict__ Pg) {
    extern __shared__ __align__(16) float sm[];
    float* Qt   = sm;                  // [d][i]   64 x SQ
    float* Kt   = Qt + 64 * SQ;        // [d][j]   64 x SQ
    float* Vs   = Kt + 64 * SQ;        // [j][d]  128 x SV
    float* Ps   = Vs + 128 * SV;       // [i][j]  128 x SP
    float* rp_s = Ps + 128 * SP;       // [i][4]
    float* p_s  = rp_s + 512;          // [j][4]

    int b = blockIdx.z, h = blockIdx.y;
    int i0 = blockIdx.x * 128;
    int tid = threadIdx.x;
    int tx = tid & 15, ty = tid >> 4;
    int lr = tid >> 1;              // 0..127
    int half = (tid & 1) * 32;      // d half

    const float* Qg = g_Q + (size_t)(b*Hh + h) * Nn * Dd;
    const float* Kg = g_K + (size_t)(b*Hh + h) * Nn * Dd;
    const float* Vg = g_V + (size_t)(b*Hh + h) * Nn * Dd;

    // Load Q tile transposed: Qt[d][i]
#pragma unroll
    for (int p = 0; p < 8; p++) {
        int d = half + p * 4;
        float4 q = *(const float4*)&Qg[(size_t)(i0 + lr) * Dd + d];
        Qt[(d+0)*SQ + lr] = q.x; Qt[(d+1)*SQ + lr] = q.y;
        Qt[(d+2)*SQ + lr] = q.z; Qt[(d+3)*SQ + lr] = q.w;
    }
    if (tid < 128) {
        const float* rp = &g_RP[((size_t)b * Nn + i0 + tid) * 4];
        rp_s[tid*4+0] = rp[0]; rp_s[tid*4+1] = rp[1]; rp_s[tid*4+2] = rp[2];
    }
    __syncthreads();

    float m_old[8], lsum[8];
    u64 O2[8][2];
#pragma unroll
    for (int r = 0; r < 8; r++) {
        m_old[r] = -INFINITY; lsum[r] = 0.f;
        O2[r][0] = 0ull; O2[r][1] = 0ull;
    }

    for (int j0 = 0; j0 < Nn; j0 += 128) {
        // Load K transposed, V natural, P coords
#pragma unroll
        for (int p = 0; p < 8; p++) {
            int d = half + p * 4;
            float4 kv = *(const float4*)&Kg[(size_t)(j0 + lr) * Dd + d];
            Kt[(d+0)*SQ + lr] = kv.x; Kt[(d+1)*SQ + lr] = kv.y;
            Kt[(d+2)*SQ + lr] = kv.z; Kt[(d+3)*SQ + lr] = kv.w;
            float4 vv = *(const float4*)&Vg[(size_t)(j0 + lr) * Dd + d];
            *(float4*)&Vs[lr*SV + d] = vv;
        }
        if (tid < 128) {
            p_s[tid*4+0] = Pg[(j0+tid)*3+0];
            p_s[tid*4+1] = Pg[(j0+tid)*3+1];
            p_s[tid*4+2] = Pg[(j0+tid)*3+2];
        }
        __syncthreads();

        // GEMM1: S = Q K^T (8x8 per thread, f32x2 over col pairs)
        u64 s2[8][4];
#pragma unroll
        for (int r = 0; r < 8; r++)
#pragma unroll
            for (int c = 0; c < 4; c++) s2[r][c] = 0ull;

#pragma unroll 8
        for (int d = 0; d < 64; d++) {
            float a[8];
            *(float4*)(a+0) = *(const float4*)&Qt[d*SQ + ty*8];
            *(float4*)(a+4) = *(const float4*)&Qt[d*SQ + ty*8 + 4];
            ulonglong2 b01 = *(const ulonglong2*)&Kt[d*SQ + tx*8];
            ulonglong2 b23 = *(const ulonglong2*)&Kt[d*SQ + tx*8 + 4];
            u64 B[4] = {b01.x, b01.y, b23.x, b23.y};
            u64 a2[8];
#pragma unroll
            for (int r = 0; r < 8; r++) a2[r] = dup2(a[r]);
#pragma unroll
            for (int r = 0; r < 8; r++)
#pragma unroll
                for (int c = 0; c < 4; c++) s2[r][c] = fma2(a2[r], B[c], s2[r][c]);
        }

        // unpack, scale + bias
        float s[8][8];
#pragma unroll
        for (int r = 0; r < 8; r++)
#pragma unroll
            for (int cp = 0; cp < 4; cp++) {
                float2 v = unpk(s2[r][cp]);
                s[r][cp*2]   = v.x;
                s[r][cp*2+1] = v.y;
            }
        float rp0[8], rp1[8], rp2[8];
#pragma unroll
        for (int r = 0; r < 8; r++) {
            int row = ty*8 + r;
            rp0[r] = rp_s[row*4+0]; rp1[r] = rp_s[row*4+1]; rp2[r] = rp_s[row*4+2];
        }
#pragma unroll
        for (int c = 0; c < 8; c++) {
            int col = tx*8 + c;
            float p0 = p_s[col*4+0], p1 = p_s[col*4+1], p2 = p_s[col*4+2];
#pragma unroll
            for (int r = 0; r < 8; r++)
                s[r][c] = s[r][c]*SCALE + rp0[r]*p0 + rp1[r]*p1 + rp2[r]*p2;
        }

        // online softmax (rows owned by 16-lane segments)
#pragma unroll
        for (int r = 0; r < 8; r++) {
            float mt = s[r][0];
#pragma unroll
            for (int c = 1; c < 8; c++) mt = fmaxf(mt, s[r][c]);
#pragma unroll
            for (int off = 8; off; off >>= 1)
                mt = fmaxf(mt, __shfl_xor_sync(0xffffffffu, mt, off, 16));
            float m_new = fmaxf(m_old[r], mt);
            float alpha = __expf(m_old[r] - m_new);
            float rsum = 0.f;
#pragma unroll
            for (int c = 0; c < 8; c++) {
                float pv = __expf(s[r][c] - m_new);
                s[r][c] = pv;
                rsum += pv;
            }
#pragma unroll
            for (int off = 8; off; off >>= 1)
                rsum += __shfl_xor_sync(0xffffffffu, rsum, off, 16);
            lsum[r] = lsum[r] * alpha + rsum;
            m_old[r] = m_new;
            u64 al2 = dup2(alpha);
            O2[r][0] = mul2(O2[r][0], al2);
            O2[r][1] = mul2(O2[r][1], al2);
            // stash exp(S) tile
            float* prow = &Ps[(ty*8 + r)*SP + tx*8];
            *(float2*)(prow+0) = make_float2(s[r][0], s[r][1]);
            *(float2*)(prow+2) = make_float2(s[r][2], s[r][3]);
            *(float2*)(prow+4) = make_float2(s[r][4], s[r][5]);
            *(float2*)(prow+6) = make_float2(s[r][6], s[r][7]);
        }
        __syncthreads();

        // GEMM2: O += P V (8 rows x 4 cols per thread)
#pragma unroll 8
        for (int j = 0; j < 128; j++) {
            ulonglong2 v2 = *(const ulonglong2*)&Vs[j*SV + tx*4];
#pragma unroll
            for (int r = 0; r < 8; r++) {
                u64 pf = dup2(Ps[(ty*8 + r)*SP + j]);
                O2[r][0] = fma2(pf, v2.x, O2[r][0]);
                O2[r][1] = fma2(pf, v2.y, O2[r][1]);
            }
        }
        __syncthreads();
    }

    // epilogue: normalize, write (B,N,H*D)
#pragma unroll
    for (int r = 0; r < 8; r++) {
        int n = i0 + ty*8 + r;
        float inv = 1.f / lsum[r];
        float2 o0 = unpk(O2[r][0]);
        float2 o1 = unpk(O2[r][1]);
        float* dst = &g_AO[((size_t)b * Nn + n) * Cc + h*Dd + tx*4];
        dst[0] = o0.x * inv; dst[1] = o0.y * inv;
        dst[2] = o1.x * inv; dst[3] = o1.y * inv;
    }
}

// ---------------------------------------------------------------------------
extern "C" void kernel_launch(void* const* d_in, const int* in_sizes, int n_in,
                              void* d_out, int out_size) {
    const float* x         = (const float*)d_in[0];
    const float* R         = (const float*)d_in[1];
    const float* P         = (const float*)d_in[2];
    const float* qkv_w     = (const float*)d_in[3];
    const float* qkv_b     = (const float*)d_in[4];
    const float* proj_w    = (const float*)d_in[5];
    const float* proj_b    = (const float*)d_in[6];
    const float* pos_scale = (const float*)d_in[7];
    float* out = (float*)d_out;

    cudaFuncSetAttribute(flash2_kernel, cudaFuncAttributeMaxDynamicSharedMemorySize,
                         (int)FLASH_SMEM);

    rp_kernel<<<(Bb*Nn + 255) / 256, 256>>>(R, P, pos_scale);

    // QKV: M=8192, Ncols=768, K=256
    gemm2_kernel<true><<<dim3(768/128, (Bb*Nn)/128), 256>>>(x, qkv_w, qkv_b, nullptr);

    // Attention
    flash2_kernel<<<dim3(Nn/128, Hh, Bb), 256, FLASH_SMEM>>>(P);

    // Proj: M=8192, Ncols=256, K=256 (reads g_AO internally)
    gemm2_kernel<false><<<dim3(Cc/128, (Bb*Nn)/128), 256>>>(nullptr, proj_w, proj_b, out);
}

// round 4
// speedup vs baseline: 1.0010x; 1.0010x over previous
#include <cuda_runtime.h>
#include <math.h>

typedef unsigned long long u64;

#define Bb 4
#define Nn 2048
#define Cc 256
#define Hh 4
#define Dd 64
#define SCALE 0.125f   // D^-0.5

// f32x2 packed helpers (Blackwell sm_100+)
__device__ __forceinline__ u64 dup2(float v) {
    u64 r; asm("mov.b64 %0,{%1,%1};" : "=l"(r) : "f"(v)); return r;
}
__device__ __forceinline__ u64 fma2(u64 a, u64 b, u64 c) {
    u64 d; asm("fma.rn.f32x2 %0,%1,%2,%3;" : "=l"(d) : "l"(a), "l"(b), "l"(c)); return d;
}
__device__ __forceinline__ u64 mul2(u64 a, u64 b) {
    u64 d; asm("mul.rn.f32x2 %0,%1,%2;" : "=l"(d) : "l"(a), "l"(b)); return d;
}
__device__ __forceinline__ float2 unpk(u64 p) {
    float2 f; asm("mov.b64 {%0,%1},%2;" : "=f"(f.x), "=f"(f.y) : "l"(p)); return f;
}

// Scratch (device globals; no allocations allowed)
__device__ __align__(16) float g_Q[Bb*Hh*Nn*Dd];
__device__ __align__(16) float g_K[Bb*Hh*Nn*Dd];
__device__ __align__(16) float g_V[Bb*Hh*Nn*Dd];
__device__ __align__(16) float g_RP[Bb*Nn*4];      // pre-multiplied by pos_scale
__device__ __align__(16) float g_AO[Bb*Nn*Cc];     // attention output before proj

// ---------------------------------------------------------------------------
// RP[b,j,c] = pos_scale * sum_d R[b,c,d] * P[j,d]
// ---------------------------------------------------------------------------
__global__ void rp_kernel(const float* __restrict__ R, const float* __restrict__ P,
                          const float* __restrict__ pos_scale) {
    int idx = blockIdx.x * blockDim.x + threadIdx.x;
    if (idx >= Bb * Nn) return;
    int b = idx / Nn, j = idx % Nn;
    float p0 = P[j*3+0], p1 = P[j*3+1], p2 = P[j*3+2];
    float ps = *pos_scale;
    const float* Rb = R + b*9;
#pragma unroll
    for (int c = 0; c < 3; c++)
        g_RP[idx*4 + c] = ps * (Rb[c*3+0]*p0 + Rb[c*3+1]*p1 + Rb[c*3+2]*p2);
    g_RP[idx*4 + 3] = 0.f;
}

// ---------------------------------------------------------------------------
// NT GEMM (f32x2): out[m,c] = sum_k A[m,k] * W[c,k] + bias[c]
// 128x128 CTA tile, 8x8 thread tile, K-tile 16, 256 threads.
// ---------------------------------------------------------------------------
#define SG 132   // smem k-major stride

template<bool IS_QKV>
__global__ __launch_bounds__(256)
void gemm2_kernel(const float* __restrict__ A, const float* __restrict__ W,
                  const float* __restrict__ bias, float* __restrict__ Out) {
    __shared__ __align__(16) float As[16 * SG];
    __shared__ __align__(16) float Ws[16 * SG];

    const float* Ap;
    if constexpr (IS_QKV) Ap = A; else Ap = g_AO;

    int tid = threadIdx.x;
    int tx = tid & 15, ty = tid >> 4;
    int m0 = blockIdx.y * 128, n0 = blockIdx.x * 128;
    int lr = tid >> 1;            // 0..127
    int kq = (tid & 1) * 8;       // 0 or 8

    u64 acc[8][4];
#pragma unroll
    for (int r = 0; r < 8; r++)
#pragma unroll
        for (int c = 0; c < 4; c++) acc[r][c] = 0ull;

    for (int k0 = 0; k0 < Cc; k0 += 16) {
        float4 a0 = *(const float4*)&Ap[(size_t)(m0 + lr) * Cc + k0 + kq];
        float4 a1 = *(const float4*)&Ap[(size_t)(m0 + lr) * Cc + k0 + kq + 4];
        float4 w0 = *(const float4*)&W [(size_t)(n0 + lr) * Cc + k0 + kq];
        float4 w1 = *(const float4*)&W [(size_t)(n0 + lr) * Cc + k0 + kq + 4];
        As[(kq+0)*SG+lr]=a0.x; As[(kq+1)*SG+lr]=a0.y; As[(kq+2)*SG+lr]=a0.z; As[(kq+3)*SG+lr]=a0.w;
        As[(kq+4)*SG+lr]=a1.x; As[(kq+5)*SG+lr]=a1.y; As[(kq+6)*SG+lr]=a1.z; As[(kq+7)*SG+lr]=a1.w;
        Ws[(kq+0)*SG+lr]=w0.x; Ws[(kq+1)*SG+lr]=w0.y; Ws[(kq+2)*SG+lr]=w0.z; Ws[(kq+3)*SG+lr]=w0.w;
        Ws[(kq+4)*SG+lr]=w1.x; Ws[(kq+5)*SG+lr]=w1.y; Ws[(kq+6)*SG+lr]=w1.z; Ws[(kq+7)*SG+lr]=w1.w;
        __syncthreads();
#pragma unroll
        for (int kk = 0; kk < 16; kk++) {
            float a[8];
            *(float4*)(a+0) = *(const float4*)&As[kk*SG + ty*8];
            *(float4*)(a+4) = *(const float4*)&As[kk*SG + ty*8 + 4];
            ulonglong2 b01 = *(const ulonglong2*)&Ws[kk*SG + tx*8];
            ulonglong2 b23 = *(const ulonglong2*)&Ws[kk*SG + tx*8 + 4];
            u64 B[4] = {b01.x, b01.y, b23.x, b23.y};
            u64 a2[8];
#pragma unroll
            for (int r = 0; r < 8; r++) a2[r] = dup2(a[r]);
#pragma unroll
            for (int r = 0; r < 8; r++)
#pragma unroll
                for (int c = 0; c < 4; c++) acc[r][c] = fma2(a2[r], B[c], acc[r][c]);
        }
        __syncthreads();
    }

#pragma unroll
    for (int r = 0; r < 8; r++) {
        int m = m0 + ty*8 + r;
#pragma unroll
        for (int cp = 0; cp < 4; cp++) {
            float2 v = unpk(acc[r][cp]);
            int c0 = n0 + tx*8 + cp*2;
            float o0 = v.x + bias[c0];
            float o1 = v.y + bias[c0+1];
            if constexpr (IS_QKV) {
#pragma unroll
                for (int e = 0; e < 2; e++) {
                    int c = c0 + e;
                    float val = e ? o1 : o0;
                    int bb = m >> 11;
                    int n  = m & (Nn - 1);
                    int which = c >> 8;
                    int h = (c >> 6) & (Hh - 1);
                    int d = c & (Dd - 1);
                    float* dst = (which == 0) ? g_Q : ((which == 1) ? g_K : g_V);
                    dst[((size_t)(bb*Hh + h) * Nn + n) * Dd + d] = val;
                }
            } else {
                Out[(size_t)m * Cc + c0] = o0;
                Out[(size_t)m * Cc + c0 + 1] = o1;
            }
        }
    }
}

// ---------------------------------------------------------------------------
// Flash attention (f32x2): one CTA per (b, h, 128-row q tile). 128-wide kv tiles.
// S = Q K^T * SCALE + RP_i . P_j ; O = softmax(S) V
// 256 threads, 8x8 per-thread S tile, 8x4 per-thread O tile.
// ---------------------------------------------------------------------------
#define SQ 132   // Qt/Kt stride (d-major)
#define SV 72    // Vs stride (j-major)
#define SP 136   // Ps stride (i-major)
#define FLASH_FLOATS (64*SQ*2 + 128*SV + 128*SP + 512 + 512)
#define FLASH_SMEM (FLASH_FLOATS * sizeof(float))

__global__ __launch_bounds__(256, 1)
void flash2_kernel(const float* __restrict__ Pg) {
    extern __shared__ __align__(16) float sm[];
    float* Qt   = sm;                  // [d][i]   64 x SQ
    float* Kt   = Qt + 64 * SQ;        // [d][j]   64 x SQ
    float* Vs   = Kt + 64 * SQ;        // [j][d]  128 x SV
    float* Ps   = Vs + 128 * SV;       // [i][j]  128 x SP
    float* rp_s = Ps + 128 * SP;       // [i][4]
    float* p_s  = rp_s + 512;          // [j][4]

    int b = blockIdx.z, h = blockIdx.y;
    int i0 = blockIdx.x * 128;
    int tid = threadIdx.x;
    int tx = tid & 15, ty = tid >> 4;
    int lr = tid >> 1;              // 0..127
    int half = (tid & 1) * 32;      // d half

    const float* Qg = g_Q + (size_t)(b*Hh + h) * Nn * Dd;
    const float* Kg = g_K + (size_t)(b*Hh + h) * Nn * Dd;
    const float* Vg = g_V + (size_t)(b*Hh + h) * Nn * Dd;

    // Load Q tile transposed: Qt[d][i]
#pragma unroll
    for (int p = 0; p < 8; p++) {
        int d = half + p * 4;
        float4 q = *(const float4*)&Qg[(size_t)(i0 + lr) * Dd + d];
        Qt[(d+0)*SQ + lr] = q.x; Qt[(d+1)*SQ + lr] = q.y;
        Qt[(d+2)*SQ + lr] = q.z; Qt[(d+3)*SQ + lr] = q.w;
    }
    if (tid < 128) {
        const float* rp = &g_RP[((size_t)b * Nn + i0 + tid) * 4];
        rp_s[tid*4+0] = rp[0]; rp_s[tid*4+1] = rp[1]; rp_s[tid*4+2] = rp[2];
    }
    __syncthreads();

    float m_old[8], lsum[8];
    u64 O2[8][2];
#pragma unroll
    for (int r = 0; r < 8; r++) {
        m_old[r] = -INFINITY; lsum[r] = 0.f;
        O2[r][0] = 0ull; O2[r][1] = 0ull;
    }

    for (int j0 = 0; j0 < Nn; j0 += 128) {
        // Load K transposed, V natural, P coords
#pragma unroll
        for (int p = 0; p < 8; p++) {
            int d = half + p * 4;
            float4 kv = *(const float4*)&Kg[(size_t)(j0 + lr) * Dd + d];
            Kt[(d+0)*SQ + lr] = kv.x; Kt[(d+1)*SQ + lr] = kv.y;
            Kt[(d+2)*SQ + lr] = kv.z; Kt[(d+3)*SQ + lr] = kv.w;
            float4 vv = *(const float4*)&Vg[(size_t)(j0 + lr) * Dd + d];
            *(float4*)&Vs[lr*SV + d] = vv;
        }
        if (tid < 128) {
            p_s[tid*4+0] = Pg[(j0+tid)*3+0];
            p_s[tid*4+1] = Pg[(j0+tid)*3+1];
            p_s[tid*4+2] = Pg[(j0+tid)*3+2];
        }
        __syncthreads();

        // GEMM1: S = Q K^T (8x8 per thread, f32x2 over col pairs)
        u64 s2[8][4];
#pragma unroll
        for (int r = 0; r < 8; r++)
#pragma unroll
            for (int c = 0; c < 4; c++) s2[r][c] = 0ull;

#pragma unroll 8
        for (int d = 0; d < 64; d++) {
            float a[8];
            *(float4*)(a+0) = *(const float4*)&Qt[d*SQ + ty*8];
            *(float4*)(a+4) = *(const float4*)&Qt[d*SQ + ty*8 + 4];
            ulonglong2 b01 = *(const ulonglong2*)&Kt[d*SQ + tx*8];
            ulonglong2 b23 = *(const ulonglong2*)&Kt[d*SQ + tx*8 + 4];
            u64 B[4] = {b01.x, b01.y, b23.x, b23.y};
            u64 a2[8];
#pragma unroll
            for (int r = 0; r < 8; r++) a2[r] = dup2(a[r]);
#pragma unroll
            for (int r = 0; r < 8; r++)
#pragma unroll
                for (int c = 0; c < 4; c++) s2[r][c] = fma2(a2[r], B[c], s2[r][c]);
        }

        // unpack, scale + bias
        float s[8][8];
#pragma unroll
        for (int r = 0; r < 8; r++)
#pragma unroll
            for (int cp = 0; cp < 4; cp++) {
                float2 v = unpk(s2[r][cp]);
                s[r][cp*2]   = v.x;
                s[r][cp*2+1] = v.y;
            }
        float rp0[8], rp1[8], rp2[8];
#pragma unroll
        for (int r = 0; r < 8; r++) {
            int row = ty*8 + r;
            rp0[r] = rp_s[row*4+0]; rp1[r] = rp_s[row*4+1]; rp2[r] = rp_s[row*4+2];
        }
#pragma unroll
        for (int c = 0; c < 8; c++) {
            int col = tx*8 + c;
            float p0 = p_s[col*4+0], p1 = p_s[col*4+1], p2 = p_s[col*4+2];
#pragma unroll
            for (int r = 0; r < 8; r++)
                s[r][c] = s[r][c]*SCALE + rp0[r]*p0 + rp1[r]*p1 + rp2[r]*p2;
        }

        // online softmax (rows owned by 16-lane segments)
#pragma unroll
        for (int r = 0; r < 8; r++) {
            float mt = s[r][0];
#pragma unroll
            for (int c = 1; c < 8; c++) mt = fmaxf(mt, s[r][c]);
#pragma unroll
            for (int off = 8; off; off >>= 1)
                mt = fmaxf(mt, __shfl_xor_sync(0xffffffffu, mt, off, 16));
            float m_new = fmaxf(m_old[r], mt);
            float alpha = __expf(m_old[r] - m_new);
            float rsum = 0.f;
#pragma unroll
            for (int c = 0; c < 8; c++) {
                float pv = __expf(s[r][c] - m_new);
                s[r][c] = pv;
                rsum += pv;
            }
#pragma unroll
            for (int off = 8; off; off >>= 1)
                rsum += __shfl_xor_sync(0xffffffffu, rsum, off, 16);
            lsum[r] = lsum[r] * alpha + rsum;
            m_old[r] = m_new;
            u64 al2 = dup2(alpha);
            O2[r][0] = mul2(O2[r][0], al2);
            O2[r][1] = mul2(O2[r][1], al2);
            // stash exp(S) tile
            float* prow = &Ps[(ty*8 + r)*SP + tx*8];
            *(float2*)(prow+0) = make_float2(s[r][0], s[r][1]);
            *(float2*)(prow+2) = make_float2(s[r][2], s[r][3]);
            *(float2*)(prow+4) = make_float2(s[r][4], s[r][5]);
            *(float2*)(prow+6) = make_float2(s[r][6], s[r][7]);
        }
        __syncthreads();

        // GEMM2: O += P V (8 rows x 4 cols per thread)
#pragma unroll 8
        for (int j = 0; j < 128; j++) {
            ulonglong2 v2 = *(const ulonglong2*)&Vs[j*SV + tx*4];
#pragma unroll
            for (int r = 0; r < 8; r++) {
                u64 pf = dup2(Ps[(ty*8 + r)*SP + j]);
                O2[r][0] = fma2(pf, v2.x, O2[r][0]);
                O2[r][1] = fma2(pf, v2.y, O2[r][1]);
            }
        }
        __syncthreads();
    }

    // epilogue: normalize, write (B,N,H*D)
#pragma unroll
    for (int r = 0; r < 8; r++) {
        int n = i0 + ty*8 + r;
        float inv = 1.f / lsum[r];
        float2 o0 = unpk(O2[r][0]);
        float2 o1 = unpk(O2[r][1]);
        float* dst = &g_AO[((size_t)b * Nn + n) * Cc + h*Dd + tx*4];
        dst[0] = o0.x * inv; dst[1] = o0.y * inv;
        dst[2] = o1.x * inv; dst[3] = o1.y * inv;
    }
}

// ---------------------------------------------------------------------------
extern "C" void kernel_launch(void* const* d_in, const int* in_sizes, int n_in,
                              void* d_out, int out_size) {
    const float* x         = (const float*)d_in[0];
    const float* R         = (const float*)d_in[1];
    const float* P         = (const float*)d_in[2];
    const float* qkv_w     = (const float*)d_in[3];
    const float* qkv_b     = (const float*)d_in[4];
    const float* proj_w    = (const float*)d_in[5];
    const float* proj_b    = (const float*)d_in[6];
    const float* pos_scale = (const float*)d_in[7];
    float* out = (float*)d_out;

    cudaFuncSetAttribute(flash2_kernel, cudaFuncAttributeMaxDynamicSharedMemorySize,
                         (int)FLASH_SMEM);

    rp_kernel<<<(Bb*Nn + 255) / 256, 256>>>(R, P, pos_scale);

    // QKV: M=8192, Ncols=768, K=256
    gemm2_kernel<true><<<dim3(768/128, (Bb*Nn)/128), 256>>>(x, qkv_w, qkv_b, nullptr);

    // Attention
    flash2_kernel<<<dim3(Nn/128, Hh, Bb), 256, FLASH_SMEM>>>(P);

    // Proj: M=8192, Ncols=256, K=256 (reads g_AO internally)
    gemm2_kernel<false><<<dim3(Cc/128, (Bb*Nn)/128), 256>>>(nullptr, proj_w, proj_b, out);
}

// round 7
// speedup vs baseline: 1.6214x; 1.6198x over previous
#include <cuda_runtime.h>
#include <cstdint>
#include <math.h>

typedef unsigned long long u64;

#define Bb 4
#define Nn 2048
#define Cc 256
#define Hh 4
#define Dd 64
#define K1EXP 0.18033688011112042f   // 0.125 * log2(e)
#define LOG2E 1.4426950408889634f

// ===================== f32x2 helpers =====================
__device__ __forceinline__ u64 dup2(float v) {
    u64 r; asm("mov.b64 %0,{%1,%1};" : "=l"(r) : "f"(v)); return r;
}
__device__ __forceinline__ u64 fma2(u64 a, u64 b, u64 c) {
    u64 d; asm("fma.rn.f32x2 %0,%1,%2,%3;" : "=l"(d) : "l"(a), "l"(b), "l"(c)); return d;
}
__device__ __forceinline__ float2 unpk(u64 p) {
    float2 f; asm("mov.b64 {%0,%1},%2;" : "=f"(f.x), "=f"(f.y) : "l"(p)); return f;
}

// ===================== mma.sync tf32 helpers =====================
__device__ __forceinline__ uint32_t tf32u(float x) {
    uint32_t u; asm("cvt.rna.tf32.f32 %0,%1;" : "=r"(u) : "f"(x)); return u;
}
__device__ __forceinline__ float tf32f(float x) { return __uint_as_float(tf32u(x)); }
__device__ __forceinline__ float ex2f(float x) {
    float y; asm("ex2.approx.f32 %0,%1;" : "=f"(y) : "f"(x)); return y;
}
__device__ __forceinline__ void mma_tf32(float c[4], const uint32_t a[4],
                                         uint32_t b0, uint32_t b1) {
    asm volatile("mma.sync.aligned.m16n8k8.row.col.f32.tf32.tf32.f32 "
        "{%0,%1,%2,%3}, {%4,%5,%6,%7}, {%8,%9}, {%0,%1,%2,%3};"
        : "+f"(c[0]), "+f"(c[1]), "+f"(c[2]), "+f"(c[3])
        : "r"(a[0]), "r"(a[1]), "r"(a[2]), "r"(a[3]), "r"(b0), "r"(b1));
}

// ===================== scratch =====================
__device__ __align__(16) float g_Q[Bb*Hh*Nn*Dd];
__device__ __align__(16) float g_K[Bb*Hh*Nn*Dd];
__device__ __align__(16) float g_V[Bb*Hh*Nn*Dd];
__device__ __align__(16) float g_RP[Bb*Nn*4];    // rp * pos_scale * log2(e), padded float4
__device__ __align__(16) float g_AO[Bb*Nn*Cc];

// ---------------------------------------------------------------------------
// g_RP[b,j,:] = pos_scale * log2e * (R[b] @ P[j])
// ---------------------------------------------------------------------------
__global__ void rp_kernel(const float* __restrict__ R, const float* __restrict__ P,
                          const float* __restrict__ pos_scale) {
    int idx = blockIdx.x * blockDim.x + threadIdx.x;
    if (idx >= Bb * Nn) return;
    int b = idx / Nn, j = idx % Nn;
    float p0 = P[j*3+0], p1 = P[j*3+1], p2 = P[j*3+2];
    float ps = *pos_scale * LOG2E;
    const float* Rb = R + b*9;
#pragma unroll
    for (int c = 0; c < 3; c++)
        g_RP[idx*4 + c] = ps * (Rb[c*3+0]*p0 + Rb[c*3+1]*p1 + Rb[c*3+2]*p2);
    g_RP[idx*4 + 3] = 0.f;
}

// ---------------------------------------------------------------------------
// f32x2 NT GEMM (unchanged; known good)
// ---------------------------------------------------------------------------
#define SG 132

template<bool IS_QKV>
__global__ __launch_bounds__(256)
void gemm2_kernel(const float* __restrict__ A, const float* __restrict__ W,
                  const float* __restrict__ bias, float* __restrict__ Out) {
    __shared__ __align__(16) float As[16 * SG];
    __shared__ __align__(16) float Ws[16 * SG];

    const float* Ap;
    if constexpr (IS_QKV) Ap = A; else Ap = g_AO;

    int tid = threadIdx.x;
    int tx = tid & 15, ty = tid >> 4;
    int m0 = blockIdx.y * 128, n0 = blockIdx.x * 128;
    int lr = tid >> 1;
    int kq = (tid & 1) * 8;

    u64 acc[8][4];
#pragma unroll
    for (int r = 0; r < 8; r++)
#pragma unroll
        for (int c = 0; c < 4; c++) acc[r][c] = 0ull;

    for (int k0 = 0; k0 < Cc; k0 += 16) {
        float4 a0 = *(const float4*)&Ap[(size_t)(m0 + lr) * Cc + k0 + kq];
        float4 a1 = *(const float4*)&Ap[(size_t)(m0 + lr) * Cc + k0 + kq + 4];
        float4 w0 = *(const float4*)&W [(size_t)(n0 + lr) * Cc + k0 + kq];
        float4 w1 = *(const float4*)&W [(size_t)(n0 + lr) * Cc + k0 + kq + 4];
        As[(kq+0)*SG+lr]=a0.x; As[(kq+1)*SG+lr]=a0.y; As[(kq+2)*SG+lr]=a0.z; As[(kq+3)*SG+lr]=a0.w;
        As[(kq+4)*SG+lr]=a1.x; As[(kq+5)*SG+lr]=a1.y; As[(kq+6)*SG+lr]=a1.z; As[(kq+7)*SG+lr]=a1.w;
        Ws[(kq+0)*SG+lr]=w0.x; Ws[(kq+1)*SG+lr]=w0.y; Ws[(kq+2)*SG+lr]=w0.z; Ws[(kq+3)*SG+lr]=w0.w;
        Ws[(kq+4)*SG+lr]=w1.x; Ws[(kq+5)*SG+lr]=w1.y; Ws[(kq+6)*SG+lr]=w1.z; Ws[(kq+7)*SG+lr]=w1.w;
        __syncthreads();
#pragma unroll
        for (int kk = 0; kk < 16; kk++) {
            float a[8];
            *(float4*)(a+0) = *(const float4*)&As[kk*SG + ty*8];
            *(float4*)(a+4) = *(const float4*)&As[kk*SG + ty*8 + 4];
            ulonglong2 b01 = *(const ulonglong2*)&Ws[kk*SG + tx*8];
            ulonglong2 b23 = *(const ulonglong2*)&Ws[kk*SG + tx*8 + 4];
            u64 B[4] = {b01.x, b01.y, b23.x, b23.y};
            u64 a2[8];
#pragma unroll
            for (int r = 0; r < 8; r++) a2[r] = dup2(a[r]);
#pragma unroll
            for (int r = 0; r < 8; r++)
#pragma unroll
                for (int c = 0; c < 4; c++) acc[r][c] = fma2(a2[r], B[c], acc[r][c]);
        }
        __syncthreads();
    }

#pragma unroll
    for (int r = 0; r < 8; r++) {
        int m = m0 + ty*8 + r;
#pragma unroll
        for (int cp = 0; cp < 4; cp++) {
            float2 v = unpk(acc[r][cp]);
            int c0 = n0 + tx*8 + cp*2;
            float o0 = v.x + bias[c0];
            float o1 = v.y + bias[c0+1];
            if constexpr (IS_QKV) {
#pragma unroll
                for (int e = 0; e < 2; e++) {
                    int c = c0 + e;
                    float val = e ? o1 : o0;
                    int bb = m >> 11;
                    int n  = m & (Nn - 1);
                    int which = c >> 8;
                    int h = (c >> 6) & (Hh - 1);
                    int d = c & (Dd - 1);
                    float* dst = (which == 0) ? g_Q : ((which == 1) ? g_K : g_V);
                    dst[((size_t)(bb*Hh + h) * Nn + n) * Dd + d] = val;
                }
            } else {
                Out[(size_t)m * Cc + c0] = o0;
                Out[(size_t)m * Cc + c0 + 1] = o1;
            }
        }
    }
}

// ---------------------------------------------------------------------------
// Flash attention via mma.sync.m16n8k8.tf32. No-max single-pass softmax.
// CTA = (b, h, 128 q rows); 8 warps x 16 rows; kv tiles of 128.
// ---------------------------------------------------------------------------
#define SK 72                         // K/V smem stride (floats)
#define SPP 132                       // P (and Q staging) smem stride (floats)
#define KS_OFF 0
#define VS_OFF (128*SK)               // 9216
#define PS_OFF (2*128*SK)             // 18432
#define PJ_OFF (PS_OFF + 128*SPP)     // 35328
#define FL_FLOATS (PJ_OFF + 128*4)    // 35840
#define FL_SMEM (FL_FLOATS * 4)       // 143360 B

__global__ __launch_bounds__(256, 1)
void flash_mma_kernel(const float* __restrict__ Pg) {
    extern __shared__ __align__(16) float sm[];
    float* Ks  = sm + KS_OFF;
    float* Vs  = sm + VS_OFF;
    float* Ps  = sm + PS_OFF;
    float* pj4 = sm + PJ_OFF;

    int tid = threadIdx.x;
    int w = tid >> 5, t = tid & 31;
    int g = t >> 2, q = t & 3;
    int b = blockIdx.z, h = blockIdx.y;
    int i0 = blockIdx.x * 128;

    const float* Qg = g_Q + (size_t)(b*Hh + h) * Nn * Dd;
    const float* Kg = g_K + (size_t)(b*Hh + h) * Nn * Dd;
    const float* Vg = g_V + (size_t)(b*Hh + h) * Nn * Dd;

    // ---- stage Q (tf32) into Ps region, then pull fragments to registers ----
    {
        int row = tid >> 1, dh = (tid & 1) * 32;
        const float* src = Qg + (size_t)(i0 + row) * Dd + dh;
#pragma unroll
        for (int i = 0; i < 8; i++) {
            float4 v = *(const float4*)(src + i*4);
            v.x = tf32f(v.x); v.y = tf32f(v.y); v.z = tf32f(v.z); v.w = tf32f(v.w);
            *(float4*)&Ps[row*SPP + dh + i*4] = v;
        }
    }
    __syncthreads();

    int r0 = w*16 + g, r1 = r0 + 8;
    uint32_t aQ[8][4];
#pragma unroll
    for (int kk = 0; kk < 8; kk++) {
        aQ[kk][0] = __float_as_uint(Ps[r0*SPP + kk*8 + q]);
        aQ[kk][1] = __float_as_uint(Ps[r1*SPP + kk*8 + q]);
        aQ[kk][2] = __float_as_uint(Ps[r0*SPP + kk*8 + q + 4]);
        aQ[kk][3] = __float_as_uint(Ps[r1*SPP + kk*8 + q + 4]);
    }
    float4 rpl0 = *(const float4*)&g_RP[((size_t)b*Nn + i0 + r0) * 4];
    float4 rpl1 = *(const float4*)&g_RP[((size_t)b*Nn + i0 + r1) * 4];

    float o[8][4];
#pragma unroll
    for (int n = 0; n < 8; n++)
#pragma unroll
        for (int c = 0; c < 4; c++) o[n][c] = 0.f;
    float lsum0 = 0.f, lsum1 = 0.f;

    for (int tt = 0; tt < Nn / 128; tt++) {
        int j0 = tt * 128;
        // ---- stage K, V (tf32), and p_j coords ----
        {
            int row = tid >> 1, dh = (tid & 1) * 32;
            const float* ksrc = Kg + (size_t)(j0 + row) * Dd + dh;
            const float* vsrc = Vg + (size_t)(j0 + row) * Dd + dh;
#pragma unroll
            for (int i = 0; i < 8; i++) {
                float4 kv = *(const float4*)(ksrc + i*4);
                kv.x = tf32f(kv.x); kv.y = tf32f(kv.y); kv.z = tf32f(kv.z); kv.w = tf32f(kv.w);
                *(float4*)&Ks[row*SK + dh + i*4] = kv;
                float4 vv = *(const float4*)(vsrc + i*4);
                vv.x = tf32f(vv.x); vv.y = tf32f(vv.y); vv.z = tf32f(vv.z); vv.w = tf32f(vv.w);
                *(float4*)&Vs[row*SK + dh + i*4] = vv;
            }
        }
        if (tid < 128) {
            const float* pp = Pg + (size_t)(j0 + tid) * 3;
            *(float4*)&pj4[tid*4] = make_float4(pp[0], pp[1], pp[2], 0.f);
        }
        __syncthreads();

        // ---- GEMM1 + exp + P store, one 16x8 tile at a time ----
#pragma unroll
        for (int ni = 0; ni < 16; ni++) {
            float c[4] = {0.f, 0.f, 0.f, 0.f};
            int jb = ni*8 + g;
#pragma unroll
            for (int kk = 0; kk < 8; kk++) {
                uint32_t b0 = __float_as_uint(Ks[jb*SK + kk*8 + q]);
                uint32_t b1 = __float_as_uint(Ks[jb*SK + kk*8 + q + 4]);
                mma_tf32(c, aQ[kk], b0, b1);
            }
            int clo = ni*8 + q*2;
            float4 plo = *(const float4*)&pj4[clo*4];
            float4 phi = *(const float4*)&pj4[(clo+1)*4];
            float dl0 = rpl0.x*plo.x + rpl0.y*plo.y + rpl0.z*plo.z;
            float dh0 = rpl0.x*phi.x + rpl0.y*phi.y + rpl0.z*phi.z;
            float dl1 = rpl1.x*plo.x + rpl1.y*plo.y + rpl1.z*plo.z;
            float dh1 = rpl1.x*phi.x + rpl1.y*phi.y + rpl1.z*phi.z;
            float e00 = ex2f(fmaf(c[0], K1EXP, dl0));
            float e01 = ex2f(fmaf(c[1], K1EXP, dh0));
            float e10 = ex2f(fmaf(c[2], K1EXP, dl1));
            float e11 = ex2f(fmaf(c[3], K1EXP, dh1));
            lsum0 += e00 + e01;
            lsum1 += e10 + e11;
            *(float2*)&Ps[r0*SPP + clo] = make_float2(tf32f(e00), tf32f(e01));
            *(float2*)&Ps[r1*SPP + clo] = make_float2(tf32f(e10), tf32f(e11));
        }
        __syncthreads();

        // ---- GEMM2: O += P @ V ----
#pragma unroll
        for (int kk = 0; kk < 16; kk++) {
            uint32_t aP[4];
            aP[0] = __float_as_uint(Ps[r0*SPP + kk*8 + q]);
            aP[1] = __float_as_uint(Ps[r1*SPP + kk*8 + q]);
            aP[2] = __float_as_uint(Ps[r0*SPP + kk*8 + q + 4]);
            aP[3] = __float_as_uint(Ps[r1*SPP + kk*8 + q + 4]);
#pragma unroll
            for (int n = 0; n < 8; n++) {
                uint32_t b0 = __float_as_uint(Vs[(kk*8 + q)*SK + n*8 + g]);
                uint32_t b1 = __float_as_uint(Vs[(kk*8 + q + 4)*SK + n*8 + g]);
                mma_tf32(o[n], aP, b0, b1);
            }
        }
        __syncthreads();
    }

    // ---- reduce row sums over quad lanes, normalize, write ----
    lsum0 += __shfl_xor_sync(0xffffffffu, lsum0, 1);
    lsum0 += __shfl_xor_sync(0xffffffffu, lsum0, 2);
    lsum1 += __shfl_xor_sync(0xffffffffu, lsum1, 1);
    lsum1 += __shfl_xor_sync(0xffffffffu, lsum1, 2);
    float inv0 = 1.f / lsum0, inv1 = 1.f / lsum1;

    float* dst0 = g_AO + ((size_t)b*Nn + i0 + r0) * Cc + h*Dd;
    float* dst1 = g_AO + ((size_t)b*Nn + i0 + r1) * Cc + h*Dd;
#pragma unroll
    for (int n = 0; n < 8; n++) {
        int col = n*8 + q*2;
        *(float2*)(dst0 + col) = make_float2(o[n][0]*inv0, o[n][1]*inv0);
        *(float2*)(dst1 + col) = make_float2(o[n][2]*inv1, o[n][3]*inv1);
    }
}

// ---------------------------------------------------------------------------
extern "C" void kernel_launch(void* const* d_in, const int* in_sizes, int n_in,
                              void* d_out, int out_size) {
    const float* x         = (const float*)d_in[0];
    const float* R         = (const float*)d_in[1];
    const float* P         = (const float*)d_in[2];
    const float* qkv_w     = (const float*)d_in[3];
    const float* qkv_b     = (const float*)d_in[4];
    const float* proj_w    = (const float*)d_in[5];
    const float* proj_b    = (const float*)d_in[6];
    const float* pos_scale = (const float*)d_in[7];
    float* out = (float*)d_out;

    cudaFuncSetAttribute(flash_mma_kernel, cudaFuncAttributeMaxDynamicSharedMemorySize, FL_SMEM);

    rp_kernel<<<(Bb*Nn + 255) / 256, 256>>>(R, P, pos_scale);
    gemm2_kernel<true><<<dim3(768/128, (Bb*Nn)/128), 256>>>(x, qkv_w, qkv_b, nullptr);
    flash_mma_kernel<<<dim3(Nn/128, Hh, Bb), 256, FL_SMEM>>>(P);
    gemm2_kernel<false><<<dim3(Cc/128, (Bb*Nn)/128), 256>>>(nullptr, proj_w, proj_b, out);
}

// round 8
// speedup vs baseline: 1.7919x; 1.1051x over previous
#include <cuda_runtime.h>
#include <cstdint>
#include <math.h>

#define Bb 4
#define Nn 2048
#define Cc 256
#define Hh 4
#define Dd 64
#define K1EXP 0.18033688011112042f   // 0.125 * log2(e)
#define LOG2E 1.4426950408889634f

// ===================== tf32 / mma helpers =====================
__device__ __forceinline__ uint32_t tf32u(float x) {
    uint32_t u; asm("cvt.rna.tf32.f32 %0,%1;" : "=r"(u) : "f"(x)); return u;
}
__device__ __forceinline__ float tf32f(float x) { return __uint_as_float(tf32u(x)); }
__device__ __forceinline__ float ex2f(float x) {
    float y; asm("ex2.approx.f32 %0,%1;" : "=f"(y) : "f"(x)); return y;
}
__device__ __forceinline__ void mma_tf32(float c[4], const uint32_t a[4],
                                         uint32_t b0, uint32_t b1) {
    asm volatile("mma.sync.aligned.m16n8k8.row.col.f32.tf32.tf32.f32 "
        "{%0,%1,%2,%3}, {%4,%5,%6,%7}, {%8,%9}, {%0,%1,%2,%3};"
        : "+f"(c[0]), "+f"(c[1]), "+f"(c[2]), "+f"(c[3])
        : "r"(a[0]), "r"(a[1]), "r"(a[2]), "r"(a[3]), "r"(b0), "r"(b1));
}
__device__ __forceinline__ float4 tf32x4(float4 v) {
    return make_float4(tf32f(v.x), tf32f(v.y), tf32f(v.z), tf32f(v.w));
}
__device__ __forceinline__ float4 sub4(float4 a, float4 b) {
    return make_float4(a.x-b.x, a.y-b.y, a.z-b.z, a.w-b.w);
}

// ===================== scratch =====================
__device__ __align__(16) float g_Q[Bb*Hh*Nn*Dd];
__device__ __align__(16) float g_K[Bb*Hh*Nn*Dd];
__device__ __align__(16) float g_V[Bb*Hh*Nn*Dd];
__device__ __align__(16) float g_RP[Bb*Nn*4];    // rp * pos_scale * log2(e)
__device__ __align__(16) float g_AO[Bb*Nn*Cc];

// ---------------------------------------------------------------------------
__global__ void rp_kernel(const float* __restrict__ R, const float* __restrict__ P,
                          const float* __restrict__ pos_scale) {
    int idx = blockIdx.x * blockDim.x + threadIdx.x;
    if (idx >= Bb * Nn) return;
    int b = idx / Nn, j = idx % Nn;
    float p0 = P[j*3+0], p1 = P[j*3+1], p2 = P[j*3+2];
    float ps = *pos_scale * LOG2E;
    const float* Rb = R + b*9;
#pragma unroll
    for (int c = 0; c < 3; c++)
        g_RP[idx*4 + c] = ps * (Rb[c*3+0]*p0 + Rb[c*3+1]*p1 + Rb[c*3+2]*p2);
    g_RP[idx*4 + 3] = 0.f;
}

// ---------------------------------------------------------------------------
// Tensor-core NT GEMM: out[m,n] = sum_k A[m,k]*W[n,k] + bias[n]
// 3-pass tf32 hi/lo split (error ~2^-22). CTA tile 128m x 64n, 8 warps (4x2),
// warp = 32m x 32n, K-tile 16, software-pipelined gmem staging.
// ---------------------------------------------------------------------------
#define GST 20   // smem row stride (floats)

template<bool IS_QKV>
__global__ __launch_bounds__(256)
void gemm_mma_kernel(const float* __restrict__ A, const float* __restrict__ W,
                     const float* __restrict__ bias, float* __restrict__ Out) {
    __shared__ __align__(16) float As_h[128*GST];
    __shared__ __align__(16) float As_l[128*GST];
    __shared__ __align__(16) float Ws_h[64*GST];
    __shared__ __align__(16) float Ws_l[64*GST];

    const float* Ap;
    if constexpr (IS_QKV) Ap = A; else Ap = g_AO;

    int tid = threadIdx.x;
    int w = tid >> 5, lane = tid & 31, g = lane >> 2, q = lane & 3;
    int wm = (w & 3) * 32, wn = (w >> 2) * 32;
    int m0 = blockIdx.y * 128, n0 = blockIdx.x * 64;

    int ar = tid >> 1, ak = (tid & 1) * 8;   // A staging: row, k-offset
    int wr = tid >> 2, wk = (tid & 3) * 4;   // W staging

    float4 sa0, sa1, sw0;
    const float* Abase = Ap + (size_t)(m0 + ar) * Cc + ak;
    const float* Wbase = W  + (size_t)(n0 + wr) * Cc + wk;

    sa0 = *(const float4*)(Abase);
    sa1 = *(const float4*)(Abase + 4);
    sw0 = *(const float4*)(Wbase);

    float c[2][4][4];
#pragma unroll
    for (int mt = 0; mt < 2; mt++)
#pragma unroll
        for (int nt = 0; nt < 4; nt++)
#pragma unroll
            for (int i = 0; i < 4; i++) c[mt][nt][i] = 0.f;

    for (int it = 0; it < Cc/16; it++) {
        __syncthreads();
        {
            float4 h0 = tf32x4(sa0), h1 = tf32x4(sa1), hw = tf32x4(sw0);
            float4 l0 = tf32x4(sub4(sa0, h0)), l1 = tf32x4(sub4(sa1, h1)), lw = tf32x4(sub4(sw0, hw));
            *(float4*)&As_h[ar*GST + ak]     = h0;
            *(float4*)&As_h[ar*GST + ak + 4] = h1;
            *(float4*)&As_l[ar*GST + ak]     = l0;
            *(float4*)&As_l[ar*GST + ak + 4] = l1;
            *(float4*)&Ws_h[wr*GST + wk]     = hw;
            *(float4*)&Ws_l[wr*GST + wk]     = lw;
        }
        __syncthreads();
        if (it + 1 < Cc/16) {
            sa0 = *(const float4*)(Abase + (it+1)*16);
            sa1 = *(const float4*)(Abase + (it+1)*16 + 4);
            sw0 = *(const float4*)(Wbase + (it+1)*16);
        }
#pragma unroll
        for (int ks = 0; ks < 2; ks++) {
            uint32_t ah[2][4], al[2][4];
#pragma unroll
            for (int mt = 0; mt < 2; mt++) {
                int r0 = wm + mt*16 + g, r1 = r0 + 8;
                ah[mt][0] = __float_as_uint(As_h[r0*GST + ks*8 + q]);
                ah[mt][1] = __float_as_uint(As_h[r1*GST + ks*8 + q]);
                ah[mt][2] = __float_as_uint(As_h[r0*GST + ks*8 + q + 4]);
                ah[mt][3] = __float_as_uint(As_h[r1*GST + ks*8 + q + 4]);
                al[mt][0] = __float_as_uint(As_l[r0*GST + ks*8 + q]);
                al[mt][1] = __float_as_uint(As_l[r1*GST + ks*8 + q]);
                al[mt][2] = __float_as_uint(As_l[r0*GST + ks*8 + q + 4]);
                al[mt][3] = __float_as_uint(As_l[r1*GST + ks*8 + q + 4]);
            }
#pragma unroll
            for (int nt = 0; nt < 4; nt++) {
                int nr = wn + nt*8 + g;
                uint32_t bh0 = __float_as_uint(Ws_h[nr*GST + ks*8 + q]);
                uint32_t bh1 = __float_as_uint(Ws_h[nr*GST + ks*8 + q + 4]);
                uint32_t bl0 = __float_as_uint(Ws_l[nr*GST + ks*8 + q]);
                uint32_t bl1 = __float_as_uint(Ws_l[nr*GST + ks*8 + q + 4]);
                mma_tf32(c[0][nt], ah[0], bh0, bh1);
                mma_tf32(c[1][nt], ah[1], bh0, bh1);
                mma_tf32(c[0][nt], al[0], bh0, bh1);
                mma_tf32(c[1][nt], al[1], bh0, bh1);
                mma_tf32(c[0][nt], ah[0], bl0, bl1);
                mma_tf32(c[1][nt], ah[1], bl0, bl1);
            }
        }
    }

    // epilogue
#pragma unroll
    for (int mt = 0; mt < 2; mt++) {
#pragma unroll
        for (int nt = 0; nt < 4; nt++) {
            int n = n0 + wn + nt*8 + q*2;
            float b0 = bias[n], b1 = bias[n+1];
#pragma unroll
            for (int half = 0; half < 2; half++) {
                int m = m0 + wm + mt*16 + g + half*8;
                float v0 = c[mt][nt][half*2]   + b0;
                float v1 = c[mt][nt][half*2+1] + b1;
                if constexpr (IS_QKV) {
                    int bb = m >> 11;
                    int nnr = m & (Nn - 1);
                    int which = n >> 8;
                    int h = (n >> 6) & (Hh - 1);
                    int d = n & (Dd - 1);
                    float* dst = (which == 0) ? g_Q : ((which == 1) ? g_K : g_V);
                    *(float2*)&dst[((size_t)(bb*Hh + h) * Nn + nnr) * Dd + d] = make_float2(v0, v1);
                } else {
                    *(float2*)&Out[(size_t)m * Cc + n] = make_float2(v0, v1);
                }
            }
        }
    }
}

// ---------------------------------------------------------------------------
// Flash attention via mma.sync tf32 (unchanged from R7, passing @ 3.4e-4)
// ---------------------------------------------------------------------------
#define SK 72
#define SPP 132
#define KS_OFF 0
#define VS_OFF (128*SK)
#define PS_OFF (2*128*SK)
#define PJ_OFF (PS_OFF + 128*SPP)
#define FL_FLOATS (PJ_OFF + 128*4)
#define FL_SMEM (FL_FLOATS * 4)

__global__ __launch_bounds__(256, 1)
void flash_mma_kernel(const float* __restrict__ Pg) {
    extern __shared__ __align__(16) float sm[];
    float* Ks  = sm + KS_OFF;
    float* Vs  = sm + VS_OFF;
    float* Ps  = sm + PS_OFF;
    float* pj4 = sm + PJ_OFF;

    int tid = threadIdx.x;
    int w = tid >> 5, t = tid & 31;
    int g = t >> 2, q = t & 3;
    int b = blockIdx.z, h = blockIdx.y;
    int i0 = blockIdx.x * 128;

    const float* Qg = g_Q + (size_t)(b*Hh + h) * Nn * Dd;
    const float* Kg = g_K + (size_t)(b*Hh + h) * Nn * Dd;
    const float* Vg = g_V + (size_t)(b*Hh + h) * Nn * Dd;

    {
        int row = tid >> 1, dh = (tid & 1) * 32;
        const float* src = Qg + (size_t)(i0 + row) * Dd + dh;
#pragma unroll
        for (int i = 0; i < 8; i++) {
            float4 v = *(const float4*)(src + i*4);
            *(float4*)&Ps[row*SPP + dh + i*4] = tf32x4(v);
        }
    }
    __syncthreads();

    int r0 = w*16 + g, r1 = r0 + 8;
    uint32_t aQ[8][4];
#pragma unroll
    for (int kk = 0; kk < 8; kk++) {
        aQ[kk][0] = __float_as_uint(Ps[r0*SPP + kk*8 + q]);
        aQ[kk][1] = __float_as_uint(Ps[r1*SPP + kk*8 + q]);
        aQ[kk][2] = __float_as_uint(Ps[r0*SPP + kk*8 + q + 4]);
        aQ[kk][3] = __float_as_uint(Ps[r1*SPP + kk*8 + q + 4]);
    }
    float4 rpl0 = *(const float4*)&g_RP[((size_t)b*Nn + i0 + r0) * 4];
    float4 rpl1 = *(const float4*)&g_RP[((size_t)b*Nn + i0 + r1) * 4];

    float o[8][4];
#pragma unroll
    for (int n = 0; n < 8; n++)
#pragma unroll
        for (int c = 0; c < 4; c++) o[n][c] = 0.f;
    float lsum0 = 0.f, lsum1 = 0.f;

    for (int tt = 0; tt < Nn / 128; tt++) {
        int j0 = tt * 128;
        {
            int row = tid >> 1, dh = (tid & 1) * 32;
            const float* ksrc = Kg + (size_t)(j0 + row) * Dd + dh;
            const float* vsrc = Vg + (size_t)(j0 + row) * Dd + dh;
#pragma unroll
            for (int i = 0; i < 8; i++) {
                float4 kv = *(const float4*)(ksrc + i*4);
                *(float4*)&Ks[row*SK + dh + i*4] = tf32x4(kv);
                float4 vv = *(const float4*)(vsrc + i*4);
                *(float4*)&Vs[row*SK + dh + i*4] = tf32x4(vv);
            }
        }
        if (tid < 128) {
            const float* pp = Pg + (size_t)(j0 + tid) * 3;
            *(float4*)&pj4[tid*4] = make_float4(pp[0], pp[1], pp[2], 0.f);
        }
        __syncthreads();

#pragma unroll
        for (int ni = 0; ni < 16; ni++) {
            float c[4] = {0.f, 0.f, 0.f, 0.f};
            int jb = ni*8 + g;
#pragma unroll
            for (int kk = 0; kk < 8; kk++) {
                uint32_t b0 = __float_as_uint(Ks[jb*SK + kk*8 + q]);
                uint32_t b1 = __float_as_uint(Ks[jb*SK + kk*8 + q + 4]);
                mma_tf32(c, aQ[kk], b0, b1);
            }
            int clo = ni*8 + q*2;
            float4 plo = *(const float4*)&pj4[clo*4];
            float4 phi = *(const float4*)&pj4[(clo+1)*4];
            float dl0 = rpl0.x*plo.x + rpl0.y*plo.y + rpl0.z*plo.z;
            float dh0 = rpl0.x*phi.x + rpl0.y*phi.y + rpl0.z*phi.z;
            float dl1 = rpl1.x*plo.x + rpl1.y*plo.y + rpl1.z*plo.z;
            float dh1 = rpl1.x*phi.x + rpl1.y*phi.y + rpl1.z*phi.z;
            float e00 = ex2f(fmaf(c[0], K1EXP, dl0));
            float e01 = ex2f(fmaf(c[1], K1EXP, dh0));
            float e10 = ex2f(fmaf(c[2], K1EXP, dl1));
            float e11 = ex2f(fmaf(c[3], K1EXP, dh1));
            lsum0 += e00 + e01;
            lsum1 += e10 + e11;
            *(float2*)&Ps[r0*SPP + clo] = make_float2(tf32f(e00), tf32f(e01));
            *(float2*)&Ps[r1*SPP + clo] = make_float2(tf32f(e10), tf32f(e11));
        }
        __syncthreads();

#pragma unroll
        for (int kk = 0; kk < 16; kk++) {
            uint32_t aP[4];
            aP[0] = __float_as_uint(Ps[r0*SPP + kk*8 + q]);
            aP[1] = __float_as_uint(Ps[r1*SPP + kk*8 + q]);
            aP[2] = __float_as_uint(Ps[r0*SPP + kk*8 + q + 4]);
            aP[3] = __float_as_uint(Ps[r1*SPP + kk*8 + q + 4]);
#pragma unroll
            for (int n = 0; n < 8; n++) {
                uint32_t b0 = __float_as_uint(Vs[(kk*8 + q)*SK + n*8 + g]);
                uint32_t b1 = __float_as_uint(Vs[(kk*8 + q + 4)*SK + n*8 + g]);
                mma_tf32(o[n], aP, b0, b1);
            }
        }
        __syncthreads();
    }

    lsum0 += __shfl_xor_sync(0xffffffffu, lsum0, 1);
    lsum0 += __shfl_xor_sync(0xffffffffu, lsum0, 2);
    lsum1 += __shfl_xor_sync(0xffffffffu, lsum1, 1);
    lsum1 += __shfl_xor_sync(0xffffffffu, lsum1, 2);
    float inv0 = 1.f / lsum0, inv1 = 1.f / lsum1;

    float* dst0 = g_AO + ((size_t)b*Nn + i0 + r0) * Cc + h*Dd;
    float* dst1 = g_AO + ((size_t)b*Nn + i0 + r1) * Cc + h*Dd;
#pragma unroll
    for (int n = 0; n < 8; n++) {
        int col = n*8 + q*2;
        *(float2*)(dst0 + col) = make_float2(o[n][0]*inv0, o[n][1]*inv0);
        *(float2*)(dst1 + col) = make_float2(o[n][2]*inv1, o[n][3]*inv1);
    }
}

// ---------------------------------------------------------------------------
extern "C" void kernel_launch(void* const* d_in, const int* in_sizes, int n_in,
                              void* d_out, int out_size) {
    const float* x         = (const float*)d_in[0];
    const float* R         = (const float*)d_in[1];
    const float* P         = (const float*)d_in[2];
    const float* qkv_w     = (const float*)d_in[3];
    const float* qkv_b     = (const float*)d_in[4];
    const float* proj_w    = (const float*)d_in[5];
    const float* proj_b    = (const float*)d_in[6];
    const float* pos_scale = (const float*)d_in[7];
    float* out = (float*)d_out;

    cudaFuncSetAttribute(flash_mma_kernel, cudaFuncAttributeMaxDynamicSharedMemorySize, FL_SMEM);

    rp_kernel<<<(Bb*Nn + 255) / 256, 256>>>(R, P, pos_scale);
    // QKV: M=8192, N=768, K=256 -> grid (12, 64)
    gemm_mma_kernel<true><<<dim3(768/64, (Bb*Nn)/128), 256>>>(x, qkv_w, qkv_b, nullptr);
    flash_mma_kernel<<<dim3(Nn/128, Hh, Bb), 256, FL_SMEM>>>(P);
    // Proj: M=8192, N=256, K=256 -> grid (4, 64)
    gemm_mma_kernel<false><<<dim3(Cc/64, (Bb*Nn)/128), 256>>>(nullptr, proj_w, proj_b, out);
}

// round 9
// speedup vs baseline: 1.9082x; 1.0649x over previous
#include <cuda_runtime.h>
#include <cstdint>
#include <math.h>

#define Bb 4
#define Nn 2048
#define Cc 256
#define Hh 4
#define Dd 64
#define K1EXP 0.18033688011112042f   // 0.125 * log2(e)
#define LOG2E 1.4426950408889634f

// ===================== tf32 / mma helpers =====================
__device__ __forceinline__ uint32_t tf32u(float x) {
    uint32_t u; asm("cvt.rna.tf32.f32 %0,%1;" : "=r"(u) : "f"(x)); return u;
}
__device__ __forceinline__ float tf32f(float x) { return __uint_as_float(tf32u(x)); }
__device__ __forceinline__ float ex2f(float x) {
    float y; asm("ex2.approx.f32 %0,%1;" : "=f"(y) : "f"(x)); return y;
}
__device__ __forceinline__ void mma_tf32(float c[4], const uint32_t a[4],
                                         uint32_t b0, uint32_t b1) {
    asm volatile("mma.sync.aligned.m16n8k8.row.col.f32.tf32.tf32.f32 "
        "{%0,%1,%2,%3}, {%4,%5,%6,%7}, {%8,%9}, {%0,%1,%2,%3};"
        : "+f"(c[0]), "+f"(c[1]), "+f"(c[2]), "+f"(c[3])
        : "r"(a[0]), "r"(a[1]), "r"(a[2]), "r"(a[3]), "r"(b0), "r"(b1));
}
__device__ __forceinline__ float4 tf32x4(float4 v) {
    return make_float4(tf32f(v.x), tf32f(v.y), tf32f(v.z), tf32f(v.w));
}
__device__ __forceinline__ float4 sub4(float4 a, float4 b) {
    return make_float4(a.x-b.x, a.y-b.y, a.z-b.z, a.w-b.w);
}

// ===================== scratch =====================
__device__ __align__(16) float g_Q[Bb*Hh*Nn*Dd];
__device__ __align__(16) float g_K[Bb*Hh*Nn*Dd];
__device__ __align__(16) float g_V[Bb*Hh*Nn*Dd];
__device__ __align__(16) float g_RP[Bb*Nn*4];    // rp * pos_scale * log2(e)
__device__ __align__(16) float g_AO[Bb*Nn*Cc];

// ---------------------------------------------------------------------------
__global__ void rp_kernel(const float* __restrict__ R, const float* __restrict__ P,
                          const float* __restrict__ pos_scale) {
    int idx = blockIdx.x * blockDim.x + threadIdx.x;
    if (idx >= Bb * Nn) return;
    int b = idx / Nn, j = idx % Nn;
    float p0 = P[j*3+0], p1 = P[j*3+1], p2 = P[j*3+2];
    float ps = *pos_scale * LOG2E;
    const float* Rb = R + b*9;
#pragma unroll
    for (int c = 0; c < 3; c++)
        g_RP[idx*4 + c] = ps * (Rb[c*3+0]*p0 + Rb[c*3+1]*p1 + Rb[c*3+2]*p2);
    g_RP[idx*4 + 3] = 0.f;
}

// ---------------------------------------------------------------------------
// Tensor-core NT GEMM (unchanged from R8, passing): 3-pass tf32 hi/lo split.
// ---------------------------------------------------------------------------
#define GST 20

template<bool IS_QKV>
__global__ __launch_bounds__(256)
void gemm_mma_kernel(const float* __restrict__ A, const float* __restrict__ W,
                     const float* __restrict__ bias, float* __restrict__ Out) {
    __shared__ __align__(16) float As_h[128*GST];
    __shared__ __align__(16) float As_l[128*GST];
    __shared__ __align__(16) float Ws_h[64*GST];
    __shared__ __align__(16) float Ws_l[64*GST];

    const float* Ap;
    if constexpr (IS_QKV) Ap = A; else Ap = g_AO;

    int tid = threadIdx.x;
    int w = tid >> 5, lane = tid & 31, g = lane >> 2, q = lane & 3;
    int wm = (w & 3) * 32, wn = (w >> 2) * 32;
    int m0 = blockIdx.y * 128, n0 = blockIdx.x * 64;

    int ar = tid >> 1, ak = (tid & 1) * 8;
    int wr = tid >> 2, wk = (tid & 3) * 4;

    float4 sa0, sa1, sw0;
    const float* Abase = Ap + (size_t)(m0 + ar) * Cc + ak;
    const float* Wbase = W  + (size_t)(n0 + wr) * Cc + wk;

    sa0 = *(const float4*)(Abase);
    sa1 = *(const float4*)(Abase + 4);
    sw0 = *(const float4*)(Wbase);

    float c[2][4][4];
#pragma unroll
    for (int mt = 0; mt < 2; mt++)
#pragma unroll
        for (int nt = 0; nt < 4; nt++)
#pragma unroll
            for (int i = 0; i < 4; i++) c[mt][nt][i] = 0.f;

    for (int it = 0; it < Cc/16; it++) {
        __syncthreads();
        {
            float4 h0 = tf32x4(sa0), h1 = tf32x4(sa1), hw = tf32x4(sw0);
            float4 l0 = tf32x4(sub4(sa0, h0)), l1 = tf32x4(sub4(sa1, h1)), lw = tf32x4(sub4(sw0, hw));
            *(float4*)&As_h[ar*GST + ak]     = h0;
            *(float4*)&As_h[ar*GST + ak + 4] = h1;
            *(float4*)&As_l[ar*GST + ak]     = l0;
            *(float4*)&As_l[ar*GST + ak + 4] = l1;
            *(float4*)&Ws_h[wr*GST + wk]     = hw;
            *(float4*)&Ws_l[wr*GST + wk]     = lw;
        }
        __syncthreads();
        if (it + 1 < Cc/16) {
            sa0 = *(const float4*)(Abase + (it+1)*16);
            sa1 = *(const float4*)(Abase + (it+1)*16 + 4);
            sw0 = *(const float4*)(Wbase + (it+1)*16);
        }
#pragma unroll
        for (int ks = 0; ks < 2; ks++) {
            uint32_t ah[2][4], al[2][4];
#pragma unroll
            for (int mt = 0; mt < 2; mt++) {
                int r0 = wm + mt*16 + g, r1 = r0 + 8;
                ah[mt][0] = __float_as_uint(As_h[r0*GST + ks*8 + q]);
                ah[mt][1] = __float_as_uint(As_h[r1*GST + ks*8 + q]);
                ah[mt][2] = __float_as_uint(As_h[r0*GST + ks*8 + q + 4]);
                ah[mt][3] = __float_as_uint(As_h[r1*GST + ks*8 + q + 4]);
                al[mt][0] = __float_as_uint(As_l[r0*GST + ks*8 + q]);
                al[mt][1] = __float_as_uint(As_l[r1*GST + ks*8 + q]);
                al[mt][2] = __float_as_uint(As_l[r0*GST + ks*8 + q + 4]);
                al[mt][3] = __float_as_uint(As_l[r1*GST + ks*8 + q + 4]);
            }
#pragma unroll
            for (int nt = 0; nt < 4; nt++) {
                int nr = wn + nt*8 + g;
                uint32_t bh0 = __float_as_uint(Ws_h[nr*GST + ks*8 + q]);
                uint32_t bh1 = __float_as_uint(Ws_h[nr*GST + ks*8 + q + 4]);
                uint32_t bl0 = __float_as_uint(Ws_l[nr*GST + ks*8 + q]);
                uint32_t bl1 = __float_as_uint(Ws_l[nr*GST + ks*8 + q + 4]);
                mma_tf32(c[0][nt], ah[0], bh0, bh1);
                mma_tf32(c[1][nt], ah[1], bh0, bh1);
                mma_tf32(c[0][nt], al[0], bh0, bh1);
                mma_tf32(c[1][nt], al[1], bh0, bh1);
                mma_tf32(c[0][nt], ah[0], bl0, bl1);
                mma_tf32(c[1][nt], ah[1], bl0, bl1);
            }
        }
    }

#pragma unroll
    for (int mt = 0; mt < 2; mt++) {
#pragma unroll
        for (int nt = 0; nt < 4; nt++) {
            int n = n0 + wn + nt*8 + q*2;
            float b0 = bias[n], b1 = bias[n+1];
#pragma unroll
            for (int half = 0; half < 2; half++) {
                int m = m0 + wm + mt*16 + g + half*8;
                float v0 = c[mt][nt][half*2]   + b0;
                float v1 = c[mt][nt][half*2+1] + b1;
                if constexpr (IS_QKV) {
                    int bb = m >> 11;
                    int nnr = m & (Nn - 1);
                    int which = n >> 8;
                    int h = (n >> 6) & (Hh - 1);
                    int d = n & (Dd - 1);
                    float* dst = (which == 0) ? g_Q : ((which == 1) ? g_K : g_V);
                    *(float2*)&dst[((size_t)(bb*Hh + h) * Nn + nnr) * Dd + d] = make_float2(v0, v1);
                } else {
                    *(float2*)&Out[(size_t)m * Cc + n] = make_float2(v0, v1);
                }
            }
        }
    }
}

// ---------------------------------------------------------------------------
// Flash attention via mma.sync tf32, fused per-tile pipeline:
// GEMM1 -> exp -> quad-shuffle P fragments -> GEMM2, no P smem.
// smem = K + V + pj = 75.8KB -> 2 CTAs/SM, full grid resident in one wave.
// ---------------------------------------------------------------------------
#define SK 72
#define KS_OFF 0
#define VS_OFF (128*SK)
#define PJ_OFF (2*128*SK)
#define FL_FLOATS (PJ_OFF + 128*4)
#define FL_SMEM (FL_FLOATS * 4)   // 75776 B

__global__ __launch_bounds__(256, 2)
void flash_mma_kernel(const float* __restrict__ Pg) {
    extern __shared__ __align__(16) float sm[];
    float* Ks  = sm + KS_OFF;
    float* Vs  = sm + VS_OFF;
    float* pj4 = sm + PJ_OFF;

    int tid = threadIdx.x;
    int w = tid >> 5, t = tid & 31;
    int g = t >> 2, q = t & 3;
    int b = blockIdx.z, h = blockIdx.y;
    int i0 = blockIdx.x * 128;

    const float* Qg = g_Q + (size_t)(b*Hh + h) * Nn * Dd;
    const float* Kg = g_K + (size_t)(b*Hh + h) * Nn * Dd;
    const float* Vg = g_V + (size_t)(b*Hh + h) * Nn * Dd;

    // ---- stage Q (tf32) into Ks region, pull fragments, release ----
    {
        int row = tid >> 1, dh = (tid & 1) * 32;
        const float* src = Qg + (size_t)(i0 + row) * Dd + dh;
#pragma unroll
        for (int i = 0; i < 8; i++) {
            float4 v = *(const float4*)(src + i*4);
            *(float4*)&Ks[row*SK + dh + i*4] = tf32x4(v);
        }
    }
    __syncthreads();

    int r0 = w*16 + g, r1 = r0 + 8;
    uint32_t aQ[8][4];
#pragma unroll
    for (int kk = 0; kk < 8; kk++) {
        aQ[kk][0] = __float_as_uint(Ks[r0*SK + kk*8 + q]);
        aQ[kk][1] = __float_as_uint(Ks[r1*SK + kk*8 + q]);
        aQ[kk][2] = __float_as_uint(Ks[r0*SK + kk*8 + q + 4]);
        aQ[kk][3] = __float_as_uint(Ks[r1*SK + kk*8 + q + 4]);
    }
    float4 rpl0 = *(const float4*)&g_RP[((size_t)b*Nn + i0 + r0) * 4];
    float4 rpl1 = *(const float4*)&g_RP[((size_t)b*Nn + i0 + r1) * 4];

    float o[8][4];
#pragma unroll
    for (int n = 0; n < 8; n++)
#pragma unroll
        for (int c = 0; c < 4; c++) o[n][c] = 0.f;
    float lsum0 = 0.f, lsum1 = 0.f;

    int s0 = q >> 1, s1 = s0 + 2;
    bool odd = (q & 1);

    for (int tt = 0; tt < Nn / 128; tt++) {
        int j0 = tt * 128;
        __syncthreads();   // WAR: prior tile reads (and Q frag reads) complete
        {
            int row = tid >> 1, dh = (tid & 1) * 32;
            const float* ksrc = Kg + (size_t)(j0 + row) * Dd + dh;
            const float* vsrc = Vg + (size_t)(j0 + row) * Dd + dh;
#pragma unroll
            for (int i = 0; i < 8; i++) {
                float4 kv = *(const float4*)(ksrc + i*4);
                *(float4*)&Ks[row*SK + dh + i*4] = tf32x4(kv);
                float4 vv = *(const float4*)(vsrc + i*4);
                *(float4*)&Vs[row*SK + dh + i*4] = tf32x4(vv);
            }
        }
        if (tid < 128) {
            const float* pp = Pg + (size_t)(j0 + tid) * 3;
            *(float4*)&pj4[tid*4] = make_float4(pp[0], pp[1], pp[2], 0.f);
        }
        __syncthreads();

        // ---- fused: per 16x8 S tile -> exp -> shuffle P frags -> PV mma ----
#pragma unroll
        for (int ni = 0; ni < 16; ni++) {
            float c[4] = {0.f, 0.f, 0.f, 0.f};
            int jb = ni*8 + g;
#pragma unroll
            for (int kk = 0; kk < 8; kk++) {
                uint32_t b0 = __float_as_uint(Ks[jb*SK + kk*8 + q]);
                uint32_t b1 = __float_as_uint(Ks[jb*SK + kk*8 + q + 4]);
                mma_tf32(c, aQ[kk], b0, b1);
            }
            int clo = ni*8 + q*2;
            float4 plo = *(const float4*)&pj4[clo*4];
            float4 phi = *(const float4*)&pj4[(clo+1)*4];
            float dl0 = rpl0.x*plo.x + rpl0.y*plo.y + rpl0.z*plo.z;
            float dh0 = rpl0.x*phi.x + rpl0.y*phi.y + rpl0.z*phi.z;
            float dl1 = rpl1.x*plo.x + rpl1.y*plo.y + rpl1.z*plo.z;
            float dh1 = rpl1.x*phi.x + rpl1.y*phi.y + rpl1.z*phi.z;
            float e00 = ex2f(fmaf(c[0], K1EXP, dl0));
            float e01 = ex2f(fmaf(c[1], K1EXP, dh0));
            float e10 = ex2f(fmaf(c[2], K1EXP, dl1));
            float e11 = ex2f(fmaf(c[3], K1EXP, dh1));
            lsum0 += e00 + e01;
            lsum1 += e10 + e11;

            // P fragments via quad shuffles (P[r][ni*8+q], [ni*8+q+4])
            float t00a = __shfl_sync(0xffffffffu, e00, s0, 4);
            float t01a = __shfl_sync(0xffffffffu, e01, s0, 4);
            float t10a = __shfl_sync(0xffffffffu, e10, s0, 4);
            float t11a = __shfl_sync(0xffffffffu, e11, s0, 4);
            float t00b = __shfl_sync(0xffffffffu, e00, s1, 4);
            float t01b = __shfl_sync(0xffffffffu, e01, s1, 4);
            float t10b = __shfl_sync(0xffffffffu, e10, s1, 4);
            float t11b = __shfl_sync(0xffffffffu, e11, s1, 4);
            uint32_t aP[4];
            aP[0] = tf32u(odd ? t01a : t00a);
            aP[1] = tf32u(odd ? t11a : t10a);
            aP[2] = tf32u(odd ? t01b : t00b);
            aP[3] = tf32u(odd ? t11b : t10b);

#pragma unroll
            for (int n = 0; n < 8; n++) {
                uint32_t b0 = __float_as_uint(Vs[(ni*8 + q)*SK + n*8 + g]);
                uint32_t b1 = __float_as_uint(Vs[(ni*8 + q + 4)*SK + n*8 + g]);
                mma_tf32(o[n], aP, b0, b1);
            }
        }
    }

    lsum0 += __shfl_xor_sync(0xffffffffu, lsum0, 1);
    lsum0 += __shfl_xor_sync(0xffffffffu, lsum0, 2);
    lsum1 += __shfl_xor_sync(0xffffffffu, lsum1, 1);
    lsum1 += __shfl_xor_sync(0xffffffffu, lsum1, 2);
    float inv0 = 1.f / lsum0, inv1 = 1.f / lsum1;

    float* dst0 = g_AO + ((size_t)b*Nn + i0 + r0) * Cc + h*Dd;
    float* dst1 = g_AO + ((size_t)b*Nn + i0 + r1) * Cc + h*Dd;
#pragma unroll
    for (int n = 0; n < 8; n++) {
        int col = n*8 + q*2;
        *(float2*)(dst0 + col) = make_float2(o[n][0]*inv0, o[n][1]*inv0);
        *(float2*)(dst1 + col) = make_float2(o[n][2]*inv1, o[n][3]*inv1);
    }
}

// ---------------------------------------------------------------------------
extern "C" void kernel_launch(void* const* d_in, const int* in_sizes, int n_in,
                              void* d_out, int out_size) {
    const float* x         = (const float*)d_in[0];
    const float* R         = (const float*)d_in[1];
    const float* P         = (const float*)d_in[2];
    const float* qkv_w     = (const float*)d_in[3];
    const float* qkv_b     = (const float*)d_in[4];
    const float* proj_w    = (const float*)d_in[5];
    const float* proj_b    = (const float*)d_in[6];
    const float* pos_scale = (const float*)d_in[7];
    float* out = (float*)d_out;

    cudaFuncSetAttribute(flash_mma_kernel, cudaFuncAttributeMaxDynamicSharedMemorySize, FL_SMEM);

    rp_kernel<<<(Bb*Nn + 255) / 256, 256>>>(R, P, pos_scale);
    gemm_mma_kernel<true><<<dim3(768/64, (Bb*Nn)/128), 256>>>(x, qkv_w, qkv_b, nullptr);
    flash_mma_kernel<<<dim3(Nn/128, Hh, Bb), 256, FL_SMEM>>>(P);
    gemm_mma_kernel<false><<<dim3(Cc/64, (Bb*Nn)/128), 256>>>(nullptr, proj_w, proj_b, out);
}

// round 10
// speedup vs baseline: 1.9839x; 1.0396x over previous
#include <cuda_runtime.h>
#include <cstdint>
#include <math.h>

#define Bb 4
#define Nn 2048
#define Cc 256
#define Hh 4
#define Dd 64
#define K1EXP 0.18033688011112042f   // 0.125 * log2(e)
#define LOG2E 1.4426950408889634f

// ===================== tf32 / mma helpers =====================
__device__ __forceinline__ uint32_t tf32u(float x) {
    uint32_t u; asm("cvt.rna.tf32.f32 %0,%1;" : "=r"(u) : "f"(x)); return u;
}
__device__ __forceinline__ float tf32f(float x) { return __uint_as_float(tf32u(x)); }
__device__ __forceinline__ float ex2f(float x) {
    float y; asm("ex2.approx.f32 %0,%1;" : "=f"(y) : "f"(x)); return y;
}
__device__ __forceinline__ void mma_tf32(float c[4], const uint32_t a[4],
                                         uint32_t b0, uint32_t b1) {
    asm volatile("mma.sync.aligned.m16n8k8.row.col.f32.tf32.tf32.f32 "
        "{%0,%1,%2,%3}, {%4,%5,%6,%7}, {%8,%9}, {%0,%1,%2,%3};"
        : "+f"(c[0]), "+f"(c[1]), "+f"(c[2]), "+f"(c[3])
        : "r"(a[0]), "r"(a[1]), "r"(a[2]), "r"(a[3]), "r"(b0), "r"(b1));
}
__device__ __forceinline__ float4 tf32x4(float4 v) {
    return make_float4(tf32f(v.x), tf32f(v.y), tf32f(v.z), tf32f(v.w));
}
__device__ __forceinline__ float4 sub4(float4 a, float4 b) {
    return make_float4(a.x-b.x, a.y-b.y, a.z-b.z, a.w-b.w);
}

// ===================== scratch =====================
__device__ __align__(16) float g_Q[Bb*Hh*Nn*Dd];
__device__ __align__(16) float g_K[Bb*Hh*Nn*Dd];
__device__ __align__(16) float g_V[Bb*Hh*Nn*Dd];
__device__ __align__(16) float g_RP[Bb*Nn*4];    // rp * pos_scale * log2(e)
__device__ __align__(16) float g_AO[Bb*Nn*Cc];

// ---------------------------------------------------------------------------
__global__ void rp_kernel(const float* __restrict__ R, const float* __restrict__ P,
                          const float* __restrict__ pos_scale) {
    int idx = blockIdx.x * blockDim.x + threadIdx.x;
    if (idx >= Bb * Nn) return;
    int b = idx / Nn, j = idx % Nn;
    float p0 = P[j*3+0], p1 = P[j*3+1], p2 = P[j*3+2];
    float ps = *pos_scale * LOG2E;
    const float* Rb = R + b*9;
#pragma unroll
    for (int c = 0; c < 3; c++)
        g_RP[idx*4 + c] = ps * (Rb[c*3+0]*p0 + Rb[c*3+1]*p1 + Rb[c*3+2]*p2);
    g_RP[idx*4 + 3] = 0.f;
}

// ---------------------------------------------------------------------------
// Tensor-core NT GEMM, 2-pass split: A = tf32(A) single, W = Wh + Wl.
// CTA 128m x 64n, 8 warps (4x2), warp 32x32, K-tile 16.
// ---------------------------------------------------------------------------
#define GST 20

template<bool IS_QKV>
__global__ __launch_bounds__(256)
void gemm_mma_kernel(const float* __restrict__ A, const float* __restrict__ W,
                     const float* __restrict__ bias, float* __restrict__ Out) {
    __shared__ __align__(16) float As[128*GST];
    __shared__ __align__(16) float Ws_h[64*GST];
    __shared__ __align__(16) float Ws_l[64*GST];

    const float* Ap;
    if constexpr (IS_QKV) Ap = A; else Ap = g_AO;

    int tid = threadIdx.x;
    int w = tid >> 5, lane = tid & 31, g = lane >> 2, q = lane & 3;
    int wm = (w & 3) * 32, wn = (w >> 2) * 32;
    int m0 = blockIdx.y * 128, n0 = blockIdx.x * 64;

    int ar = tid >> 1, ak = (tid & 1) * 8;
    int wr = tid >> 2, wk = (tid & 3) * 4;

    float4 sa0, sa1, sw0;
    const float* Abase = Ap + (size_t)(m0 + ar) * Cc + ak;
    const float* Wbase = W  + (size_t)(n0 + wr) * Cc + wk;

    sa0 = *(const float4*)(Abase);
    sa1 = *(const float4*)(Abase + 4);
    sw0 = *(const float4*)(Wbase);

    float c[2][4][4];
#pragma unroll
    for (int mt = 0; mt < 2; mt++)
#pragma unroll
        for (int nt = 0; nt < 4; nt++)
#pragma unroll
            for (int i = 0; i < 4; i++) c[mt][nt][i] = 0.f;

    for (int it = 0; it < Cc/16; it++) {
        __syncthreads();
        {
            float4 hw = tf32x4(sw0);
            float4 lw = tf32x4(sub4(sw0, hw));
            *(float4*)&As[ar*GST + ak]     = tf32x4(sa0);
            *(float4*)&As[ar*GST + ak + 4] = tf32x4(sa1);
            *(float4*)&Ws_h[wr*GST + wk]   = hw;
            *(float4*)&Ws_l[wr*GST + wk]   = lw;
        }
        __syncthreads();
        if (it + 1 < Cc/16) {
            sa0 = *(const float4*)(Abase + (it+1)*16);
            sa1 = *(const float4*)(Abase + (it+1)*16 + 4);
            sw0 = *(const float4*)(Wbase + (it+1)*16);
        }
#pragma unroll
        for (int ks = 0; ks < 2; ks++) {
            uint32_t ah[2][4];
#pragma unroll
            for (int mt = 0; mt < 2; mt++) {
                int r0 = wm + mt*16 + g, r1 = r0 + 8;
                ah[mt][0] = __float_as_uint(As[r0*GST + ks*8 + q]);
                ah[mt][1] = __float_as_uint(As[r1*GST + ks*8 + q]);
                ah[mt][2] = __float_as_uint(As[r0*GST + ks*8 + q + 4]);
                ah[mt][3] = __float_as_uint(As[r1*GST + ks*8 + q + 4]);
            }
#pragma unroll
            for (int nt = 0; nt < 4; nt++) {
                int nr = wn + nt*8 + g;
                uint32_t bh0 = __float_as_uint(Ws_h[nr*GST + ks*8 + q]);
                uint32_t bh1 = __float_as_uint(Ws_h[nr*GST + ks*8 + q + 4]);
                uint32_t bl0 = __float_as_uint(Ws_l[nr*GST + ks*8 + q]);
                uint32_t bl1 = __float_as_uint(Ws_l[nr*GST + ks*8 + q + 4]);
                mma_tf32(c[0][nt], ah[0], bh0, bh1);
                mma_tf32(c[1][nt], ah[1], bh0, bh1);
                mma_tf32(c[0][nt], ah[0], bl0, bl1);
                mma_tf32(c[1][nt], ah[1], bl0, bl1);
            }
        }
    }

#pragma unroll
    for (int mt = 0; mt < 2; mt++) {
#pragma unroll
        for (int nt = 0; nt < 4; nt++) {
            int n = n0 + wn + nt*8 + q*2;
            float b0 = bias[n], b1 = bias[n+1];
#pragma unroll
            for (int half = 0; half < 2; half++) {
                int m = m0 + wm + mt*16 + g + half*8;
                float v0 = c[mt][nt][half*2]   + b0;
                float v1 = c[mt][nt][half*2+1] + b1;
                if constexpr (IS_QKV) {
                    int bb = m >> 11;
                    int nnr = m & (Nn - 1);
                    int which = n >> 8;
                    int h = (n >> 6) & (Hh - 1);
                    int d = n & (Dd - 1);
                    float* dst = (which == 0) ? g_Q : ((which == 1) ? g_K : g_V);
                    *(float2*)&dst[((size_t)(bb*Hh + h) * Nn + nnr) * Dd + d] = make_float2(v0, v1);
                } else {
                    *(float2*)&Out[(size_t)m * Cc + n] = make_float2(v0, v1);
                }
            }
        }
    }
}

// ---------------------------------------------------------------------------
// Flash attention via mma.sync tf32, fused pipeline, fragment-major smem.
// Layout: X[row*SK + (k&7)*8 + (k>>3)] so B/A fragment runs are contiguous.
// ---------------------------------------------------------------------------
#define SK 68
#define KS_OFF 0
#define VS_OFF (128*SK)
#define PJ_OFF (2*128*SK)
#define FL_FLOATS (PJ_OFF + 128*4)
#define FL_SMEM (FL_FLOATS * 4)   // 71680 B -> 2 CTAs/SM

__device__ __forceinline__ void stage_perm(float* dst, const float* src, int row, int dh) {
    // store 32 consecutive k (starting at dh) of one row into permuted layout
#pragma unroll
    for (int i = 0; i < 8; i++) {
        int k0 = dh + i*4;
        float4 v = *(const float4*)(src + i*4);
        int base = row*SK + (k0 & 7)*8 + (k0 >> 3);
        dst[base]      = tf32f(v.x);   // k0:   (k&7)=c, (k>>3)=r
        dst[base + 8]  = tf32f(v.y);   // k0+1: col+1 -> +8
        dst[base + 16] = tf32f(v.z);
        dst[base + 24] = tf32f(v.w);
    }
}

__global__ __launch_bounds__(256, 2)
void flash_mma_kernel(const float* __restrict__ Pg) {
    extern __shared__ __align__(16) float sm[];
    float* Ks  = sm + KS_OFF;
    float* Vs  = sm + VS_OFF;
    float* pj4 = sm + PJ_OFF;

    int tid = threadIdx.x;
    int w = tid >> 5, t = tid & 31;
    int g = t >> 2, q = t & 3;
    int b = blockIdx.z, h = blockIdx.y;
    int i0 = blockIdx.x * 128;

    const float* Qg = g_Q + (size_t)(b*Hh + h) * Nn * Dd;
    const float* Kg = g_K + (size_t)(b*Hh + h) * Nn * Dd;
    const float* Vg = g_V + (size_t)(b*Hh + h) * Nn * Dd;

    // ---- stage Q (permuted, tf32) into Ks region, pull fragments ----
    {
        int row = tid >> 1, dh = (tid & 1) * 32;
        stage_perm(Ks, Qg + (size_t)(i0 + row) * Dd + dh, row, dh);
    }
    __syncthreads();

    int r0 = w*16 + g, r1 = r0 + 8;
    uint32_t aQ[8][4];
    {
        float4 x0 = *(const float4*)&Ks[r0*SK + q*8];
        float4 x1 = *(const float4*)&Ks[r0*SK + q*8 + 4];
        float4 y0 = *(const float4*)&Ks[r1*SK + q*8];
        float4 y1 = *(const float4*)&Ks[r1*SK + q*8 + 4];
        float4 z0 = *(const float4*)&Ks[r0*SK + (q+4)*8];
        float4 z1 = *(const float4*)&Ks[r0*SK + (q+4)*8 + 4];
        float4 w0 = *(const float4*)&Ks[r1*SK + (q+4)*8];
        float4 w1 = *(const float4*)&Ks[r1*SK + (q+4)*8 + 4];
        const float* xs[8] = {&x0.x,&x0.y,&x0.z,&x0.w,&x1.x,&x1.y,&x1.z,&x1.w};
        const float* ys[8] = {&y0.x,&y0.y,&y0.z,&y0.w,&y1.x,&y1.y,&y1.z,&y1.w};
        const float* zs[8] = {&z0.x,&z0.y,&z0.z,&z0.w,&z1.x,&z1.y,&z1.z,&z1.w};
        const float* ws[8] = {&w0.x,&w0.y,&w0.z,&w0.w,&w1.x,&w1.y,&w1.z,&w1.w};
#pragma unroll
        for (int kk = 0; kk < 8; kk++) {
            aQ[kk][0] = __float_as_uint(*xs[kk]);
            aQ[kk][1] = __float_as_uint(*ys[kk]);
            aQ[kk][2] = __float_as_uint(*zs[kk]);
            aQ[kk][3] = __float_as_uint(*ws[kk]);
        }
    }
    float4 rpl0 = *(const float4*)&g_RP[((size_t)b*Nn + i0 + r0) * 4];
    float4 rpl1 = *(const float4*)&g_RP[((size_t)b*Nn + i0 + r1) * 4];

    float o[8][4];
#pragma unroll
    for (int n = 0; n < 8; n++)
#pragma unroll
        for (int c = 0; c < 4; c++) o[n][c] = 0.f;
    float lsum0 = 0.f, lsum1 = 0.f;

    int s0 = q >> 1, s1 = s0 + 2;
    bool odd = (q & 1);

    for (int tt = 0; tt < Nn / 128; tt++) {
        int j0 = tt * 128;
        __syncthreads();   // WAR on prior tile
        {
            int row = tid >> 1, dh = (tid & 1) * 32;
            stage_perm(Ks, Kg + (size_t)(j0 + row) * Dd + dh, row, dh);
            stage_perm(Vs, Vg + (size_t)(j0 + row) * Dd + dh, row, dh);
        }
        if (tid < 128) {
            const float* pp = Pg + (size_t)(j0 + tid) * 3;
            *(float4*)&pj4[tid*4] = make_float4(pp[0], pp[1], pp[2], 0.f);
        }
        __syncthreads();

#pragma unroll
        for (int ni = 0; ni < 16; ni++) {
            int jb = ni*8 + g;
            // K fragments: contiguous vector loads
            float4 kb0 = *(const float4*)&Ks[jb*SK + q*8];
            float4 kb1 = *(const float4*)&Ks[jb*SK + q*8 + 4];
            float4 kc0 = *(const float4*)&Ks[jb*SK + (q+4)*8];
            float4 kc1 = *(const float4*)&Ks[jb*SK + (q+4)*8 + 4];
            float cA[4] = {0.f,0.f,0.f,0.f}, cB[4] = {0.f,0.f,0.f,0.f};
            mma_tf32(cA, aQ[0], __float_as_uint(kb0.x), __float_as_uint(kc0.x));
            mma_tf32(cB, aQ[1], __float_as_uint(kb0.y), __float_as_uint(kc0.y));
            mma_tf32(cA, aQ[2], __float_as_uint(kb0.z), __float_as_uint(kc0.z));
            mma_tf32(cB, aQ[3], __float_as_uint(kb0.w), __float_as_uint(kc0.w));
            mma_tf32(cA, aQ[4], __float_as_uint(kb1.x), __float_as_uint(kc1.x));
            mma_tf32(cB, aQ[5], __float_as_uint(kb1.y), __float_as_uint(kc1.y));
            mma_tf32(cA, aQ[6], __float_as_uint(kb1.z), __float_as_uint(kc1.z));
            mma_tf32(cB, aQ[7], __float_as_uint(kb1.w), __float_as_uint(kc1.w));

            int clo = ni*8 + q*2;
            float4 plo = *(const float4*)&pj4[clo*4];
            float4 phi = *(const float4*)&pj4[(clo+1)*4];
            float dl0 = rpl0.x*plo.x + rpl0.y*plo.y + rpl0.z*plo.z;
            float dh0 = rpl0.x*phi.x + rpl0.y*phi.y + rpl0.z*phi.z;
            float dl1 = rpl1.x*plo.x + rpl1.y*plo.y + rpl1.z*plo.z;
            float dh1 = rpl1.x*phi.x + rpl1.y*phi.y + rpl1.z*phi.z;
            float e00 = ex2f(fmaf(cA[0] + cB[0], K1EXP, dl0));
            float e01 = ex2f(fmaf(cA[1] + cB[1], K1EXP, dh0));
            float e10 = ex2f(fmaf(cA[2] + cB[2], K1EXP, dl1));
            float e11 = ex2f(fmaf(cA[3] + cB[3], K1EXP, dh1));
            lsum0 += e00 + e01;
            lsum1 += e10 + e11;

            // P fragments via quad shuffles
            float t00a = __shfl_sync(0xffffffffu, e00, s0, 4);
            float t01a = __shfl_sync(0xffffffffu, e01, s0, 4);
            float t10a = __shfl_sync(0xffffffffu, e10, s0, 4);
            float t11a = __shfl_sync(0xffffffffu, e11, s0, 4);
            float t00b = __shfl_sync(0xffffffffu, e00, s1, 4);
            float t01b = __shfl_sync(0xffffffffu, e01, s1, 4);
            float t10b = __shfl_sync(0xffffffffu, e10, s1, 4);
            float t11b = __shfl_sync(0xffffffffu, e11, s1, 4);
            uint32_t aP[4];
            aP[0] = tf32u(odd ? t01a : t00a);
            aP[1] = tf32u(odd ? t11a : t10a);
            aP[2] = tf32u(odd ? t01b : t00b);
            aP[3] = tf32u(odd ? t11b : t10b);

            // V fragments: contiguous vector loads (rows j=ni*8+q, +4)
            float4 vb0 = *(const float4*)&Vs[(ni*8 + q)*SK + g*8];
            float4 vb1 = *(const float4*)&Vs[(ni*8 + q)*SK + g*8 + 4];
            float4 vc0 = *(const float4*)&Vs[(ni*8 + q + 4)*SK + g*8];
            float4 vc1 = *(const float4*)&Vs[(ni*8 + q + 4)*SK + g*8 + 4];
            mma_tf32(o[0], aP, __float_as_uint(vb0.x), __float_as_uint(vc0.x));
            mma_tf32(o[1], aP, __float_as_uint(vb0.y), __float_as_uint(vc0.y));
            mma_tf32(o[2], aP, __float_as_uint(vb0.z), __float_as_uint(vc0.z));
            mma_tf32(o[3], aP, __float_as_uint(vb0.w), __float_as_uint(vc0.w));
            mma_tf32(o[4], aP, __float_as_uint(vb1.x), __float_as_uint(vc1.x));
            mma_tf32(o[5], aP, __float_as_uint(vb1.y), __float_as_uint(vc1.y));
            mma_tf32(o[6], aP, __float_as_uint(vb1.z), __float_as_uint(vc1.z));
            mma_tf32(o[7], aP, __float_as_uint(vb1.w), __float_as_uint(vc1.w));
        }
    }

    lsum0 += __shfl_xor_sync(0xffffffffu, lsum0, 1);
    lsum0 += __shfl_xor_sync(0xffffffffu, lsum0, 2);
    lsum1 += __shfl_xor_sync(0xffffffffu, lsum1, 1);
    lsum1 += __shfl_xor_sync(0xffffffffu, lsum1, 2);
    float inv0 = 1.f / lsum0, inv1 = 1.f / lsum1;

    // NOTE: permuted V means o[n] columns map to d = n*8 + g? No —
    // V fragment b0 element n corresponds to logical d with (d&7)*8+(d>>3) = g*8+n
    // -> d&7 = g? g*8+n means col index in permuted space = g*8+n, which holds
    //    value of logical d where (d&7)=g, (d>>3)=n  =>  d = n*8 + g.
    // mma output col = fragment col index = the SAME n ordering we fed; output
    // column 'nc' of the mma equals logical d = nc*8 + g? Output cols are the
    // B columns in the order supplied: we supplied B col block n (8 cols per mma:
    // cols = n*8..n*8+7 in fragment space)... Each mma n covers output cols
    // [fragment cols] = {d : (d>>3)==n}? No: one mma produces 8 output columns;
    // we issue 8 mma (n=0..7), mma 'n' using B values at permuted cols g*8+n for
    // g=0..7 -> logical d = n*8+g... wait (d&7)*8+(d>>3) = g*8+n  =>  d&7=g, d>>3=n
    // => d = n*8+g. Within mma 'n', the 8 B-columns are indexed by g (lane group),
    // i.e. output col index within tile = g -> logical d = n*8 + g. The mma's
    // output column for lane q*2 pair is col (q*2, q*2+1) in ITS 8-col space ->
    // logical d = n*8 + q*2 (+1). Same mapping as before. Writes below unchanged.
    float* dst0 = g_AO + ((size_t)b*Nn + i0 + r0) * Cc + h*Dd;
    float* dst1 = g_AO + ((size_t)b*Nn + i0 + r1) * Cc + h*Dd;
#pragma unroll
    for (int n = 0; n < 8; n++) {
        int col = n*8 + q*2;
        *(float2*)(dst0 + col) = make_float2(o[n][0]*inv0, o[n][1]*inv0);
        *(float2*)(dst1 + col) = make_float2(o[n][2]*inv1, o[n][3]*inv1);
    }
}

// ---------------------------------------------------------------------------
extern "C" void kernel_launch(void* const* d_in, const int* in_sizes, int n_in,
                              void* d_out, int out_size) {
    const float* x         = (const float*)d_in[0];
    const float* R         = (const float*)d_in[1];
    const float* P         = (const float*)d_in[2];
    const float* qkv_w     = (const float*)d_in[3];
    const float* qkv_b     = (const float*)d_in[4];
    const float* proj_w    = (const float*)d_in[5];
    const float* proj_b    = (const float*)d_in[6];
    const float* pos_scale = (const float*)d_in[7];
    float* out = (float*)d_out;

    cudaFuncSetAttribute(flash_mma_kernel, cudaFuncAttributeMaxDynamicSharedMemorySize, FL_SMEM);

    rp_kernel<<<(Bb*Nn + 255) / 256, 256>>>(R, P, pos_scale);
    gemm_mma_kernel<true><<<dim3(768/64, (Bb*Nn)/128), 256>>>(x, qkv_w, qkv_b, nullptr);
    flash_mma_kernel<<<dim3(Nn/128, Hh, Bb), 256, FL_SMEM>>>(P);
    gemm_mma_kernel<false><<<dim3(Cc/64, (Bb*Nn)/128), 256>>>(nullptr, proj_w, proj_b, out);
}

// round 13
// speedup vs baseline: 2.8545x; 1.4389x over previous
#include <cuda_runtime.h>
#include <cuda_fp16.h>
#include <cstdint>
#include <math.h>

#define Bb 4
#define Nn 2048
#define Cc 256
#define Hh 4
#define Dd 64
#define K1EXP 0.18033688011112042f   // 0.125 * log2(e)
#define LOG2E 1.4426950408889634f

// ===================== helpers =====================
__device__ __forceinline__ uint32_t tf32u(float x) {
    uint32_t u; asm("cvt.rna.tf32.f32 %0,%1;" : "=r"(u) : "f"(x)); return u;
}
__device__ __forceinline__ float tf32f(float x) { return __uint_as_float(tf32u(x)); }
__device__ __forceinline__ float ex2f(float x) {
    float y; asm("ex2.approx.f32 %0,%1;" : "=f"(y) : "f"(x)); return y;
}
__device__ __forceinline__ void mma_tf32(float c[4], const uint32_t a[4],
                                         uint32_t b0, uint32_t b1) {
    asm volatile("mma.sync.aligned.m16n8k8.row.col.f32.tf32.tf32.f32 "
        "{%0,%1,%2,%3}, {%4,%5,%6,%7}, {%8,%9}, {%0,%1,%2,%3};"
        : "+f"(c[0]), "+f"(c[1]), "+f"(c[2]), "+f"(c[3])
        : "r"(a[0]), "r"(a[1]), "r"(a[2]), "r"(a[3]), "r"(b0), "r"(b1));
}
__device__ __forceinline__ void mma_f16(float c[4], const uint32_t a[4],
                                        uint32_t b0, uint32_t b1) {
    asm volatile("mma.sync.aligned.m16n8k16.row.col.f32.f16.f16.f32 "
        "{%0,%1,%2,%3}, {%4,%5,%6,%7}, {%8,%9}, {%0,%1,%2,%3};"
        : "+f"(c[0]), "+f"(c[1]), "+f"(c[2]), "+f"(c[3])
        : "r"(a[0]), "r"(a[1]), "r"(a[2]), "r"(a[3]), "r"(b0), "r"(b1));
}
__device__ __forceinline__ uint32_t h2u(float a, float b) {
    __half2 h = __floats2half2_rn(a, b);
    return *reinterpret_cast<uint32_t*>(&h);
}
__device__ __forceinline__ float4 tf32x4(float4 v) {
    return make_float4(tf32f(v.x), tf32f(v.y), tf32f(v.z), tf32f(v.w));
}
__device__ __forceinline__ float4 sub4(float4 a, float4 b) {
    return make_float4(a.x-b.x, a.y-b.y, a.z-b.z, a.w-b.w);
}

// ===================== scratch =====================
__device__ __align__(16) float g_Q[Bb*Hh*Nn*Dd];
__device__ __align__(16) float g_K[Bb*Hh*Nn*Dd];
__device__ __align__(16) float g_V[Bb*Hh*Nn*Dd];
__device__ __align__(16) float g_RP[Bb*Nn*4];    // rp * pos_scale * log2(e)
__device__ __align__(16) float g_AO[Bb*Nn*Cc];

// ---------------------------------------------------------------------------
__global__ void rp_kernel(const float* __restrict__ R, const float* __restrict__ P,
                          const float* __restrict__ pos_scale) {
    int idx = blockIdx.x * blockDim.x + threadIdx.x;
    if (idx >= Bb * Nn) return;
    int b = idx / Nn, j = idx % Nn;
    float p0 = P[j*3+0], p1 = P[j*3+1], p2 = P[j*3+2];
    float ps = *pos_scale * LOG2E;
    const float* Rb = R + b*9;
#pragma unroll
    for (int c = 0; c < 3; c++)
        g_RP[idx*4 + c] = ps * (Rb[c*3+0]*p0 + Rb[c*3+1]*p1 + Rb[c*3+2]*p2);
    g_RP[idx*4 + 3] = 0.f;
}

// ---------------------------------------------------------------------------
// Tensor-core NT GEMM (unchanged from R10, passing): 2-pass tf32 W-split.
// ---------------------------------------------------------------------------
#define GST 20

template<bool IS_QKV>
__global__ __launch_bounds__(256)
void gemm_mma_kernel(const float* __restrict__ A, const float* __restrict__ W,
                     const float* __restrict__ bias, float* __restrict__ Out) {
    __shared__ __align__(16) float As[128*GST];
    __shared__ __align__(16) float Ws_h[64*GST];
    __shared__ __align__(16) float Ws_l[64*GST];

    const float* Ap;
    if constexpr (IS_QKV) Ap = A; else Ap = g_AO;

    int tid = threadIdx.x;
    int w = tid >> 5, lane = tid & 31, g = lane >> 2, q = lane & 3;
    int wm = (w & 3) * 32, wn = (w >> 2) * 32;
    int m0 = blockIdx.y * 128, n0 = blockIdx.x * 64;

    int ar = tid >> 1, ak = (tid & 1) * 8;
    int wr = tid >> 2, wk = (tid & 3) * 4;

    float4 sa0, sa1, sw0;
    const float* Abase = Ap + (size_t)(m0 + ar) * Cc + ak;
    const float* Wbase = W  + (size_t)(n0 + wr) * Cc + wk;

    sa0 = *(const float4*)(Abase);
    sa1 = *(const float4*)(Abase + 4);
    sw0 = *(const float4*)(Wbase);

    float c[2][4][4];
#pragma unroll
    for (int mt = 0; mt < 2; mt++)
#pragma unroll
        for (int nt = 0; nt < 4; nt++)
#pragma unroll
            for (int i = 0; i < 4; i++) c[mt][nt][i] = 0.f;

    for (int it = 0; it < Cc/16; it++) {
        __syncthreads();
        {
            float4 hw = tf32x4(sw0);
            float4 lw = tf32x4(sub4(sw0, hw));
            *(float4*)&As[ar*GST + ak]     = tf32x4(sa0);
            *(float4*)&As[ar*GST + ak + 4] = tf32x4(sa1);
            *(float4*)&Ws_h[wr*GST + wk]   = hw;
            *(float4*)&Ws_l[wr*GST + wk]   = lw;
        }
        __syncthreads();
        if (it + 1 < Cc/16) {
            sa0 = *(const float4*)(Abase + (it+1)*16);
            sa1 = *(const float4*)(Abase + (it+1)*16 + 4);
            sw0 = *(const float4*)(Wbase + (it+1)*16);
        }
#pragma unroll
        for (int ks = 0; ks < 2; ks++) {
            uint32_t ah[2][4];
#pragma unroll
            for (int mt = 0; mt < 2; mt++) {
                int r0 = wm + mt*16 + g, r1 = r0 + 8;
                ah[mt][0] = __float_as_uint(As[r0*GST + ks*8 + q]);
                ah[mt][1] = __float_as_uint(As[r1*GST + ks*8 + q]);
                ah[mt][2] = __float_as_uint(As[r0*GST + ks*8 + q + 4]);
                ah[mt][3] = __float_as_uint(As[r1*GST + ks*8 + q + 4]);
            }
#pragma unroll
            for (int nt = 0; nt < 4; nt++) {
                int nr = wn + nt*8 + g;
                uint32_t bh0 = __float_as_uint(Ws_h[nr*GST + ks*8 + q]);
                uint32_t bh1 = __float_as_uint(Ws_h[nr*GST + ks*8 + q + 4]);
                uint32_t bl0 = __float_as_uint(Ws_l[nr*GST + ks*8 + q]);
                uint32_t bl1 = __float_as_uint(Ws_l[nr*GST + ks*8 + q + 4]);
                mma_tf32(c[0][nt], ah[0], bh0, bh1);
                mma_tf32(c[1][nt], ah[1], bh0, bh1);
                mma_tf32(c[0][nt], ah[0], bl0, bl1);
                mma_tf32(c[1][nt], ah[1], bl0, bl1);
            }
        }
    }

#pragma unroll
    for (int mt = 0; mt < 2; mt++) {
#pragma unroll
        for (int nt = 0; nt < 4; nt++) {
            int n = n0 + wn + nt*8 + q*2;
            float b0 = bias[n], b1 = bias[n+1];
#pragma unroll
            for (int half = 0; half < 2; half++) {
                int m = m0 + wm + mt*16 + g + half*8;
                float v0 = c[mt][nt][half*2]   + b0;
                float v1 = c[mt][nt][half*2+1] + b1;
                if constexpr (IS_QKV) {
                    int bb = m >> 11;
                    int nnr = m & (Nn - 1);
                    int which = n >> 8;
                    int h = (n >> 6) & (Hh - 1);
                    int d = n & (Dd - 1);
                    float* dst = (which == 0) ? g_Q : ((which == 1) ? g_K : g_V);
                    *(float2*)&dst[((size_t)(bb*Hh + h) * Nn + nnr) * Dd + d] = make_float2(v0, v1);
                } else {
                    *(float2*)&Out[(size_t)m * Cc + n] = make_float2(v0, v1);
                }
            }
        }
    }
}

// ---------------------------------------------------------------------------
// Flash attention via mma.sync.m16n8k16.f16 with ONLINE exact row-max.
// kv tile = 64 so full S tile fits in registers; exact max -> fp16 P always
// in normal range (headroom +8 octaves). Fragment-major smem, no P smem,
// no P shuffles.
// ---------------------------------------------------------------------------
__global__ __launch_bounds__(256, 2)
void flash_mma_kernel(const float* __restrict__ Pg) {
    __shared__ uint32_t smbuf[4352];   // Kf [0,2048), Vf [2048,4096); Qh overlaps [0,4224)
    __shared__ float pj4[256];
    uint32_t* Kf = smbuf;
    uint32_t* Vf = smbuf + 2048;
    uint32_t* Qh = smbuf;

    int tid = threadIdx.x;
    int w = tid >> 5, t = tid & 31;
    int g = t >> 2, q = t & 3;
    int b = blockIdx.z, h = blockIdx.y;
    int i0 = blockIdx.x * 128;

    const float* Qg = g_Q + (size_t)(b*Hh + h) * Nn * Dd;
    const float* Kg = g_K + (size_t)(b*Hh + h) * Nn * Dd;
    const float* Vg = g_V + (size_t)(b*Hh + h) * Nn * Dd;

    // ---- stage Q (half2), pull A-fragments, release ----
    {
        int row = tid >> 1, dh2 = (tid & 1) * 16;
        const float* src = Qg + (size_t)(i0 + row) * Dd + dh2*2;
#pragma unroll
        for (int i8 = 0; i8 < 8; i8++) {
            float4 v = *(const float4*)(src + i8*4);
            int col = dh2 + i8*2;
            Qh[row*33 + col]     = h2u(v.x, v.y);
            Qh[row*33 + col + 1] = h2u(v.z, v.w);
        }
    }
    __syncthreads();

    int r0 = w*16 + g, r1 = r0 + 8;
    uint32_t aQ[4][4];
#pragma unroll
    for (int c = 0; c < 4; c++) {
        aQ[c][0] = Qh[r0*33 + 8*c + q];
        aQ[c][1] = Qh[r1*33 + 8*c + q];
        aQ[c][2] = Qh[r0*33 + 8*c + q + 4];
        aQ[c][3] = Qh[r1*33 + 8*c + q + 4];
    }
    float4 rpl0 = *(const float4*)&g_RP[((size_t)b*Nn + i0 + r0) * 4];
    float4 rpl1 = *(const float4*)&g_RP[((size_t)b*Nn + i0 + r1) * 4];

    float o[8][4];
#pragma unroll
    for (int n = 0; n < 8; n++)
#pragma unroll
        for (int c = 0; c < 4; c++) o[n][c] = 0.f;
    float lsum0 = 0.f, lsum1 = 0.f;
    float m0 = -1e30f, m1 = -1e30f;

    // K/V staging constants (64-row tiles)
    int row4 = tid >> 2;           // 0..63 : j row
    int c4 = tid & 3;              // k16-chunk for K / d-quarter for V
    int dh = c4 * 16;
    int jodd = row4 & 1;
    int q_j = (row4 >> 1) & 3;
    int b_j = (row4 >> 3) & 1;
    int pi_j = row4 >> 4;
    int kni = row4 >> 3, kg = row4 & 7;

    for (int tt = 0; tt < Nn / 64; tt++) {
        int j0 = tt * 64;
        __syncthreads();   // WAR on prior tile (and Q frag reads at tt=0)

        // ---- stage K (fragment-major) ----
        {
            const float* src = Kg + (size_t)(j0 + row4) * Dd + c4*16;
#pragma unroll
            for (int i8 = 0; i8 < 4; i8++) {
                float4 v = *(const float4*)(src + i8*4);
                int b2 = i8 >> 1, q0 = (i8*2) & 3;
                int addr = kni*256 + c4*64 + b2*32 + kg*4 + q0;
                *(uint2*)&Kf[addr] = make_uint2(h2u(v.x, v.y), h2u(v.z, v.w));
            }
        }
        // ---- stage V (transposed to half2-along-j) ----
        {
            const float* src = Vg + (size_t)(j0 + row4) * Dd + dh;
            float v[16];
#pragma unroll
            for (int i8 = 0; i8 < 4; i8++)
                *(float4*)&v[i8*4] = *(const float4*)(src + i8*4);
#pragma unroll
            for (int i = 0; i < 8; i++) {
                float send = jodd ? v[i] : v[8 + i];
                float recv = __shfl_xor_sync(0xffffffffu, send, 4);
                int d = dh + (jodd ? 8 : 0) + i;
                uint32_t h2 = jodd ? h2u(recv, v[8 + i]) : h2u(v[i], recv);
                Vf[pi_j*512 + (d >> 3)*64 + b_j*32 + (d & 7)*4 + q_j] = h2;
            }
        }
        if (tid < 64) {
            const float* pp = Pg + (size_t)(j0 + tid) * 3;
            *(float4*)&pj4[tid*4] = make_float4(pp[0], pp[1], pp[2], 0.f);
        }
        __syncthreads();

        // ---- GEMM1: all 8 ni tiles into registers (logits, log2 domain) ----
        float s[8][4];
#pragma unroll
        for (int ni = 0; ni < 8; ni++) {
            float cA[4] = {0.f,0.f,0.f,0.f}, cB[4] = {0.f,0.f,0.f,0.f};
            int kbase = ni*256 + g*4 + q;
            mma_f16(cA, aQ[0], Kf[kbase +   0], Kf[kbase +  32]);
            mma_f16(cB, aQ[1], Kf[kbase +  64], Kf[kbase +  96]);
            mma_f16(cA, aQ[2], Kf[kbase + 128], Kf[kbase + 160]);
            mma_f16(cB, aQ[3], Kf[kbase + 192], Kf[kbase + 224]);

            int clo = ni*8 + q*2;
            float4 plo = *(const float4*)&pj4[clo*4];
            float4 phi = *(const float4*)&pj4[(clo+1)*4];
            s[ni][0] = fmaf(cA[0] + cB[0], K1EXP, rpl0.x*plo.x + rpl0.y*plo.y + rpl0.z*plo.z);
            s[ni][1] = fmaf(cA[1] + cB[1], K1EXP, rpl0.x*phi.x + rpl0.y*phi.y + rpl0.z*phi.z);
            s[ni][2] = fmaf(cA[2] + cB[2], K1EXP, rpl1.x*plo.x + rpl1.y*plo.y + rpl1.z*plo.z);
            s[ni][3] = fmaf(cA[3] + cB[3], K1EXP, rpl1.x*phi.x + rpl1.y*phi.y + rpl1.z*phi.z);
        }

        // ---- exact tile max (quad reduce), online rescale ----
        float mt0 = fmaxf(s[0][0], s[0][1]), mt1 = fmaxf(s[0][2], s[0][3]);
#pragma unroll
        for (int ni = 1; ni < 8; ni++) {
            mt0 = fmaxf(mt0, fmaxf(s[ni][0], s[ni][1]));
            mt1 = fmaxf(mt1, fmaxf(s[ni][2], s[ni][3]));
        }
        mt0 = fmaxf(mt0, __shfl_xor_sync(0xffffffffu, mt0, 1));
        mt0 = fmaxf(mt0, __shfl_xor_sync(0xffffffffu, mt0, 2));
        mt1 = fmaxf(mt1, __shfl_xor_sync(0xffffffffu, mt1, 1));
        mt1 = fmaxf(mt1, __shfl_xor_sync(0xffffffffu, mt1, 2));
        float mn0 = fmaxf(m0, mt0), mn1 = fmaxf(m1, mt1);
        float al0 = ex2f(m0 - mn0), al1 = ex2f(m1 - mn1);
        m0 = mn0; m1 = mn1;
        lsum0 *= al0; lsum1 *= al1;
#pragma unroll
        for (int n = 0; n < 8; n++) {
            o[n][0] *= al0; o[n][1] *= al0;
            o[n][2] *= al1; o[n][3] *= al1;
        }

        // ---- exp (headroom +8 octaves: P in [2^-14, 2^8], all normal fp16) ----
        float sh0 = 8.0f - mn0, sh1 = 8.0f - mn1;
#pragma unroll
        for (int ni = 0; ni < 8; ni++) {
            float e0 = ex2f(s[ni][0] + sh0);
            float e1 = ex2f(s[ni][1] + sh0);
            float e2 = ex2f(s[ni][2] + sh1);
            float e3 = ex2f(s[ni][3] + sh1);
            lsum0 += e0 + e1;
            lsum1 += e2 + e3;
            s[ni][0] = e0; s[ni][1] = e1; s[ni][2] = e2; s[ni][3] = e3;
        }

        // ---- PV: 4 k16 tiles ----
#pragma unroll
        for (int pi = 0; pi < 4; pi++) {
            uint32_t aP[4];
            aP[0] = h2u(s[2*pi][0],   s[2*pi][1]);
            aP[1] = h2u(s[2*pi][2],   s[2*pi][3]);
            aP[2] = h2u(s[2*pi+1][0], s[2*pi+1][1]);
            aP[3] = h2u(s[2*pi+1][2], s[2*pi+1][3]);
            int vbase = pi*512 + g*4 + q;
#pragma unroll
            for (int n = 0; n < 8; n++) {
                uint32_t vb0 = Vf[vbase + n*64];
                uint32_t vb1 = Vf[vbase + n*64 + 32];
                mma_f16(o[n], aP, vb0, vb1);
            }
        }
    }

    lsum0 += __shfl_xor_sync(0xffffffffu, lsum0, 1);
    lsum0 += __shfl_xor_sync(0xffffffffu, lsum0, 2);
    lsum1 += __shfl_xor_sync(0xffffffffu, lsum1, 1);
    lsum1 += __shfl_xor_sync(0xffffffffu, lsum1, 2);
    float inv0 = 1.f / lsum0, inv1 = 1.f / lsum1;

    float* dst0 = g_AO + ((size_t)b*Nn + i0 + r0) * Cc + h*Dd;
    float* dst1 = g_AO + ((size_t)b*Nn + i0 + r1) * Cc + h*Dd;
#pragma unroll
    for (int n = 0; n < 8; n++) {
        int col = n*8 + q*2;
        *(float2*)(dst0 + col) = make_float2(o[n][0]*inv0, o[n][1]*inv0);
        *(float2*)(dst1 + col) = make_float2(o[n][2]*inv1, o[n][3]*inv1);
    }
}

// ---------------------------------------------------------------------------
extern "C" void kernel_launch(void* const* d_in, const int* in_sizes, int n_in,
                              void* d_out, int out_size) {
    const float* x         = (const float*)d_in[0];
    const float* R         = (const float*)d_in[1];
    const float* P         = (const float*)d_in[2];
    const float* qkv_w     = (const float*)d_in[3];
    const float* qkv_b     = (const float*)d_in[4];
    const float* proj_w    = (const float*)d_in[5];
    const float* proj_b    = (const float*)d_in[6];
    const float* pos_scale = (const float*)d_in[7];
    float* out = (float*)d_out;

    rp_kernel<<<(Bb*Nn + 255) / 256, 256>>>(R, P, pos_scale);
    gemm_mma_kernel<true><<<dim3(768/64, (Bb*Nn)/128), 256>>>(x, qkv_w, qkv_b, nullptr);
    flash_mma_kernel<<<dim3(Nn/128, Hh, Bb), 256>>>(P);
    gemm_mma_kernel<false><<<dim3(Cc/64, (Bb*Nn)/128), 256>>>(nullptr, proj_w, proj_b, out);
}

// round 14
// speedup vs baseline: 3.0355x; 1.0634x over previous
#include <cuda_runtime.h>
#include <cuda_fp16.h>
#include <cstdint>
#include <math.h>

#define Bb 4
#define Nn 2048
#define Cc 256
#define Hh 4
#define Dd 64
#define K1EXP 0.18033688011112042f   // 0.125 * log2(e)
#define LOG2E 1.4426950408889634f

// ===================== helpers =====================
__device__ __forceinline__ float ex2f(float x) {
    float y; asm("ex2.approx.f32 %0,%1;" : "=f"(y) : "f"(x)); return y;
}
__device__ __forceinline__ void mma_f16(float c[4], const uint32_t a[4],
                                        uint32_t b0, uint32_t b1) {
    asm volatile("mma.sync.aligned.m16n8k16.row.col.f32.f16.f16.f32 "
        "{%0,%1,%2,%3}, {%4,%5,%6,%7}, {%8,%9}, {%0,%1,%2,%3};"
        : "+f"(c[0]), "+f"(c[1]), "+f"(c[2]), "+f"(c[3])
        : "r"(a[0]), "r"(a[1]), "r"(a[2]), "r"(a[3]), "r"(b0), "r"(b1));
}
__device__ __forceinline__ uint32_t h2u(float a, float b) {
    __half2 h = __floats2half2_rn(a, b);
    return *reinterpret_cast<uint32_t*>(&h);
}

// ===================== scratch =====================
__device__ __align__(16) float g_Q[Bb*Hh*Nn*Dd];
__device__ __align__(16) float g_K[Bb*Hh*Nn*Dd];
__device__ __align__(16) float g_V[Bb*Hh*Nn*Dd];
__device__ __align__(16) float g_RP[Bb*Nn*4];    // rp * pos_scale * log2(e)
__device__ __align__(16) float g_AO[Bb*Nn*Cc];

// ---------------------------------------------------------------------------
__global__ void rp_kernel(const float* __restrict__ R, const float* __restrict__ P,
                          const float* __restrict__ pos_scale) {
    int idx = blockIdx.x * blockDim.x + threadIdx.x;
    if (idx >= Bb * Nn) return;
    int b = idx / Nn, j = idx % Nn;
    float p0 = P[j*3+0], p1 = P[j*3+1], p2 = P[j*3+2];
    float ps = *pos_scale * LOG2E;
    const float* Rb = R + b*9;
#pragma unroll
    for (int c = 0; c < 3; c++)
        g_RP[idx*4 + c] = ps * (Rb[c*3+0]*p0 + Rb[c*3+1]*p1 + Rb[c*3+2]*p2);
    g_RP[idx*4 + 3] = 0.f;
}

// ---------------------------------------------------------------------------
// fp16 k16 NT GEMM, 2-pass hi/lo W split (fp16 mantissa == tf32 mantissa).
// CTA 128m x 64n, 8 warps (4x2), warp 32x32, K-tile 32.
// smem fragment-major half2 rows, stride 17 (conflict-free).
// ---------------------------------------------------------------------------
#define AST 17   // uint32 (half2) stride per row

template<bool IS_QKV>
__global__ __launch_bounds__(256)
void gemm_f16_kernel(const float* __restrict__ A, const float* __restrict__ W,
                     const float* __restrict__ bias, float* __restrict__ Out) {
    __shared__ uint32_t Ahs[128*AST];
    __shared__ uint32_t Whs[64*AST];
    __shared__ uint32_t Wls[64*AST];

    const float* Ap;
    if constexpr (IS_QKV) Ap = A; else Ap = g_AO;

    int tid = threadIdx.x;
    int w = tid >> 5, lane = tid & 31, g = lane >> 2, q = lane & 3;
    int wm = (w & 3) * 32, wn = (w >> 2) * 32;
    int m0 = blockIdx.y * 128, n0 = blockIdx.x * 64;

    int ar = tid >> 1, ak = (tid & 1) * 16;   // A: row, k-offset (halves of 32)
    int wr = tid >> 2, wk = (tid & 3) * 8;    // W: row, k-offset

    const float* Abase = Ap + (size_t)(m0 + ar) * Cc + ak;
    const float* Wbase = W  + (size_t)(n0 + wr) * Cc + wk;

    float4 sa[4], sw[2];
#pragma unroll
    for (int i = 0; i < 4; i++) sa[i] = *(const float4*)(Abase + i*4);
#pragma unroll
    for (int i = 0; i < 2; i++) sw[i] = *(const float4*)(Wbase + i*4);

    float c[2][4][4];
#pragma unroll
    for (int mt = 0; mt < 2; mt++)
#pragma unroll
        for (int nt = 0; nt < 4; nt++)
#pragma unroll
            for (int i = 0; i < 4; i++) c[mt][nt][i] = 0.f;

    for (int it = 0; it < Cc/32; it++) {
        __syncthreads();
        {
            int abase = ar*AST + (ak >> 1);
#pragma unroll
            for (int i = 0; i < 4; i++) {
                Ahs[abase + i*2]     = h2u(sa[i].x, sa[i].y);
                Ahs[abase + i*2 + 1] = h2u(sa[i].z, sa[i].w);
            }
            int wbase = wr*AST + (wk >> 1);
#pragma unroll
            for (int i = 0; i < 2; i++) {
                __half hx = __float2half_rn(sw[i].x), hy = __float2half_rn(sw[i].y);
                __half hz = __float2half_rn(sw[i].z), hw = __float2half_rn(sw[i].w);
                uint32_t u0 = (uint32_t)__half_as_ushort(hx) | ((uint32_t)__half_as_ushort(hy) << 16);
                uint32_t u1 = (uint32_t)__half_as_ushort(hz) | ((uint32_t)__half_as_ushort(hw) << 16);
                Whs[wbase + i*2]     = u0;
                Whs[wbase + i*2 + 1] = u1;
                Wls[wbase + i*2]     = h2u(sw[i].x - __half2float(hx), sw[i].y - __half2float(hy));
                Wls[wbase + i*2 + 1] = h2u(sw[i].z - __half2float(hz), sw[i].w - __half2float(hw));
            }
        }
        __syncthreads();
        if (it + 1 < Cc/32) {
#pragma unroll
            for (int i = 0; i < 4; i++) sa[i] = *(const float4*)(Abase + (it+1)*32 + i*4);
#pragma unroll
            for (int i = 0; i < 2; i++) sw[i] = *(const float4*)(Wbase + (it+1)*32 + i*4);
        }
#pragma unroll
        for (int ch = 0; ch < 2; ch++) {    // two k16 chunks
            uint32_t a[2][4];
#pragma unroll
            for (int mt = 0; mt < 2; mt++) {
                int r0 = wm + mt*16 + g, r1 = r0 + 8;
                a[mt][0] = Ahs[r0*AST + ch*8 + q];
                a[mt][1] = Ahs[r1*AST + ch*8 + q];
                a[mt][2] = Ahs[r0*AST + ch*8 + q + 4];
                a[mt][3] = Ahs[r1*AST + ch*8 + q + 4];
            }
#pragma unroll
            for (int nt = 0; nt < 4; nt++) {
                int nr = wn + nt*8 + g;
                uint32_t bh0 = Whs[nr*AST + ch*8 + q];
                uint32_t bh1 = Whs[nr*AST + ch*8 + q + 4];
                uint32_t bl0 = Wls[nr*AST + ch*8 + q];
                uint32_t bl1 = Wls[nr*AST + ch*8 + q + 4];
                mma_f16(c[0][nt], a[0], bh0, bh1);
                mma_f16(c[1][nt], a[1], bh0, bh1);
                mma_f16(c[0][nt], a[0], bl0, bl1);
                mma_f16(c[1][nt], a[1], bl0, bl1);
            }
        }
    }

#pragma unroll
    for (int mt = 0; mt < 2; mt++) {
#pragma unroll
        for (int nt = 0; nt < 4; nt++) {
            int n = n0 + wn + nt*8 + q*2;
            float b0 = bias[n], b1 = bias[n+1];
#pragma unroll
            for (int half = 0; half < 2; half++) {
                int m = m0 + wm + mt*16 + g + half*8;
                float v0 = c[mt][nt][half*2]   + b0;
                float v1 = c[mt][nt][half*2+1] + b1;
                if constexpr (IS_QKV) {
                    int bb = m >> 11;
                    int nnr = m & (Nn - 1);
                    int which = n >> 8;
                    int h = (n >> 6) & (Hh - 1);
                    int d = n & (Dd - 1);
                    float* dst = (which == 0) ? g_Q : ((which == 1) ? g_K : g_V);
                    *(float2*)&dst[((size_t)(bb*Hh + h) * Nn + nnr) * Dd + d] = make_float2(v0, v1);
                } else {
                    *(float2*)&Out[(size_t)m * Cc + n] = make_float2(v0, v1);
                }
            }
        }
    }
}

// ---------------------------------------------------------------------------
// Flash attention (unchanged from R13, passing @ 4.38e-4):
// mma.sync.m16n8k16.f16, online exact row-max, kv tile 64, fragment-major smem.
// ---------------------------------------------------------------------------
__global__ __launch_bounds__(256, 2)
void flash_mma_kernel(const float* __restrict__ Pg) {
    __shared__ uint32_t smbuf[4352];
    __shared__ float pj4[256];
    uint32_t* Kf = smbuf;
    uint32_t* Vf = smbuf + 2048;
    uint32_t* Qh = smbuf;

    int tid = threadIdx.x;
    int w = tid >> 5, t = tid & 31;
    int g = t >> 2, q = t & 3;
    int b = blockIdx.z, h = blockIdx.y;
    int i0 = blockIdx.x * 128;

    const float* Qg = g_Q + (size_t)(b*Hh + h) * Nn * Dd;
    const float* Kg = g_K + (size_t)(b*Hh + h) * Nn * Dd;
    const float* Vg = g_V + (size_t)(b*Hh + h) * Nn * Dd;

    {
        int row = tid >> 1, dh2 = (tid & 1) * 16;
        const float* src = Qg + (size_t)(i0 + row) * Dd + dh2*2;
#pragma unroll
        for (int i8 = 0; i8 < 8; i8++) {
            float4 v = *(const float4*)(src + i8*4);
            int col = dh2 + i8*2;
            Qh[row*33 + col]     = h2u(v.x, v.y);
            Qh[row*33 + col + 1] = h2u(v.z, v.w);
        }
    }
    __syncthreads();

    int r0 = w*16 + g, r1 = r0 + 8;
    uint32_t aQ[4][4];
#pragma unroll
    for (int c = 0; c < 4; c++) {
        aQ[c][0] = Qh[r0*33 + 8*c + q];
        aQ[c][1] = Qh[r1*33 + 8*c + q];
        aQ[c][2] = Qh[r0*33 + 8*c + q + 4];
        aQ[c][3] = Qh[r1*33 + 8*c + q + 4];
    }
    float4 rpl0 = *(const float4*)&g_RP[((size_t)b*Nn + i0 + r0) * 4];
    float4 rpl1 = *(const float4*)&g_RP[((size_t)b*Nn + i0 + r1) * 4];

    float o[8][4];
#pragma unroll
    for (int n = 0; n < 8; n++)
#pragma unroll
        for (int c = 0; c < 4; c++) o[n][c] = 0.f;
    float lsum0 = 0.f, lsum1 = 0.f;
    float m0 = -1e30f, m1 = -1e30f;

    int row4 = tid >> 2;
    int c4 = tid & 3;
    int dh = c4 * 16;
    int jodd = row4 & 1;
    int q_j = (row4 >> 1) & 3;
    int b_j = (row4 >> 3) & 1;
    int pi_j = row4 >> 4;
    int kni = row4 >> 3, kg = row4 & 7;

    for (int tt = 0; tt < Nn / 64; tt++) {
        int j0 = tt * 64;
        __syncthreads();

        {
            const float* src = Kg + (size_t)(j0 + row4) * Dd + c4*16;
#pragma unroll
            for (int i8 = 0; i8 < 4; i8++) {
                float4 v = *(const float4*)(src + i8*4);
                int b2 = i8 >> 1, q0 = (i8*2) & 3;
                int addr = kni*256 + c4*64 + b2*32 + kg*4 + q0;
                *(uint2*)&Kf[addr] = make_uint2(h2u(v.x, v.y), h2u(v.z, v.w));
            }
        }
        {
            const float* src = Vg + (size_t)(j0 + row4) * Dd + dh;
            float v[16];
#pragma unroll
            for (int i8 = 0; i8 < 4; i8++)
                *(float4*)&v[i8*4] = *(const float4*)(src + i8*4);
#pragma unroll
            for (int i = 0; i < 8; i++) {
                float send = jodd ? v[i] : v[8 + i];
                float recv = __shfl_xor_sync(0xffffffffu, send, 4);
                int d = dh + (jodd ? 8 : 0) + i;
                uint32_t h2 = jodd ? h2u(recv, v[8 + i]) : h2u(v[i], recv);
                Vf[pi_j*512 + (d >> 3)*64 + b_j*32 + (d & 7)*4 + q_j] = h2;
            }
        }
        if (tid < 64) {
            const float* pp = Pg + (size_t)(j0 + tid) * 3;
            *(float4*)&pj4[tid*4] = make_float4(pp[0], pp[1], pp[2], 0.f);
        }
        __syncthreads();

        float s[8][4];
#pragma unroll
        for (int ni = 0; ni < 8; ni++) {
            float cA[4] = {0.f,0.f,0.f,0.f}, cB[4] = {0.f,0.f,0.f,0.f};
            int kbase = ni*256 + g*4 + q;
            mma_f16(cA, aQ[0], Kf[kbase +   0], Kf[kbase +  32]);
            mma_f16(cB, aQ[1], Kf[kbase +  64], Kf[kbase +  96]);
            mma_f16(cA, aQ[2], Kf[kbase + 128], Kf[kbase + 160]);
            mma_f16(cB, aQ[3], Kf[kbase + 192], Kf[kbase + 224]);

            int clo = ni*8 + q*2;
            float4 plo = *(const float4*)&pj4[clo*4];
            float4 phi = *(const float4*)&pj4[(clo+1)*4];
            s[ni][0] = fmaf(cA[0] + cB[0], K1EXP, rpl0.x*plo.x + rpl0.y*plo.y + rpl0.z*plo.z);
            s[ni][1] = fmaf(cA[1] + cB[1], K1EXP, rpl0.x*phi.x + rpl0.y*phi.y + rpl0.z*phi.z);
            s[ni][2] = fmaf(cA[2] + cB[2], K1EXP, rpl1.x*plo.x + rpl1.y*plo.y + rpl1.z*plo.z);
            s[ni][3] = fmaf(cA[3] + cB[3], K1EXP, rpl1.x*phi.x + rpl1.y*phi.y + rpl1.z*phi.z);
        }

        float mt0 = fmaxf(s[0][0], s[0][1]), mt1 = fmaxf(s[0][2], s[0][3]);
#pragma unroll
        for (int ni = 1; ni < 8; ni++) {
            mt0 = fmaxf(mt0, fmaxf(s[ni][0], s[ni][1]));
            mt1 = fmaxf(mt1, fmaxf(s[ni][2], s[ni][3]));
        }
        mt0 = fmaxf(mt0, __shfl_xor_sync(0xffffffffu, mt0, 1));
        mt0 = fmaxf(mt0, __shfl_xor_sync(0xffffffffu, mt0, 2));
        mt1 = fmaxf(mt1, __shfl_xor_sync(0xffffffffu, mt1, 1));
        mt1 = fmaxf(mt1, __shfl_xor_sync(0xffffffffu, mt1, 2));
        float mn0 = fmaxf(m0, mt0), mn1 = fmaxf(m1, mt1);
        float al0 = ex2f(m0 - mn0), al1 = ex2f(m1 - mn1);
        m0 = mn0; m1 = mn1;
        lsum0 *= al0; lsum1 *= al1;
#pragma unroll
        for (int n = 0; n < 8; n++) {
            o[n][0] *= al0; o[n][1] *= al0;
            o[n][2] *= al1; o[n][3] *= al1;
        }

        float sh0 = 8.0f - mn0, sh1 = 8.0f - mn1;
#pragma unroll
        for (int ni = 0; ni < 8; ni++) {
            float e0 = ex2f(s[ni][0] + sh0);
            float e1 = ex2f(s[ni][1] + sh0);
            float e2 = ex2f(s[ni][2] + sh1);
            float e3 = ex2f(s[ni][3] + sh1);
            lsum0 += e0 + e1;
            lsum1 += e2 + e3;
            s[ni][0] = e0; s[ni][1] = e1; s[ni][2] = e2; s[ni][3] = e3;
        }

#pragma unroll
        for (int pi = 0; pi < 4; pi++) {
            uint32_t aP[4];
            aP[0] = h2u(s[2*pi][0],   s[2*pi][1]);
            aP[1] = h2u(s[2*pi][2],   s[2*pi][3]);
            aP[2] = h2u(s[2*pi+1][0], s[2*pi+1][1]);
            aP[3] = h2u(s[2*pi+1][2], s[2*pi+1][3]);
            int vbase = pi*512 + g*4 + q;
#pragma unroll
            for (int n = 0; n < 8; n++) {
                uint32_t vb0 = Vf[vbase + n*64];
                uint32_t vb1 = Vf[vbase + n*64 + 32];
                mma_f16(o[n], aP, vb0, vb1);
            }
        }
    }

    lsum0 += __shfl_xor_sync(0xffffffffu, lsum0, 1);
    lsum0 += __shfl_xor_sync(0xffffffffu, lsum0, 2);
    lsum1 += __shfl_xor_sync(0xffffffffu, lsum1, 1);
    lsum1 += __shfl_xor_sync(0xffffffffu, lsum1, 2);
    float inv0 = 1.f / lsum0, inv1 = 1.f / lsum1;

    float* dst0 = g_AO + ((size_t)b*Nn + i0 + r0) * Cc + h*Dd;
    float* dst1 = g_AO + ((size_t)b*Nn + i0 + r1) * Cc + h*Dd;
#pragma unroll
    for (int n = 0; n < 8; n++) {
        int col = n*8 + q*2;
        *(float2*)(dst0 + col) = make_float2(o[n][0]*inv0, o[n][1]*inv0);
        *(float2*)(dst1 + col) = make_float2(o[n][2]*inv1, o[n][3]*inv1);
    }
}

// ---------------------------------------------------------------------------
extern "C" void kernel_launch(void* const* d_in, const int* in_sizes, int n_in,
                              void* d_out, int out_size) {
    const float* x         = (const float*)d_in[0];
    const float* R         = (const float*)d_in[1];
    const float* P         = (const float*)d_in[2];
    const float* qkv_w     = (const float*)d_in[3];
    const float* qkv_b     = (const float*)d_in[4];
    const float* proj_w    = (const float*)d_in[5];
    const float* proj_b    = (const float*)d_in[6];
    const float* pos_scale = (const float*)d_in[7];
    float* out = (float*)d_out;

    rp_kernel<<<(Bb*Nn + 255) / 256, 256>>>(R, P, pos_scale);
    gemm_f16_kernel<true><<<dim3(768/64, (Bb*Nn)/128), 256>>>(x, qkv_w, qkv_b, nullptr);
    flash_mma_kernel<<<dim3(Nn/128, Hh, Bb), 256>>>(P);
    gemm_f16_kernel<false><<<dim3(Cc/64, (Bb*Nn)/128), 256>>>(nullptr, proj_w, proj_b, out);
}

// round 15
// speedup vs baseline: 3.1166x; 1.0267x over previous
#include <cuda_runtime.h>
#include <cuda_fp16.h>
#include <cstdint>
#include <math.h>

#define Bb 4
#define Nn 2048
#define Cc 256
#define Hh 4
#define Dd 64
#define K1EXP 0.18033688011112042f   // 0.125 * log2(e)
#define LOG2E 1.4426950408889634f

// ===================== helpers =====================
__device__ __forceinline__ float ex2f(float x) {
    float y; asm("ex2.approx.f32 %0,%1;" : "=f"(y) : "f"(x)); return y;
}
__device__ __forceinline__ void mma_f16(float c[4], const uint32_t a[4],
                                        uint32_t b0, uint32_t b1) {
    asm volatile("mma.sync.aligned.m16n8k16.row.col.f32.f16.f16.f32 "
        "{%0,%1,%2,%3}, {%4,%5,%6,%7}, {%8,%9}, {%0,%1,%2,%3};"
        : "+f"(c[0]), "+f"(c[1]), "+f"(c[2]), "+f"(c[3])
        : "r"(a[0]), "r"(a[1]), "r"(a[2]), "r"(a[3]), "r"(b0), "r"(b1));
}
__device__ __forceinline__ uint32_t h2u(float a, float b) {
    __half2 h = __floats2half2_rn(a, b);
    return *reinterpret_cast<uint32_t*>(&h);
}

// ===================== scratch =====================
__device__ __align__(16) float g_Q[Bb*Hh*Nn*Dd];
__device__ __align__(16) float g_K[Bb*Hh*Nn*Dd];
__device__ __align__(16) float g_V[Bb*Hh*Nn*Dd];
__device__ __align__(16) float g_RP[Bb*Nn*4];    // rp * pos_scale * log2(e)
__device__ __align__(16) float g_AO[Bb*Nn*Cc];

// ---------------------------------------------------------------------------
__global__ void rp_kernel(const float* __restrict__ R, const float* __restrict__ P,
                          const float* __restrict__ pos_scale) {
    int idx = blockIdx.x * blockDim.x + threadIdx.x;
    if (idx >= Bb * Nn) return;
    int b = idx / Nn, j = idx % Nn;
    float p0 = P[j*3+0], p1 = P[j*3+1], p2 = P[j*3+2];
    float ps = *pos_scale * LOG2E;
    const float* Rb = R + b*9;
#pragma unroll
    for (int c = 0; c < 3; c++)
        g_RP[idx*4 + c] = ps * (Rb[c*3+0]*p0 + Rb[c*3+1]*p1 + Rb[c*3+2]*p2);
    g_RP[idx*4 + 3] = 0.f;
}

// ---------------------------------------------------------------------------
// fp16 k16 NT GEMM, 2-pass hi/lo W split, PING-PONG double buffer:
// one sync per K-tile, stores overlap other warps' mma.
// ---------------------------------------------------------------------------
#define AST 17   // uint32 (half2) stride per row

template<bool IS_QKV>
__global__ __launch_bounds__(256)
void gemm_f16_kernel(const float* __restrict__ A, const float* __restrict__ W,
                     const float* __restrict__ bias, float* __restrict__ Out) {
    __shared__ uint32_t Ahs[2][128*AST];
    __shared__ uint32_t Whs[2][64*AST];
    __shared__ uint32_t Wls[2][64*AST];

    const float* Ap;
    if constexpr (IS_QKV) Ap = A; else Ap = g_AO;

    int tid = threadIdx.x;
    int w = tid >> 5, lane = tid & 31, g = lane >> 2, q = lane & 3;
    int wm = (w & 3) * 32, wn = (w >> 2) * 32;
    int m0 = blockIdx.y * 128, n0 = blockIdx.x * 64;

    int ar = tid >> 1, ak = (tid & 1) * 16;
    int wr = tid >> 2, wk = (tid & 3) * 8;

    const float* Abase = Ap + (size_t)(m0 + ar) * Cc + ak;
    const float* Wbase = W  + (size_t)(n0 + wr) * Cc + wk;

    float4 sa[4], sw[2];

    auto loadregs = [&](int it) {
#pragma unroll
        for (int i = 0; i < 4; i++) sa[i] = *(const float4*)(Abase + it*32 + i*4);
#pragma unroll
        for (int i = 0; i < 2; i++) sw[i] = *(const float4*)(Wbase + it*32 + i*4);
    };
    auto stage = [&](int bufi) {
        int abase = ar*AST + (ak >> 1);
#pragma unroll
        for (int i = 0; i < 4; i++) {
            Ahs[bufi][abase + i*2]     = h2u(sa[i].x, sa[i].y);
            Ahs[bufi][abase + i*2 + 1] = h2u(sa[i].z, sa[i].w);
        }
        int wbase = wr*AST + (wk >> 1);
#pragma unroll
        for (int i = 0; i < 2; i++) {
            __half hx = __float2half_rn(sw[i].x), hy = __float2half_rn(sw[i].y);
            __half hz = __float2half_rn(sw[i].z), hw = __float2half_rn(sw[i].w);
            Whs[bufi][wbase + i*2]     = (uint32_t)__half_as_ushort(hx) | ((uint32_t)__half_as_ushort(hy) << 16);
            Whs[bufi][wbase + i*2 + 1] = (uint32_t)__half_as_ushort(hz) | ((uint32_t)__half_as_ushort(hw) << 16);
            Wls[bufi][wbase + i*2]     = h2u(sw[i].x - __half2float(hx), sw[i].y - __half2float(hy));
            Wls[bufi][wbase + i*2 + 1] = h2u(sw[i].z - __half2float(hz), sw[i].w - __half2float(hw));
        }
    };

    float c[2][4][4];
#pragma unroll
    for (int mt = 0; mt < 2; mt++)
#pragma unroll
        for (int nt = 0; nt < 4; nt++)
#pragma unroll
            for (int i = 0; i < 4; i++) c[mt][nt][i] = 0.f;

    loadregs(0);
    stage(0);
    __syncthreads();

    for (int it = 0; it < Cc/32; it++) {
        int cur = it & 1;
        if (it + 1 < Cc/32) loadregs(it + 1);
#pragma unroll
        for (int ch = 0; ch < 2; ch++) {
            uint32_t a[2][4];
#pragma unroll
            for (int mt = 0; mt < 2; mt++) {
                int r0 = wm + mt*16 + g, r1 = r0 + 8;
                a[mt][0] = Ahs[cur][r0*AST + ch*8 + q];
                a[mt][1] = Ahs[cur][r1*AST + ch*8 + q];
                a[mt][2] = Ahs[cur][r0*AST + ch*8 + q + 4];
                a[mt][3] = Ahs[cur][r1*AST + ch*8 + q + 4];
            }
#pragma unroll
            for (int nt = 0; nt < 4; nt++) {
                int nr = wn + nt*8 + g;
                uint32_t bh0 = Whs[cur][nr*AST + ch*8 + q];
                uint32_t bh1 = Whs[cur][nr*AST + ch*8 + q + 4];
                uint32_t bl0 = Wls[cur][nr*AST + ch*8 + q];
                uint32_t bl1 = Wls[cur][nr*AST + ch*8 + q + 4];
                mma_f16(c[0][nt], a[0], bh0, bh1);
                mma_f16(c[1][nt], a[1], bh0, bh1);
                mma_f16(c[0][nt], a[0], bl0, bl1);
                mma_f16(c[1][nt], a[1], bl0, bl1);
            }
        }
        if (it + 1 < Cc/32) stage(1 - cur);
        __syncthreads();
    }

#pragma unroll
    for (int mt = 0; mt < 2; mt++) {
#pragma unroll
        for (int nt = 0; nt < 4; nt++) {
            int n = n0 + wn + nt*8 + q*2;
            float b0 = bias[n], b1 = bias[n+1];
#pragma unroll
            for (int half = 0; half < 2; half++) {
                int m = m0 + wm + mt*16 + g + half*8;
                float v0 = c[mt][nt][half*2]   + b0;
                float v1 = c[mt][nt][half*2+1] + b1;
                if constexpr (IS_QKV) {
                    int bb = m >> 11;
                    int nnr = m & (Nn - 1);
                    int which = n >> 8;
                    int h = (n >> 6) & (Hh - 1);
                    int d = n & (Dd - 1);
                    float* dst = (which == 0) ? g_Q : ((which == 1) ? g_K : g_V);
                    *(float2*)&dst[((size_t)(bb*Hh + h) * Nn + nnr) * Dd + d] = make_float2(v0, v1);
                } else {
                    *(float2*)&Out[(size_t)m * Cc + n] = make_float2(v0, v1);
                }
            }
        }
    }
}

// ---------------------------------------------------------------------------
// Flash attention: mma.sync.m16n8k16.f16, online exact row-max (guarded
// rescale), PING-PONG K/V buffers, one sync per kv tile.
// ---------------------------------------------------------------------------
__global__ __launch_bounds__(256, 2)
void flash_mma_kernel(const float* __restrict__ Pg) {
    __shared__ uint32_t smbuf[2][4096];   // per buf: Kf [0,2048), Vf [2048,4096)
    __shared__ float pj4[2][256];
    uint32_t* Qh = &smbuf[0][0];          // 128*33=4224 u32, spans both bufs; consumed pre-loop

    int tid = threadIdx.x;
    int w = tid >> 5, t = tid & 31;
    int g = t >> 2, q = t & 3;
    int b = blockIdx.z, h = blockIdx.y;
    int i0 = blockIdx.x * 128;

    const float* Qg = g_Q + (size_t)(b*Hh + h) * Nn * Dd;
    const float* Kg = g_K + (size_t)(b*Hh + h) * Nn * Dd;
    const float* Vg = g_V + (size_t)(b*Hh + h) * Nn * Dd;

    // staging constants
    int row4 = tid >> 2;           // 0..63 : j row
    int c4 = tid & 3;
    int dh = c4 * 16;
    int jodd = row4 & 1;
    int q_j = (row4 >> 1) & 3;
    int b_j = (row4 >> 3) & 1;
    int pi_j = row4 >> 4;
    int kni = row4 >> 3, kg = row4 & 7;

    auto stage_tile = [&](int j0, int bufi) {
        uint32_t* Kf = &smbuf[bufi][0];
        uint32_t* Vf = &smbuf[bufi][2048];
        {
            const float* src = Kg + (size_t)(j0 + row4) * Dd + c4*16;
#pragma unroll
            for (int i8 = 0; i8 < 4; i8++) {
                float4 v = *(const float4*)(src + i8*4);
                int b2 = i8 >> 1, q0 = (i8*2) & 3;
                int addr = kni*256 + c4*64 + b2*32 + kg*4 + q0;
                *(uint2*)&Kf[addr] = make_uint2(h2u(v.x, v.y), h2u(v.z, v.w));
            }
        }
        {
            const float* src = Vg + (size_t)(j0 + row4) * Dd + dh;
            float v[16];
#pragma unroll
            for (int i8 = 0; i8 < 4; i8++)
                *(float4*)&v[i8*4] = *(const float4*)(src + i8*4);
#pragma unroll
            for (int i = 0; i < 8; i++) {
                float send = jodd ? v[i] : v[8 + i];
                float recv = __shfl_xor_sync(0xffffffffu, send, 4);
                int d = dh + (jodd ? 8 : 0) + i;
                uint32_t h2 = jodd ? h2u(recv, v[8 + i]) : h2u(v[i], recv);
                Vf[pi_j*512 + (d >> 3)*64 + b_j*32 + (d & 7)*4 + q_j] = h2;
            }
        }
        if (tid < 64) {
            const float* pp = Pg + (size_t)(j0 + tid) * 3;
            *(float4*)&pj4[bufi][tid*4] = make_float4(pp[0], pp[1], pp[2], 0.f);
        }
    };

    // ---- stage Q (half2), pull A-fragments ----
    {
        int row = tid >> 1, dh2 = (tid & 1) * 16;
        const float* src = Qg + (size_t)(i0 + row) * Dd + dh2*2;
#pragma unroll
        for (int i8 = 0; i8 < 8; i8++) {
            float4 v = *(const float4*)(src + i8*4);
            int col = dh2 + i8*2;
            Qh[row*33 + col]     = h2u(v.x, v.y);
            Qh[row*33 + col + 1] = h2u(v.z, v.w);
        }
    }
    __syncthreads();

    int r0 = w*16 + g, r1 = r0 + 8;
    uint32_t aQ[4][4];
#pragma unroll
    for (int c = 0; c < 4; c++) {
        aQ[c][0] = Qh[r0*33 + 8*c + q];
        aQ[c][1] = Qh[r1*33 + 8*c + q];
        aQ[c][2] = Qh[r0*33 + 8*c + q + 4];
        aQ[c][3] = Qh[r1*33 + 8*c + q + 4];
    }
    float4 rpl0 = *(const float4*)&g_RP[((size_t)b*Nn + i0 + r0) * 4];
    float4 rpl1 = *(const float4*)&g_RP[((size_t)b*Nn + i0 + r1) * 4];
    __syncthreads();   // aQ reads done before tile-0 staging overwrites Qh region

    stage_tile(0, 0);
    __syncthreads();

    float o[8][4];
#pragma unroll
    for (int n = 0; n < 8; n++)
#pragma unroll
        for (int c = 0; c < 4; c++) o[n][c] = 0.f;
    float lsum0 = 0.f, lsum1 = 0.f;
    float m0 = -1e30f, m1 = -1e30f;

    for (int tt = 0; tt < Nn / 64; tt++) {
        int cur = tt & 1;
        uint32_t* Kf = &smbuf[cur][0];
        uint32_t* Vf = &smbuf[cur][2048];
        const float* pj = pj4[cur];

        // ---- GEMM1: 8 ni tiles into registers (log2-domain logits) ----
        float s[8][4];
#pragma unroll
        for (int ni = 0; ni < 8; ni++) {
            float cA[4] = {0.f,0.f,0.f,0.f}, cB[4] = {0.f,0.f,0.f,0.f};
            int kbase = ni*256 + g*4 + q;
            mma_f16(cA, aQ[0], Kf[kbase +   0], Kf[kbase +  32]);
            mma_f16(cB, aQ[1], Kf[kbase +  64], Kf[kbase +  96]);
            mma_f16(cA, aQ[2], Kf[kbase + 128], Kf[kbase + 160]);
            mma_f16(cB, aQ[3], Kf[kbase + 192], Kf[kbase + 224]);

            int clo = ni*8 + q*2;
            float4 plo = *(const float4*)&pj[clo*4];
            float4 phi = *(const float4*)&pj[(clo+1)*4];
            s[ni][0] = fmaf(cA[0] + cB[0], K1EXP, rpl0.x*plo.x + rpl0.y*plo.y + rpl0.z*plo.z);
            s[ni][1] = fmaf(cA[1] + cB[1], K1EXP, rpl0.x*phi.x + rpl0.y*phi.y + rpl0.z*phi.z);
            s[ni][2] = fmaf(cA[2] + cB[2], K1EXP, rpl1.x*plo.x + rpl1.y*plo.y + rpl1.z*plo.z);
            s[ni][3] = fmaf(cA[3] + cB[3], K1EXP, rpl1.x*phi.x + rpl1.y*phi.y + rpl1.z*phi.z);
        }

        // ---- exact tile max (quad reduce), guarded online rescale ----
        float mt0 = fmaxf(s[0][0], s[0][1]), mt1 = fmaxf(s[0][2], s[0][3]);
#pragma unroll
        for (int ni = 1; ni < 8; ni++) {
            mt0 = fmaxf(mt0, fmaxf(s[ni][0], s[ni][1]));
            mt1 = fmaxf(mt1, fmaxf(s[ni][2], s[ni][3]));
        }
        mt0 = fmaxf(mt0, __shfl_xor_sync(0xffffffffu, mt0, 1));
        mt0 = fmaxf(mt0, __shfl_xor_sync(0xffffffffu, mt0, 2));
        mt1 = fmaxf(mt1, __shfl_xor_sync(0xffffffffu, mt1, 1));
        mt1 = fmaxf(mt1, __shfl_xor_sync(0xffffffffu, mt1, 2));
        if (mt0 > m0 || mt1 > m1) {          // bit-exact: skipped iff alphas == 1.0
            float mn0 = fmaxf(m0, mt0), mn1 = fmaxf(m1, mt1);
            float al0 = ex2f(m0 - mn0), al1 = ex2f(m1 - mn1);
            m0 = mn0; m1 = mn1;
            lsum0 *= al0; lsum1 *= al1;
#pragma unroll
            for (int n = 0; n < 8; n++) {
                o[n][0] *= al0; o[n][1] *= al0;
                o[n][2] *= al1; o[n][3] *= al1;
            }
        }

        // ---- exp (P in [2^-14, 2^8], all normal fp16) ----
        float sh0 = 8.0f - m0, sh1 = 8.0f - m1;
#pragma unroll
        for (int ni = 0; ni < 8; ni++) {
            float e0 = ex2f(s[ni][0] + sh0);
            float e1 = ex2f(s[ni][1] + sh0);
            float e2 = ex2f(s[ni][2] + sh1);
            float e3 = ex2f(s[ni][3] + sh1);
            lsum0 += e0 + e1;
            lsum1 += e2 + e3;
            s[ni][0] = e0; s[ni][1] = e1; s[ni][2] = e2; s[ni][3] = e3;
        }

        // ---- PV: 4 k16 tiles ----
#pragma unroll
        for (int pi = 0; pi < 4; pi++) {
            uint32_t aP[4];
            aP[0] = h2u(s[2*pi][0],   s[2*pi][1]);
            aP[1] = h2u(s[2*pi][2],   s[2*pi][3]);
            aP[2] = h2u(s[2*pi+1][0], s[2*pi+1][1]);
            aP[3] = h2u(s[2*pi+1][2], s[2*pi+1][3]);
            int vbase = pi*512 + g*4 + q;
#pragma unroll
            for (int n = 0; n < 8; n++) {
                uint32_t vb0 = Vf[vbase + n*64];
                uint32_t vb1 = Vf[vbase + n*64 + 32];
                mma_f16(o[n], aP, vb0, vb1);
            }
        }

        // ---- stage next tile into the other buffer, one sync ----
        if (tt + 1 < Nn / 64) stage_tile((tt + 1) * 64, 1 - cur);
        __syncthreads();
    }

    lsum0 += __shfl_xor_sync(0xffffffffu, lsum0, 1);
    lsum0 += __shfl_xor_sync(0xffffffffu, lsum0, 2);
    lsum1 += __shfl_xor_sync(0xffffffffu, lsum1, 1);
    lsum1 += __shfl_xor_sync(0xffffffffu, lsum1, 2);
    float inv0 = 1.f / lsum0, inv1 = 1.f / lsum1;

    float* dst0 = g_AO + ((size_t)b*Nn + i0 + r0) * Cc + h*Dd;
    float* dst1 = g_AO + ((size_t)b*Nn + i0 + r1) * Cc + h*Dd;
#pragma unroll
    for (int n = 0; n < 8; n++) {
        int col = n*8 + q*2;
        *(float2*)(dst0 + col) = make_float2(o[n][0]*inv0, o[n][1]*inv0);
        *(float2*)(dst1 + col) = make_float2(o[n][2]*inv1, o[n][3]*inv1);
    }
}

// ---------------------------------------------------------------------------
extern "C" void kernel_launch(void* const* d_in, const int* in_sizes, int n_in,
                              void* d_out, int out_size) {
    const float* x         = (const float*)d_in[0];
    const float* R         = (const float*)d_in[1];
    const float* P         = (const float*)d_in[2];
    const float* qkv_w     = (const float*)d_in[3];
    const float* qkv_b     = (const float*)d_in[4];
    const float* proj_w    = (const float*)d_in[5];
    const float* proj_b    = (const float*)d_in[6];
    const float* pos_scale = (const float*)d_in[7];
    float* out = (float*)d_out;

    rp_kernel<<<(Bb*Nn + 255) / 256, 256>>>(R, P, pos_scale);
    gemm_f16_kernel<true><<<dim3(768/64, (Bb*Nn)/128), 256>>>(x, qkv_w, qkv_b, nullptr);
    flash_mma_kernel<<<dim3(Nn/128, Hh, Bb), 256>>>(P);
    gemm_f16_kernel<false><<<dim3(Cc/64, (Bb*Nn)/128), 256>>>(nullptr, proj_w, proj_b, out);
}

// round 16
// speedup vs baseline: 3.4176x; 1.0966x over previous
#include <cuda_runtime.h>
#include <cuda_fp16.h>
#include <cstdint>
#include <math.h>

#define Bb 4
#define Nn 2048
#define Cc 256
#define Hh 4
#define Dd 64
#define K1EXP 0.18033688011112042f   // 0.125 * log2(e)
#define LOG2E 1.4426950408889634f

// ===================== helpers =====================
__device__ __forceinline__ float ex2f(float x) {
    float y; asm("ex2.approx.f32 %0,%1;" : "=f"(y) : "f"(x)); return y;
}
__device__ __forceinline__ void mma_f16(float c[4], const uint32_t a[4],
                                        uint32_t b0, uint32_t b1) {
    asm volatile("mma.sync.aligned.m16n8k16.row.col.f32.f16.f16.f32 "
        "{%0,%1,%2,%3}, {%4,%5,%6,%7}, {%8,%9}, {%0,%1,%2,%3};"
        : "+f"(c[0]), "+f"(c[1]), "+f"(c[2]), "+f"(c[3])
        : "r"(a[0]), "r"(a[1]), "r"(a[2]), "r"(a[3]), "r"(b0), "r"(b1));
}
__device__ __forceinline__ uint32_t h2u(float a, float b) {
    __half2 h = __floats2half2_rn(a, b);
    return *reinterpret_cast<uint32_t*>(&h);
}
__device__ __forceinline__ uint32_t packh(__half a, __half b) {
    return (uint32_t)__half_as_ushort(a) | ((uint32_t)__half_as_ushort(b) << 16);
}

// ===================== scratch =====================
__device__ __align__(16) float g_Q[Bb*Hh*Nn*Dd];
__device__ __align__(16) float g_K[Bb*Hh*Nn*Dd];
__device__ __align__(16) float g_V[Bb*Hh*Nn*Dd];
__device__ __align__(16) float g_RP[Bb*Nn*4];    // rp * pos_scale * log2(e)
__device__ __align__(16) float g_AO[Bb*Nn*Cc];

// ---------------------------------------------------------------------------
__global__ void rp_kernel(const float* __restrict__ R, const float* __restrict__ P,
                          const float* __restrict__ pos_scale) {
    int idx = blockIdx.x * blockDim.x + threadIdx.x;
    if (idx >= Bb * Nn) return;
    int b = idx / Nn, j = idx % Nn;
    float p0 = P[j*3+0], p1 = P[j*3+1], p2 = P[j*3+2];
    float ps = *pos_scale * LOG2E;
    const float* Rb = R + b*9;
#pragma unroll
    for (int c = 0; c < 3; c++)
        g_RP[idx*4 + c] = ps * (Rb[c*3+0]*p0 + Rb[c*3+1]*p1 + Rb[c*3+2]*p2);
    g_RP[idx*4 + 3] = 0.f;
}

// ---------------------------------------------------------------------------
// fp16 k16 NT GEMM, ping-pong. TWOPASS: hi/lo W split; else single-pass W.
// ---------------------------------------------------------------------------
#define AST 17   // uint32 (half2) stride per row

template<bool IS_QKV, bool TWOPASS>
__global__ __launch_bounds__(256)
void gemm_f16_kernel(const float* __restrict__ A, const float* __restrict__ W,
                     const float* __restrict__ bias, float* __restrict__ Out) {
    __shared__ uint32_t Ahs[2][128*AST];
    __shared__ uint32_t Whs[2][64*AST];
    __shared__ uint32_t Wls[TWOPASS ? 2 : 1][TWOPASS ? 64*AST : 1];

    const float* Ap;
    if constexpr (IS_QKV) Ap = A; else Ap = g_AO;

    int tid = threadIdx.x;
    int w = tid >> 5, lane = tid & 31, g = lane >> 2, q = lane & 3;
    int wm = (w & 3) * 32, wn = (w >> 2) * 32;
    int m0 = blockIdx.y * 128, n0 = blockIdx.x * 64;

    int ar = tid >> 1, ak = (tid & 1) * 16;
    int wr = tid >> 2, wk = (tid & 3) * 8;

    const float* Abase = Ap + (size_t)(m0 + ar) * Cc + ak;
    const float* Wbase = W  + (size_t)(n0 + wr) * Cc + wk;

    float4 sa[4], sw[2];

    auto loadregs = [&](int it) {
#pragma unroll
        for (int i = 0; i < 4; i++) sa[i] = *(const float4*)(Abase + it*32 + i*4);
#pragma unroll
        for (int i = 0; i < 2; i++) sw[i] = *(const float4*)(Wbase + it*32 + i*4);
    };
    auto stage = [&](int bufi) {
        int abase = ar*AST + (ak >> 1);
#pragma unroll
        for (int i = 0; i < 4; i++) {
            Ahs[bufi][abase + i*2]     = h2u(sa[i].x, sa[i].y);
            Ahs[bufi][abase + i*2 + 1] = h2u(sa[i].z, sa[i].w);
        }
        int wbase = wr*AST + (wk >> 1);
#pragma unroll
        for (int i = 0; i < 2; i++) {
            __half hx = __float2half_rn(sw[i].x), hy = __float2half_rn(sw[i].y);
            __half hz = __float2half_rn(sw[i].z), hw = __float2half_rn(sw[i].w);
            Whs[bufi][wbase + i*2]     = packh(hx, hy);
            Whs[bufi][wbase + i*2 + 1] = packh(hz, hw);
            if constexpr (TWOPASS) {
                Wls[bufi][wbase + i*2]     = h2u(sw[i].x - __half2float(hx), sw[i].y - __half2float(hy));
                Wls[bufi][wbase + i*2 + 1] = h2u(sw[i].z - __half2float(hz), sw[i].w - __half2float(hw));
            }
        }
    };

    float c[2][4][4];
#pragma unroll
    for (int mt = 0; mt < 2; mt++)
#pragma unroll
        for (int nt = 0; nt < 4; nt++)
#pragma unroll
            for (int i = 0; i < 4; i++) c[mt][nt][i] = 0.f;

    loadregs(0);
    stage(0);
    __syncthreads();

    for (int it = 0; it < Cc/32; it++) {
        int cur = it & 1;
        if (it + 1 < Cc/32) loadregs(it + 1);
#pragma unroll
        for (int ch = 0; ch < 2; ch++) {
            uint32_t a[2][4];
#pragma unroll
            for (int mt = 0; mt < 2; mt++) {
                int r0 = wm + mt*16 + g, r1 = r0 + 8;
                a[mt][0] = Ahs[cur][r0*AST + ch*8 + q];
                a[mt][1] = Ahs[cur][r1*AST + ch*8 + q];
                a[mt][2] = Ahs[cur][r0*AST + ch*8 + q + 4];
                a[mt][3] = Ahs[cur][r1*AST + ch*8 + q + 4];
            }
#pragma unroll
            for (int nt = 0; nt < 4; nt++) {
                int nr = wn + nt*8 + g;
                uint32_t bh0 = Whs[cur][nr*AST + ch*8 + q];
                uint32_t bh1 = Whs[cur][nr*AST + ch*8 + q + 4];
                mma_f16(c[0][nt], a[0], bh0, bh1);
                mma_f16(c[1][nt], a[1], bh0, bh1);
                if constexpr (TWOPASS) {
                    uint32_t bl0 = Wls[cur][nr*AST + ch*8 + q];
                    uint32_t bl1 = Wls[cur][nr*AST + ch*8 + q + 4];
                    mma_f16(c[0][nt], a[0], bl0, bl1);
                    mma_f16(c[1][nt], a[1], bl0, bl1);
                }
            }
        }
        if (it + 1 < Cc/32) stage(1 - cur);
        __syncthreads();
    }

#pragma unroll
    for (int mt = 0; mt < 2; mt++) {
#pragma unroll
        for (int nt = 0; nt < 4; nt++) {
            int n = n0 + wn + nt*8 + q*2;
            float b0 = bias[n], b1 = bias[n+1];
#pragma unroll
            for (int half = 0; half < 2; half++) {
                int m = m0 + wm + mt*16 + g + half*8;
                float v0 = c[mt][nt][half*2]   + b0;
                float v1 = c[mt][nt][half*2+1] + b1;
                if constexpr (IS_QKV) {
                    int bb = m >> 11;
                    int nnr = m & (Nn - 1);
                    int which = n >> 8;
                    int h = (n >> 6) & (Hh - 1);
                    int d = n & (Dd - 1);
                    float* dst = (which == 0) ? g_Q : ((which == 1) ? g_K : g_V);
                    *(float2*)&dst[((size_t)(bb*Hh + h) * Nn + nnr) * Dd + d] = make_float2(v0, v1);
                } else {
                    *(float2*)&Out[(size_t)m * Cc + n] = make_float2(v0, v1);
                }
            }
        }
    }
}

// ---------------------------------------------------------------------------
// Flash attention: bias folded into GEMM1 via 5th k16 chunk (fp16 hi/lo
// split of rpl and p; exact to fp32-accum level). Q pre-scaled by K1EXP so
// mma output = log2-domain logits. Online exact row-max, ping-pong buffers.
// K chunk stride 320 u32 per ni (5 chunks); Vf at +2560; buffer 4608 u32.
// ---------------------------------------------------------------------------
__global__ __launch_bounds__(256, 2)
void flash_mma_kernel(const float* __restrict__ Pg) {
    __shared__ uint32_t smbuf[2][4608];   // per buf: Kf [0,2560), Vf [2560,4608)
    uint32_t* Qh = &smbuf[0][0];          // 128 rows x 41 half2 = 5248 u32, spans both bufs

    int tid = threadIdx.x;
    int w = tid >> 5, t = tid & 31;
    int g = t >> 2, q = t & 3;
    int b = blockIdx.z, h = blockIdx.y;
    int i0 = blockIdx.x * 128;

    const float* Qg = g_Q + (size_t)(b*Hh + h) * Nn * Dd;
    const float* Kg = g_K + (size_t)(b*Hh + h) * Nn * Dd;
    const float* Vg = g_V + (size_t)(b*Hh + h) * Nn * Dd;

    // staging constants
    int row4 = tid >> 2;           // 0..63 : j row
    int c4 = tid & 3;
    int dh = c4 * 16;
    int jodd = row4 & 1;
    int q_j = (row4 >> 1) & 3;
    int b_j = (row4 >> 3) & 1;
    int pi_j = row4 >> 4;
    int kni = row4 >> 3, kg = row4 & 7;

    auto stage_tile = [&](int j0, int bufi) {
        uint32_t* Kf = &smbuf[bufi][0];
        uint32_t* Vf = &smbuf[bufi][2560];
        {   // K main chunks (raw, unscaled)
            const float* src = Kg + (size_t)(j0 + row4) * Dd + c4*16;
#pragma unroll
            for (int i8 = 0; i8 < 4; i8++) {
                float4 v = *(const float4*)(src + i8*4);
                int b2 = i8 >> 1, q0 = (i8*2) & 3;
                int addr = kni*320 + c4*64 + b2*32 + kg*4 + q0;
                *(uint2*)&Kf[addr] = make_uint2(h2u(v.x, v.y), h2u(v.z, v.w));
            }
        }
        if (c4 == 0) {   // K extension chunk: [ph0,ph1,ph2, ph0,ph1,ph2, pl0,pl1,pl2, 0..]
            const float* pp = Pg + (size_t)(j0 + row4) * 3;
            float p0 = pp[0], p1 = pp[1], p2 = pp[2];
            __half H0 = __float2half_rn(p0), H1 = __float2half_rn(p1), H2 = __float2half_rn(p2);
            uint32_t colv[8];
            colv[0] = packh(H0, H1);
            colv[1] = packh(H2, H0);
            colv[2] = packh(H1, H2);
            colv[3] = h2u(p0 - __half2float(H0), p1 - __half2float(H1));
            colv[4] = h2u(p2 - __half2float(H2), 0.f);
            colv[5] = 0; colv[6] = 0; colv[7] = 0;
#pragma unroll
            for (int cc = 0; cc < 8; cc++) {
                int addr = kni*320 + 256 + ((cc >> 2) & 1)*32 + kg*4 + (cc & 3);
                Kf[addr] = colv[cc];
            }
        }
        {   // V transposed to half2-along-j
            const float* src = Vg + (size_t)(j0 + row4) * Dd + dh;
            float v[16];
#pragma unroll
            for (int i8 = 0; i8 < 4; i8++)
                *(float4*)&v[i8*4] = *(const float4*)(src + i8*4);
#pragma unroll
            for (int i = 0; i < 8; i++) {
                float send = jodd ? v[i] : v[8 + i];
                float recv = __shfl_xor_sync(0xffffffffu, send, 4);
                int d = dh + (jodd ? 8 : 0) + i;
                uint32_t h2 = jodd ? h2u(recv, v[8 + i]) : h2u(v[i], recv);
                Vf[pi_j*512 + (d >> 3)*64 + b_j*32 + (d & 7)*4 + q_j] = h2;
            }
        }
    };

    // ---- stage Q: cols 0..31 = q*K1EXP (half2); cols 32..39 = rpl ext ----
    {
        int row = tid >> 1, dh2 = (tid & 1) * 16;
        const float* src = Qg + (size_t)(i0 + row) * Dd + dh2*2;
#pragma unroll
        for (int i8 = 0; i8 < 8; i8++) {
            float4 v = *(const float4*)(src + i8*4);
            int col = dh2 + i8*2;
            Qh[row*41 + col]     = h2u(v.x*K1EXP, v.y*K1EXP);
            Qh[row*41 + col + 1] = h2u(v.z*K1EXP, v.w*K1EXP);
        }
        if (tid & 1) {   // ext: [rh0,rh1,rh2, rl0,rl1,rl2, rh0,rh1,rh2, 0..]
            float4 r4 = *(const float4*)&g_RP[((size_t)b*Nn + i0 + row) * 4];
            __half H0 = __float2half_rn(r4.x), H1 = __float2half_rn(r4.y), H2 = __float2half_rn(r4.z);
            float l0 = r4.x - __half2float(H0);
            float l1 = r4.y - __half2float(H1);
            float l2 = r4.z - __half2float(H2);
            Qh[row*41 + 32] = packh(H0, H1);
            Qh[row*41 + 33] = (uint32_t)__half_as_ushort(H2) | ((uint32_t)(h2u(l0, 0.f) & 0xffffu) << 16);
            Qh[row*41 + 34] = h2u(l1, l2);
            Qh[row*41 + 35] = packh(H0, H1);
            Qh[row*41 + 36] = packh(H2, __float2half_rn(0.f));
            Qh[row*41 + 37] = 0; Qh[row*41 + 38] = 0; Qh[row*41 + 39] = 0;
        }
    }
    __syncthreads();

    int r0 = w*16 + g, r1 = r0 + 8;
    uint32_t aQ[5][4];
#pragma unroll
    for (int c = 0; c < 5; c++) {
        aQ[c][0] = Qh[r0*41 + 8*c + q];
        aQ[c][1] = Qh[r1*41 + 8*c + q];
        aQ[c][2] = Qh[r0*41 + 8*c + q + 4];
        aQ[c][3] = Qh[r1*41 + 8*c + q + 4];
    }
    __syncthreads();   // aQ reads done before tile-0 staging overwrites Qh

    stage_tile(0, 0);
    __syncthreads();

    float o[8][4];
#pragma unroll
    for (int n = 0; n < 8; n++)
#pragma unroll
        for (int c = 0; c < 4; c++) o[n][c] = 0.f;
    float lsum0 = 0.f, lsum1 = 0.f;
    float m0 = -1e30f, m1 = -1e30f;

    for (int tt = 0; tt < Nn / 64; tt++) {
        int cur = tt & 1;
        uint32_t* Kf = &smbuf[cur][0];
        uint32_t* Vf = &smbuf[cur][2560];

        // ---- GEMM1: logits (log2 domain) straight from mma ----
        float s[8][4];
#pragma unroll
        for (int ni = 0; ni < 8; ni++) {
            float cA[4] = {0.f,0.f,0.f,0.f}, cB[4] = {0.f,0.f,0.f,0.f};
            int kbase = ni*320 + g*4 + q;
            mma_f16(cA, aQ[0], Kf[kbase +   0], Kf[kbase +  32]);
            mma_f16(cB, aQ[1], Kf[kbase +  64], Kf[kbase +  96]);
            mma_f16(cA, aQ[2], Kf[kbase + 128], Kf[kbase + 160]);
            mma_f16(cB, aQ[3], Kf[kbase + 192], Kf[kbase + 224]);
            mma_f16(cA, aQ[4], Kf[kbase + 256], Kf[kbase + 288]);
            s[ni][0] = cA[0] + cB[0];
            s[ni][1] = cA[1] + cB[1];
            s[ni][2] = cA[2] + cB[2];
            s[ni][3] = cA[3] + cB[3];
        }

        // ---- exact tile max (quad reduce), guarded online rescale ----
        float mt0 = fmaxf(s[0][0], s[0][1]), mt1 = fmaxf(s[0][2], s[0][3]);
#pragma unroll
        for (int ni = 1; ni < 8; ni++) {
            mt0 = fmaxf(mt0, fmaxf(s[ni][0], s[ni][1]));
            mt1 = fmaxf(mt1, fmaxf(s[ni][2], s[ni][3]));
        }
        mt0 = fmaxf(mt0, __shfl_xor_sync(0xffffffffu, mt0, 1));
        mt0 = fmaxf(mt0, __shfl_xor_sync(0xffffffffu, mt0, 2));
        mt1 = fmaxf(mt1, __shfl_xor_sync(0xffffffffu, mt1, 1));
        mt1 = fmaxf(mt1, __shfl_xor_sync(0xffffffffu, mt1, 2));
        if (mt0 > m0 || mt1 > m1) {
            float mn0 = fmaxf(m0, mt0), mn1 = fmaxf(m1, mt1);
            float al0 = ex2f(m0 - mn0), al1 = ex2f(m1 - mn1);
            m0 = mn0; m1 = mn1;
            lsum0 *= al0; lsum1 *= al1;
#pragma unroll
            for (int n = 0; n < 8; n++) {
                o[n][0] *= al0; o[n][1] *= al0;
                o[n][2] *= al1; o[n][3] *= al1;
            }
        }

        // ---- exp (P in [2^-14, 2^8], all normal fp16) ----
        float sh0 = 8.0f - m0, sh1 = 8.0f - m1;
#pragma unroll
        for (int ni = 0; ni < 8; ni++) {
            float e0 = ex2f(s[ni][0] + sh0);
            float e1 = ex2f(s[ni][1] + sh0);
            float e2 = ex2f(s[ni][2] + sh1);
            float e3 = ex2f(s[ni][3] + sh1);
            lsum0 += e0 + e1;
            lsum1 += e2 + e3;
            s[ni][0] = e0; s[ni][1] = e1; s[ni][2] = e2; s[ni][3] = e3;
        }

        // ---- PV: 4 k16 tiles ----
#pragma unroll
        for (int pi = 0; pi < 4; pi++) {
            uint32_t aP[4];
            aP[0] = h2u(s[2*pi][0],   s[2*pi][1]);
            aP[1] = h2u(s[2*pi][2],   s[2*pi][3]);
            aP[2] = h2u(s[2*pi+1][0], s[2*pi+1][1]);
            aP[3] = h2u(s[2*pi+1][2], s[2*pi+1][3]);
            int vbase = pi*512 + g*4 + q;
#pragma unroll
            for (int n = 0; n < 8; n++) {
                uint32_t vb0 = Vf[vbase + n*64];
                uint32_t vb1 = Vf[vbase + n*64 + 32];
                mma_f16(o[n], aP, vb0, vb1);
            }
        }

        if (tt + 1 < Nn / 64) stage_tile((tt + 1) * 64, 1 - cur);
        __syncthreads();
    }

    lsum0 += __shfl_xor_sync(0xffffffffu, lsum0, 1);
    lsum0 += __shfl_xor_sync(0xffffffffu, lsum0, 2);
    lsum1 += __shfl_xor_sync(0xffffffffu, lsum1, 1);
    lsum1 += __shfl_xor_sync(0xffffffffu, lsum1, 2);
    float inv0 = 1.f / lsum0, inv1 = 1.f / lsum1;

    float* dst0 = g_AO + ((size_t)b*Nn + i0 + r0) * Cc + h*Dd;
    float* dst1 = g_AO + ((size_t)b*Nn + i0 + r1) * Cc + h*Dd;
#pragma unroll
    for (int n = 0; n < 8; n++) {
        int col = n*8 + q*2;
        *(float2*)(dst0 + col) = make_float2(o[n][0]*inv0, o[n][1]*inv0);
        *(float2*)(dst1 + col) = make_float2(o[n][2]*inv1, o[n][3]*inv1);
    }
}

// ---------------------------------------------------------------------------
extern "C" void kernel_launch(void* const* d_in, const int* in_sizes, int n_in,
                              void* d_out, int out_size) {
    const float* x         = (const float*)d_in[0];
    const float* R         = (const float*)d_in[1];
    const float* P         = (const float*)d_in[2];
    const float* qkv_w     = (const float*)d_in[3];
    const float* qkv_b     = (const float*)d_in[4];
    const float* proj_w    = (const float*)d_in[5];
    const float* proj_b    = (const float*)d_in[6];
    const float* pos_scale = (const float*)d_in[7];
    float* out = (float*)d_out;

    rp_kernel<<<(Bb*Nn + 255) / 256, 256>>>(R, P, pos_scale);
    gemm_f16_kernel<true, false><<<dim3(768/64, (Bb*Nn)/128), 256>>>(x, qkv_w, qkv_b, nullptr);
    flash_mma_kernel<<<dim3(Nn/128, Hh, Bb), 256>>>(P);
    gemm_f16_kernel<false, true><<<dim3(Cc/64, (Bb*Nn)/128), 256>>>(nullptr, proj_w, proj_b, out);
}

// round 17
// speedup vs baseline: 4.6096x; 1.3488x over previous
#include <cuda_runtime.h>
#include <cuda_fp16.h>
#include <cstdint>
#include <math.h>

#define Bb 4
#define Nn 2048
#define Cc 256
#define Hh 4
#define Dd 64
#define K1EXP 0.18033688011112042f   // 0.125 * log2(e)
#define LOG2E 1.4426950408889634f

// ===================== helpers =====================
__device__ __forceinline__ float ex2f(float x) {
    float y; asm("ex2.approx.f32 %0,%1;" : "=f"(y) : "f"(x)); return y;
}
__device__ __forceinline__ void mma_f16(float c[4], const uint32_t a[4],
                                        uint32_t b0, uint32_t b1) {
    asm volatile("mma.sync.aligned.m16n8k16.row.col.f32.f16.f16.f32 "
        "{%0,%1,%2,%3}, {%4,%5,%6,%7}, {%8,%9}, {%0,%1,%2,%3};"
        : "+f"(c[0]), "+f"(c[1]), "+f"(c[2]), "+f"(c[3])
        : "r"(a[0]), "r"(a[1]), "r"(a[2]), "r"(a[3]), "r"(b0), "r"(b1));
}
__device__ __forceinline__ uint32_t h2u(float a, float b) {
    __half2 h = __floats2half2_rn(a, b);
    return *reinterpret_cast<uint32_t*>(&h);
}
__device__ __forceinline__ uint32_t packh(__half a, __half b) {
    return (uint32_t)__half_as_ushort(a) | ((uint32_t)__half_as_ushort(b) << 16);
}

// ===================== scratch (fp16 intermediates as u32/half2) ============
__device__ __align__(16) uint32_t g_Qh[Bb*Hh*Nn*32];   // Q * K1EXP, half2
__device__ __align__(16) uint32_t g_Kh[Bb*Hh*Nn*32];
__device__ __align__(16) uint32_t g_Vh[Bb*Hh*Nn*32];
__device__ __align__(16) uint32_t g_AOh[Bb*Nn*128];
__device__ __align__(16) float g_RP[Bb*Nn*4];          // rp * pos_scale * log2e

// ---------------------------------------------------------------------------
__global__ void rp_kernel(const float* __restrict__ R, const float* __restrict__ P,
                          const float* __restrict__ pos_scale) {
    int idx = blockIdx.x * blockDim.x + threadIdx.x;
    if (idx >= Bb * Nn) return;
    int b = idx / Nn, j = idx % Nn;
    float p0 = P[j*3+0], p1 = P[j*3+1], p2 = P[j*3+2];
    float ps = *pos_scale * LOG2E;
    const float* Rb = R + b*9;
#pragma unroll
    for (int c = 0; c < 3; c++)
        g_RP[idx*4 + c] = ps * (Rb[c*3+0]*p0 + Rb[c*3+1]*p1 + Rb[c*3+2]*p2);
    g_RP[idx*4 + 3] = 0.f;
}

// ---------------------------------------------------------------------------
// fp16 k16 NT GEMM, ping-pong. IS_QKV: A=fp32 x, scatter fp16 Q/K/V.
// else: A = fp16 g_AOh, TWOPASS hi/lo W, fp32 Out.
// ---------------------------------------------------------------------------
#define AST 20   // u32 (half2) smem row stride

template<bool IS_QKV, bool TWOPASS>
__global__ __launch_bounds__(256)
void gemm_f16_kernel(const float* __restrict__ A, const float* __restrict__ W,
                     const float* __restrict__ bias, float* __restrict__ Out) {
    __shared__ uint32_t Ahs[2][128*AST];
    __shared__ uint32_t Whs[2][64*AST];
    __shared__ uint32_t Wls[TWOPASS ? 2 : 1][TWOPASS ? 64*AST : 1];

    int tid = threadIdx.x;
    int w = tid >> 5, lane = tid & 31, g = lane >> 2, q = lane & 3;
    int wm = (w & 3) * 32, wn = (w >> 2) * 32;
    int m0 = blockIdx.y * 128, n0 = blockIdx.x * 64;

    int ar = tid >> 1, ah8 = (tid & 1) * 8;   // A: row, half2-offset (8 u32 = 16 halves)
    int wr = tid >> 2, wk = (tid & 3) * 8;

    const float*    Abase_f = A + (size_t)(m0 + ar) * Cc + ah8*2;
    const uint32_t* Abase_h = g_AOh + (size_t)(m0 + ar) * (Cc/2) + ah8;
    const float*    Wbase   = W + (size_t)(n0 + wr) * Cc + wk;

    float4 sa[4]; uint4 ua[2]; float4 sw[2];

    auto loadregs = [&](int it) {
        if constexpr (IS_QKV) {
#pragma unroll
            for (int i = 0; i < 4; i++) sa[i] = *(const float4*)(Abase_f + it*32 + i*4);
        } else {
            ua[0] = *(const uint4*)(Abase_h + it*16);
            ua[1] = *(const uint4*)(Abase_h + it*16 + 4);
        }
#pragma unroll
        for (int i = 0; i < 2; i++) sw[i] = *(const float4*)(Wbase + it*32 + i*4);
    };
    auto stage = [&](int bufi) {
        int abase = ar*AST + ah8;
        if constexpr (IS_QKV) {
#pragma unroll
            for (int i = 0; i < 4; i++) {
                Ahs[bufi][abase + i*2]     = h2u(sa[i].x, sa[i].y);
                Ahs[bufi][abase + i*2 + 1] = h2u(sa[i].z, sa[i].w);
            }
        } else {
            *(uint4*)&Ahs[bufi][abase]     = ua[0];
            *(uint4*)&Ahs[bufi][abase + 4] = ua[1];
        }
        int wbase = wr*AST + (wk >> 1);
#pragma unroll
        for (int i = 0; i < 2; i++) {
            __half hx = __float2half_rn(sw[i].x), hy = __float2half_rn(sw[i].y);
            __half hz = __float2half_rn(sw[i].z), hw = __float2half_rn(sw[i].w);
            Whs[bufi][wbase + i*2]     = packh(hx, hy);
            Whs[bufi][wbase + i*2 + 1] = packh(hz, hw);
            if constexpr (TWOPASS) {
                Wls[bufi][wbase + i*2]     = h2u(sw[i].x - __half2float(hx), sw[i].y - __half2float(hy));
                Wls[bufi][wbase + i*2 + 1] = h2u(sw[i].z - __half2float(hz), sw[i].w - __half2float(hw));
            }
        }
    };

    float c[2][4][4];
#pragma unroll
    for (int mt = 0; mt < 2; mt++)
#pragma unroll
        for (int nt = 0; nt < 4; nt++)
#pragma unroll
            for (int i = 0; i < 4; i++) c[mt][nt][i] = 0.f;

    loadregs(0);
    stage(0);
    __syncthreads();

    for (int it = 0; it < Cc/32; it++) {
        int cur = it & 1;
        if (it + 1 < Cc/32) loadregs(it + 1);
#pragma unroll
        for (int ch = 0; ch < 2; ch++) {
            uint32_t a[2][4];
#pragma unroll
            for (int mt = 0; mt < 2; mt++) {
                int r0 = wm + mt*16 + g, r1 = r0 + 8;
                a[mt][0] = Ahs[cur][r0*AST + ch*8 + q];
                a[mt][1] = Ahs[cur][r1*AST + ch*8 + q];
                a[mt][2] = Ahs[cur][r0*AST + ch*8 + q + 4];
                a[mt][3] = Ahs[cur][r1*AST + ch*8 + q + 4];
            }
#pragma unroll
            for (int nt = 0; nt < 4; nt++) {
                int nr = wn + nt*8 + g;
                uint32_t bh0 = Whs[cur][nr*AST + ch*8 + q];
                uint32_t bh1 = Whs[cur][nr*AST + ch*8 + q + 4];
                mma_f16(c[0][nt], a[0], bh0, bh1);
                mma_f16(c[1][nt], a[1], bh0, bh1);
                if constexpr (TWOPASS) {
                    uint32_t bl0 = Wls[cur][nr*AST + ch*8 + q];
                    uint32_t bl1 = Wls[cur][nr*AST + ch*8 + q + 4];
                    mma_f16(c[0][nt], a[0], bl0, bl1);
                    mma_f16(c[1][nt], a[1], bl0, bl1);
                }
            }
        }
        if (it + 1 < Cc/32) stage(1 - cur);
        __syncthreads();
    }

#pragma unroll
    for (int mt = 0; mt < 2; mt++) {
#pragma unroll
        for (int nt = 0; nt < 4; nt++) {
            int n = n0 + wn + nt*8 + q*2;
            float b0 = bias[n], b1 = bias[n+1];
#pragma unroll
            for (int half = 0; half < 2; half++) {
                int m = m0 + wm + mt*16 + g + half*8;
                float v0 = c[mt][nt][half*2]   + b0;
                float v1 = c[mt][nt][half*2+1] + b1;
                if constexpr (IS_QKV) {
                    int bb = m >> 11;
                    int nnr = m & (Nn - 1);
                    int which = n >> 8;
                    int h = (n >> 6) & (Hh - 1);
                    int d = n & (Dd - 1);
                    float s = (which == 0) ? K1EXP : 1.0f;
                    uint32_t* dst = (which == 0) ? g_Qh : ((which == 1) ? g_Kh : g_Vh);
                    dst[((size_t)(bb*Hh + h) * Nn + nnr) * 32 + (d >> 1)] = h2u(v0*s, v1*s);
                } else {
                    *(float2*)&Out[(size_t)m * Cc + n] = make_float2(v0, v1);
                }
            }
        }
    }
}

// ---------------------------------------------------------------------------
// Flash attention: fp16 inputs, bias folded in GEMM1 (5th k16 chunk), online
// exact row-max, ping-pong K/V buffers, XOR-swizzled conflict-free staging.
// K layout: Kf[ni*320 + c*64 + b2*32 + ((g^c)&7)*4 + q]
// V layout: Vf[pi*512 + n*64 + b2*32 + ((g^n)&7)*4 + q]
// ---------------------------------------------------------------------------
__global__ __launch_bounds__(256, 2)
void flash_mma_kernel(const float* __restrict__ Pg) {
    __shared__ uint32_t smbuf[2][4608];   // per buf: Kf [0,2560), Vf [2560,4608)
    uint32_t* Qh = &smbuf[0][0];          // 128 rows x 44 u32 = 5632, spans bufs

    int tid = threadIdx.x;
    int w = tid >> 5, t = tid & 31;
    int g = t >> 2, q = t & 3;
    int b = blockIdx.z, h = blockIdx.y;
    int i0 = blockIdx.x * 128;
    int bh = b*Hh + h;

    const uint32_t* Qg = g_Qh + (size_t)bh * Nn * 32;
    const uint32_t* Kg = g_Kh + (size_t)bh * Nn * 32;
    const uint32_t* Vg = g_Vh + (size_t)bh * Nn * 32;

    int gx[8];
#pragma unroll
    for (int c = 0; c < 8; c++) gx[c] = ((g ^ c) & 7) * 4;

    // staging constants
    int row4 = tid >> 2, c4 = tid & 3;
    int jodd = row4 & 1;
    int q_j = (row4 >> 1) & 3;
    int b_j = (row4 >> 3) & 1;
    int pi_j = row4 >> 4;
    int kni = row4 >> 3, kg = row4 & 7;
    int kxor = ((kg ^ c4) & 7) * 4;
    int exor = ((kg ^ 4) & 7) * 4;
    int nn_v = c4*2 + jodd;

    auto stage_tile = [&](int j0, int bufi) {
        uint32_t* Kf = &smbuf[bufi][0];
        uint32_t* Vf = &smbuf[bufi][2560];
        {   // K: 2 LDG.128 + 2 STS.128
            const uint32_t* src = Kg + (size_t)(j0 + row4) * 32 + c4*8;
            uint4 ka = *(const uint4*)src;
            uint4 kb = *(const uint4*)(src + 4);
            int a0 = kni*320 + c4*64 + kxor;
            *(uint4*)&Kf[a0]      = ka;
            *(uint4*)&Kf[a0 + 32] = kb;
        }
        if (c4 == 0) {   // K ext chunk (fp32 P, hi/lo split) at c=4
            const float* pp = Pg + (size_t)(j0 + row4) * 3;
            float p0 = pp[0], p1 = pp[1], p2 = pp[2];
            __half H0 = __float2half_rn(p0), H1 = __float2half_rn(p1), H2 = __float2half_rn(p2);
            uint32_t colv[8];
            colv[0] = packh(H0, H1);
            colv[1] = packh(H2, H0);
            colv[2] = packh(H1, H2);
            colv[3] = h2u(p0 - __half2float(H0), p1 - __half2float(H1));
            colv[4] = h2u(p2 - __half2float(H2), 0.f);
            colv[5] = 0; colv[6] = 0; colv[7] = 0;
#pragma unroll
            for (int cc = 0; cc < 8; cc++)
                Kf[kni*320 + 256 + ((cc >> 2) & 1)*32 + exor + (cc & 3)] = colv[cc];
        }
        {   // V: 2 LDG.128, transpose via shfl + byte_perm, 8 STS.32
            const uint32_t* src = Vg + (size_t)(j0 + row4) * 32 + c4*8;
            uint4 va = *(const uint4*)src;
            uint4 vb = *(const uint4*)(src + 4);
            uint32_t mv[8] = {va.x, va.y, va.z, va.w, vb.x, vb.y, vb.z, vb.w};
            int base = pi_j*512 + nn_v*64 + b_j*32 + q_j;
#pragma unroll
            for (int i = 0; i < 4; i++) {
                uint32_t send = jodd ? mv[i] : mv[4 + i];
                uint32_t recv = __shfl_xor_sync(0xffffffffu, send, 4);
                uint32_t mine = jodd ? mv[4 + i] : mv[i];
                uint32_t lo = jodd ? __byte_perm(mine, recv, 0x1054)
                                   : __byte_perm(mine, recv, 0x5410);
                uint32_t hi = jodd ? __byte_perm(mine, recv, 0x3276)
                                   : __byte_perm(mine, recv, 0x7632);
                int dk = 2*i;
                Vf[base + (((dk)     ^ nn_v) & 7) * 4] = lo;
                Vf[base + (((dk + 1) ^ nn_v) & 7) * 4] = hi;
            }
        }
    };

    // ---- stage Q (already fp16, scaled) + rpl ext ----
    {
        int row = tid >> 1, hf = tid & 1;
        const uint32_t* src = Qg + (size_t)(i0 + row) * 32 + hf*16;
#pragma unroll
        for (int i = 0; i < 4; i++)
            *(uint4*)&Qh[row*44 + hf*16 + i*4] = *(const uint4*)(src + i*4);
        if (hf) {
            float4 r4 = *(const float4*)&g_RP[((size_t)b*Nn + i0 + row) * 4];
            __half H0 = __float2half_rn(r4.x), H1 = __float2half_rn(r4.y), H2 = __float2half_rn(r4.z);
            float l0 = r4.x - __half2float(H0);
            float l1 = r4.y - __half2float(H1);
            float l2 = r4.z - __half2float(H2);
            Qh[row*44 + 32] = packh(H0, H1);
            Qh[row*44 + 33] = (uint32_t)__half_as_ushort(H2) | ((uint32_t)(h2u(l0, 0.f) & 0xffffu) << 16);
            Qh[row*44 + 34] = h2u(l1, l2);
            Qh[row*44 + 35] = packh(H0, H1);
            Qh[row*44 + 36] = packh(H2, __float2half_rn(0.f));
            Qh[row*44 + 37] = 0; Qh[row*44 + 38] = 0; Qh[row*44 + 39] = 0;
        }
    }
    __syncthreads();

    int r0 = w*16 + g, r1 = r0 + 8;
    uint32_t aQ[5][4];
#pragma unroll
    for (int c = 0; c < 5; c++) {
        aQ[c][0] = Qh[r0*44 + 8*c + q];
        aQ[c][1] = Qh[r1*44 + 8*c + q];
        aQ[c][2] = Qh[r0*44 + 8*c + q + 4];
        aQ[c][3] = Qh[r1*44 + 8*c + q + 4];
    }
    __syncthreads();   // aQ reads complete before staging overwrites Qh

    stage_tile(0, 0);
    __syncthreads();

    float o[8][4];
#pragma unroll
    for (int n = 0; n < 8; n++)
#pragma unroll
        for (int c = 0; c < 4; c++) o[n][c] = 0.f;
    float lsum0 = 0.f, lsum1 = 0.f;
    float m0 = -1e30f, m1 = -1e30f;

    for (int tt = 0; tt < Nn / 64; tt++) {
        int cur = tt & 1;
        uint32_t* Kf = &smbuf[cur][0];
        uint32_t* Vf = &smbuf[cur][2560];

        // ---- GEMM1: log2-domain logits straight from mma ----
        float s[8][4];
#pragma unroll
        for (int ni = 0; ni < 8; ni++) {
            float cA[4] = {0.f,0.f,0.f,0.f}, cB[4] = {0.f,0.f,0.f,0.f};
            int kb = ni*320 + q;
            mma_f16(cA, aQ[0], Kf[kb +       gx[0]], Kf[kb +       gx[0] + 32]);
            mma_f16(cB, aQ[1], Kf[kb +  64 + gx[1]], Kf[kb +  64 + gx[1] + 32]);
            mma_f16(cA, aQ[2], Kf[kb + 128 + gx[2]], Kf[kb + 128 + gx[2] + 32]);
            mma_f16(cB, aQ[3], Kf[kb + 192 + gx[3]], Kf[kb + 192 + gx[3] + 32]);
            mma_f16(cA, aQ[4], Kf[kb + 256 + gx[4]], Kf[kb + 256 + gx[4] + 32]);
            s[ni][0] = cA[0] + cB[0];
            s[ni][1] = cA[1] + cB[1];
            s[ni][2] = cA[2] + cB[2];
            s[ni][3] = cA[3] + cB[3];
        }

        // ---- exact tile max (quad reduce), guarded online rescale ----
        float mt0 = fmaxf(s[0][0], s[0][1]), mt1 = fmaxf(s[0][2], s[0][3]);
#pragma unroll
        for (int ni = 1; ni < 8; ni++) {
            mt0 = fmaxf(mt0, fmaxf(s[ni][0], s[ni][1]));
            mt1 = fmaxf(mt1, fmaxf(s[ni][2], s[ni][3]));
        }
        mt0 = fmaxf(mt0, __shfl_xor_sync(0xffffffffu, mt0, 1));
        mt0 = fmaxf(mt0, __shfl_xor_sync(0xffffffffu, mt0, 2));
        mt1 = fmaxf(mt1, __shfl_xor_sync(0xffffffffu, mt1, 1));
        mt1 = fmaxf(mt1, __shfl_xor_sync(0xffffffffu, mt1, 2));
        if (mt0 > m0 || mt1 > m1) {
            float mn0 = fmaxf(m0, mt0), mn1 = fmaxf(m1, mt1);
            float al0 = ex2f(m0 - mn0), al1 = ex2f(m1 - mn1);
            m0 = mn0; m1 = mn1;
            lsum0 *= al0; lsum1 *= al1;
#pragma unroll
            for (int n = 0; n < 8; n++) {
                o[n][0] *= al0; o[n][1] *= al0;
                o[n][2] *= al1; o[n][3] *= al1;
            }
        }

        // ---- exp (P in [2^-14, 2^8], all normal fp16) ----
        float sh0 = 8.0f - m0, sh1 = 8.0f - m1;
#pragma unroll
        for (int ni = 0; ni < 8; ni++) {
            float e0 = ex2f(s[ni][0] + sh0);
            float e1 = ex2f(s[ni][1] + sh0);
            float e2 = ex2f(s[ni][2] + sh1);
            float e3 = ex2f(s[ni][3] + sh1);
            lsum0 += e0 + e1;
            lsum1 += e2 + e3;
            s[ni][0] = e0; s[ni][1] = e1; s[ni][2] = e2; s[ni][3] = e3;
        }

        // ---- PV: 4 k16 tiles ----
#pragma unroll
        for (int pi = 0; pi < 4; pi++) {
            uint32_t aP[4];
            aP[0] = h2u(s[2*pi][0],   s[2*pi][1]);
            aP[1] = h2u(s[2*pi][2],   s[2*pi][3]);
            aP[2] = h2u(s[2*pi+1][0], s[2*pi+1][1]);
            aP[3] = h2u(s[2*pi+1][2], s[2*pi+1][3]);
            int vb = pi*512 + q;
#pragma unroll
            for (int n = 0; n < 8; n++)
                mma_f16(o[n], aP, Vf[vb + n*64 + gx[n]], Vf[vb + n*64 + gx[n] + 32]);
        }

        if (tt + 1 < Nn / 64) stage_tile((tt + 1) * 64, 1 - cur);
        __syncthreads();
    }

    lsum0 += __shfl_xor_sync(0xffffffffu, lsum0, 1);
    lsum0 += __shfl_xor_sync(0xffffffffu, lsum0, 2);
    lsum1 += __shfl_xor_sync(0xffffffffu, lsum1, 1);
    lsum1 += __shfl_xor_sync(0xffffffffu, lsum1, 2);
    float inv0 = 1.f / lsum0, inv1 = 1.f / lsum1;

    uint32_t* ao0 = g_AOh + ((size_t)(b*Nn + i0 + r0) * Cc + h*Dd) / 2;
    uint32_t* ao1 = g_AOh + ((size_t)(b*Nn + i0 + r1) * Cc + h*Dd) / 2;
#pragma unroll
    for (int n = 0; n < 8; n++) {
        ao0[n*4 + q] = h2u(o[n][0]*inv0, o[n][1]*inv0);
        ao1[n*4 + q] = h2u(o[n][2]*inv1, o[n][3]*inv1);
    }
}

// ---------------------------------------------------------------------------
extern "C" void kernel_launch(void* const* d_in, const int* in_sizes, int n_in,
                              void* d_out, int out_size) {
    const float* x         = (const float*)d_in[0];
    const float* R         = (const float*)d_in[1];
    const float* P         = (const float*)d_in[2];
    const float* qkv_w     = (const float*)d_in[3];
    const float* qkv_b     = (const float*)d_in[4];
    const float* proj_w    = (const float*)d_in[5];
    const float* proj_b    = (const float*)d_in[6];
    const float* pos_scale = (const float*)d_in[7];
    float* out = (float*)d_out;

    rp_kernel<<<(Bb*Nn + 255) / 256, 256>>>(R, P, pos_scale);
    gemm_f16_kernel<true, false><<<dim3(768/64, (Bb*Nn)/128), 256>>>(x, qkv_w, qkv_b, nullptr);
    flash_mma_kernel<<<dim3(Nn/128, Hh, Bb), 256>>>(P);
    gemm_f16_kernel<false, true><<<dim3(Cc/64, (Bb*Nn)/128), 256>>>(nullptr, proj_w, proj_b, out);
}